// round 1
// baseline (speedup 1.0000x reference)
#include <cuda_runtime.h>
#include <cuda_bf16.h>
#include <cstddef>

#define B_    8
#define C_    192
#define H_    128
#define W_    128
#define HW_   16384
#define HEADS 4
#define DH    48

// ---------------- scratch (device globals; no allocation allowed) ----------
// layout (floats):
//  [0)        xn   : B*C*HW
//  [1)        qn   : B*C*HW
//  [2)        q    : B*C*HW
//  [3)        k    : B*C*HW
//  [4)        v    : B*C*HW
//  [5)        qd   : B*C*HW
//  [6)        kd   : B*C*HW
//  [7)        vd   : B*C*HW
//  part  : 32*16*2400
//  attn  : 32*48*48
//  M     : 8*192*192
#define TEN   ((size_t)B_ * C_ * HW_)          // 25165824
#define OFF_XN   ((size_t)0)
#define OFF_QN   (TEN * 1)
#define OFF_Q    (TEN * 2)
#define OFF_K    (TEN * 3)
#define OFF_V    (TEN * 4)
#define OFF_QD   (TEN * 5)
#define OFF_KD   (TEN * 6)
#define OFF_VD   (TEN * 7)
#define OFF_PART (TEN * 8)
#define PART_SZ  ((size_t)32 * 16 * 2400)
#define OFF_ATTN (OFF_PART + PART_SZ)
#define ATTN_SZ  ((size_t)32 * 48 * 48)
#define OFF_M    (OFF_ATTN + ATTN_SZ)
#define M_SZ     ((size_t)8 * 192 * 192)
#define TOTAL_SCRATCH (OFF_M + M_SZ)

__device__ float g_scratch[TOTAL_SCRATCH];

// ---------------- LayerNorm over channel dim --------------------------------
// one thread per pixel; two passes over the 192 channels (coalesced across
// pixels for every channel step).
__global__ void __launch_bounds__(256) ln_kernel(
    const float* __restrict__ in0, float* __restrict__ out0,
    const float* __restrict__ in1, float* __restrict__ out1,
    const float* __restrict__ gw, const float* __restrict__ gb)
{
    const float* in  = blockIdx.y ? in1  : in0;
    float*       out = blockIdx.y ? out1 : out0;
    int p = blockIdx.x * 256 + threadIdx.x;     // 0..131071
    int b = p >> 14;
    int pix = p & (HW_ - 1);
    const float* base = in + (size_t)b * C_ * HW_ + pix;
    float s = 0.f, ss = 0.f;
    #pragma unroll 8
    for (int c = 0; c < C_; c++) {
        float v = base[(size_t)c * HW_];
        s += v; ss += v * v;
    }
    float mu  = s * (1.f / C_);
    float var = ss * (1.f / C_) - mu * mu;
    float rstd = rsqrtf(var + 1e-5f);
    float* ob = out + (size_t)b * C_ * HW_ + pix;
    #pragma unroll 8
    for (int c = 0; c < C_; c++) {
        float v = base[(size_t)c * HW_];
        ob[(size_t)c * HW_] = (v - mu) * rstd * __ldg(&gw[c]) + __ldg(&gb[c]);
    }
}

// ---------------- SGEMM: C[o,p] = sum_c W[o,c] * X[c,p] (+ resid) -----------
// K = 192 fixed. Block tile 64(M) x 128(N), BK=16, 256 threads, 4x8/thread.
#define BM 64
#define BN 128
#define BK 16
__global__ void __launch_bounds__(256) gemm_k192(
    const float* __restrict__ X,   // [b][192][HW]
    const float* __restrict__ W,   // [ (b) ][192][192] row-major (o,c)
    float* __restrict__ Cout,      // [b][192][HW]
    const float* __restrict__ R,   // optional residual, same layout as Cout
    int wBatchStride)
{
    int b  = blockIdx.z;
    int n0 = blockIdx.x * BN;
    int m0 = blockIdx.y * BM;
    const float* Xb = X + (size_t)b * C_ * HW_;
    const float* Wb = W + (size_t)b * wBatchStride;
    float*       Cb = Cout + (size_t)b * C_ * HW_;

    __shared__ float Ws[BK][BM + 1];
    __shared__ float Xs[BK][BN];

    int tid = threadIdx.x;
    int tx = tid & 15;        // n dim
    int ty = tid >> 4;        // m dim
    int ml = ty * 4;
    int nl = tx * 8;

    float acc[4][8];
    #pragma unroll
    for (int i = 0; i < 4; i++)
        #pragma unroll
        for (int j = 0; j < 8; j++) acc[i][j] = 0.f;

    for (int k0 = 0; k0 < C_; k0 += BK) {
        #pragma unroll
        for (int r = 0; r < 4; r++) {
            int e = tid + 256 * r;          // 0..1023
            int m = e >> 4, kk = e & 15;
            Ws[kk][m] = Wb[(size_t)(m0 + m) * C_ + k0 + kk];
        }
        #pragma unroll
        for (int r = 0; r < 2; r++) {
            int e = tid + 256 * r;          // 0..511
            int kk = e >> 5, n4 = e & 31;
            float4 vv = *reinterpret_cast<const float4*>(
                &Xb[(size_t)(k0 + kk) * HW_ + n0 + n4 * 4]);
            *reinterpret_cast<float4*>(&Xs[kk][n4 * 4]) = vv;
        }
        __syncthreads();
        #pragma unroll
        for (int kk = 0; kk < BK; kk++) {
            float av[4];
            av[0] = Ws[kk][ml + 0];
            av[1] = Ws[kk][ml + 1];
            av[2] = Ws[kk][ml + 2];
            av[3] = Ws[kk][ml + 3];
            float4 b0 = *reinterpret_cast<const float4*>(&Xs[kk][nl]);
            float4 b1 = *reinterpret_cast<const float4*>(&Xs[kk][nl + 4]);
            float bv[8] = {b0.x, b0.y, b0.z, b0.w, b1.x, b1.y, b1.z, b1.w};
            #pragma unroll
            for (int i = 0; i < 4; i++)
                #pragma unroll
                for (int j = 0; j < 8; j++)
                    acc[i][j] = fmaf(av[i], bv[j], acc[i][j]);
        }
        __syncthreads();
    }

    #pragma unroll
    for (int i = 0; i < 4; i++) {
        int ch = m0 + ml + i;
        size_t off = (size_t)ch * HW_ + n0 + nl;
        float4 o0, o1;
        o0.x = acc[i][0]; o0.y = acc[i][1]; o0.z = acc[i][2]; o0.w = acc[i][3];
        o1.x = acc[i][4]; o1.y = acc[i][5]; o1.z = acc[i][6]; o1.w = acc[i][7];
        if (R) {
            const float* rb = R + (size_t)b * C_ * HW_ + off;
            float4 r0 = *reinterpret_cast<const float4*>(&rb[0]);
            float4 r1 = *reinterpret_cast<const float4*>(&rb[4]);
            o0.x += r0.x; o0.y += r0.y; o0.z += r0.z; o0.w += r0.w;
            o1.x += r1.x; o1.y += r1.y; o1.z += r1.z; o1.w += r1.w;
        }
        *reinterpret_cast<float4*>(&Cb[off])     = o0;
        *reinterpret_cast<float4*>(&Cb[off + 4]) = o1;
    }
}

// ---------------- depthwise 3x3, SAME zero pad ------------------------------
__global__ void __launch_bounds__(256) dw_kernel(
    const float* __restrict__ in, float* __restrict__ out,
    const float* __restrict__ w)
{
    int bc = blockIdx.x;              // b*C + c
    int c = bc % C_;
    const float* wp = w + c * 9;
    float w00 = __ldg(wp + 0), w01 = __ldg(wp + 1), w02 = __ldg(wp + 2);
    float w10 = __ldg(wp + 3), w11 = __ldg(wp + 4), w12 = __ldg(wp + 5);
    float w20 = __ldg(wp + 6), w21 = __ldg(wp + 7), w22 = __ldg(wp + 8);

    int p = blockIdx.y * 256 + threadIdx.x;
    int y = p >> 7, x = p & 127;
    const float* ib = in + (size_t)bc * HW_;
    bool xm = x > 0, xp = x < W_ - 1;
    float acc = 0.f;
    if (y > 0) {
        const float* r = ib + (y - 1) * W_;
        if (xm) acc = fmaf(r[x - 1], w00, acc);
        acc = fmaf(r[x], w01, acc);
        if (xp) acc = fmaf(r[x + 1], w02, acc);
    }
    {
        const float* r = ib + y * W_;
        if (xm) acc = fmaf(r[x - 1], w10, acc);
        acc = fmaf(r[x], w11, acc);
        if (xp) acc = fmaf(r[x + 1], w12, acc);
    }
    if (y < H_ - 1) {
        const float* r = ib + (y + 1) * W_;
        if (xm) acc = fmaf(r[x - 1], w20, acc);
        acc = fmaf(r[x], w21, acc);
        if (xp) acc = fmaf(r[x + 1], w22, acc);
    }
    out[(size_t)bc * HW_ + p] = acc;
}

// ---------------- Gram partial: G = q k^T (48x48) + row sumsq ---------------
// grid (16 n-chunks of 1024, 32 bh). 256 threads = 16x16, each 3x3 of G.
__global__ void __launch_bounds__(256) gram_partial(
    const float* __restrict__ qd, const float* __restrict__ kd,
    float* __restrict__ part)
{
    int chunk = blockIdx.x;   // 0..15
    int bh    = blockIdx.y;   // 0..31
    int b = bh >> 2, h = bh & 3;
    size_t rowbase = ((size_t)b * C_ + h * DH) * HW_ + (size_t)chunk * 1024;
    const float* qb = qd + rowbase;
    const float* kb = kd + rowbase;

    __shared__ float qs[32][DH + 1];   // [kk][i]
    __shared__ float ks[32][DH + 1];

    int tid = threadIdx.x;
    int ti = tid & 15, tj = tid >> 4;
    int i0 = ti * 3, j0 = tj * 3;

    float acc[3][3];
    #pragma unroll
    for (int i = 0; i < 3; i++)
        #pragma unroll
        for (int j = 0; j < 3; j++) acc[i][j] = 0.f;
    float nacc = 0.f;

    for (int t = 0; t < 32; t++) {
        __syncthreads();
        #pragma unroll
        for (int r = 0; r < 6; r++) {
            int e = tid + 256 * r;      // 0..1535 = 48 rows x 32 cols
            int i = e >> 5, nlc = e & 31;
            qs[nlc][i] = qb[(size_t)i * HW_ + t * 32 + nlc];
            ks[nlc][i] = kb[(size_t)i * HW_ + t * 32 + nlc];
        }
        __syncthreads();
        #pragma unroll
        for (int kk = 0; kk < 32; kk++) {
            float a0 = qs[kk][i0], a1 = qs[kk][i0 + 1], a2 = qs[kk][i0 + 2];
            float b0 = ks[kk][j0], b1 = ks[kk][j0 + 1], b2 = ks[kk][j0 + 2];
            acc[0][0] = fmaf(a0, b0, acc[0][0]);
            acc[0][1] = fmaf(a0, b1, acc[0][1]);
            acc[0][2] = fmaf(a0, b2, acc[0][2]);
            acc[1][0] = fmaf(a1, b0, acc[1][0]);
            acc[1][1] = fmaf(a1, b1, acc[1][1]);
            acc[1][2] = fmaf(a1, b2, acc[1][2]);
            acc[2][0] = fmaf(a2, b0, acc[2][0]);
            acc[2][1] = fmaf(a2, b1, acc[2][1]);
            acc[2][2] = fmaf(a2, b2, acc[2][2]);
        }
        if (tid < DH) {
            #pragma unroll
            for (int kk = 0; kk < 32; kk++) {
                float v = qs[kk][tid]; nacc = fmaf(v, v, nacc);
            }
        } else if (tid < 2 * DH) {
            int i = tid - DH;
            #pragma unroll
            for (int kk = 0; kk < 32; kk++) {
                float v = ks[kk][i]; nacc = fmaf(v, v, nacc);
            }
        }
    }

    float* pb = part + ((size_t)bh * 16 + chunk) * 2400;
    #pragma unroll
    for (int i = 0; i < 3; i++)
        #pragma unroll
        for (int j = 0; j < 3; j++)
            pb[(i0 + i) * DH + j0 + j] = acc[i][j];
    if (tid < 2 * DH) pb[2304 + tid] = nacc;
}

// ---------------- reduce partials + norms + softmax -> attn -----------------
__global__ void __launch_bounds__(256) reduce_softmax(
    const float* __restrict__ part, const float* __restrict__ temp,
    float* __restrict__ attn)
{
    int bh = blockIdx.x;
    int h = bh & 3;
    __shared__ float G[DH * DH];
    __shared__ float nq[DH], nk[DH];
    int tid = threadIdx.x;

    for (int e = tid; e < 2400; e += 256) {
        float s = 0.f;
        #pragma unroll
        for (int c = 0; c < 16; c++)
            s += part[((size_t)bh * 16 + c) * 2400 + e];
        if (e < 2304)      G[e] = s;
        else if (e < 2352) nq[e - 2304] = fmaxf(sqrtf(s), 1e-12f);
        else               nk[e - 2352] = fmaxf(sqrtf(s), 1e-12f);
    }
    __syncthreads();

    if (tid < DH) {
        int i = tid;
        float sc = __ldg(&temp[h]) / nq[i];
        float m = -1e30f;
        #pragma unroll 4
        for (int j = 0; j < DH; j++) {
            float s = G[i * DH + j] * sc / nk[j];
            G[i * DH + j] = s;
            m = fmaxf(m, s);
        }
        float sum = 0.f;
        #pragma unroll 4
        for (int j = 0; j < DH; j++) {
            float e = __expf(G[i * DH + j] - m);
            G[i * DH + j] = e;
            sum += e;
        }
        float rs = 1.f / sum;
        #pragma unroll 4
        for (int j = 0; j < DH; j++)
            attn[(size_t)bh * DH * DH + i * DH + j] = G[i * DH + j] * rs;
    }
}

// ---------------- M_b = W_proj @ blockdiag(attn_b) --------------------------
// M[o, 48h+d] = sum_i Wp[o, 48h+i] * attn[b,h,i,d]
__global__ void __launch_bounds__(256) build_M(
    const float* __restrict__ attn, const float* __restrict__ wp,
    float* __restrict__ M)
{
    int b = blockIdx.x;
    __shared__ float sA[HEADS * DH * DH];   // 9216 floats, 36 KB
    int tid = threadIdx.x;
    for (int e = tid; e < HEADS * DH * DH; e += 256)
        sA[e] = attn[(size_t)b * HEADS * DH * DH + e];
    __syncthreads();

    for (int e = tid; e < C_ * C_; e += 256) {
        int o = e / C_, cp = e % C_;
        int h = cp / DH, d = cp % DH;
        const float* wrow = wp + (size_t)o * C_ + h * DH;
        const float* arow = sA + h * DH * DH + d;
        float s = 0.f;
        #pragma unroll
        for (int i = 0; i < DH; i++)
            s = fmaf(__ldg(&wrow[i]), arow[i * DH], s);
        M[(size_t)b * C_ * C_ + e] = s;
    }
}

// ---------------- launch ----------------------------------------------------
extern "C" void kernel_launch(void* const* d_in, const int* in_sizes, int n_in,
                              void* d_out, int out_size)
{
    const float* xx     = (const float*)d_in[0];
    const float* q_in   = (const float*)d_in[1];
    const float* ln_w   = (const float*)d_in[2];
    const float* ln_b   = (const float*)d_in[3];
    const float* w_q    = (const float*)d_in[4];
    const float* w_k    = (const float*)d_in[5];
    const float* w_v    = (const float*)d_in[6];
    const float* wd_q   = (const float*)d_in[7];
    const float* wd_k   = (const float*)d_in[8];
    const float* wd_v   = (const float*)d_in[9];
    const float* w_proj = (const float*)d_in[10];
    const float* temp   = (const float*)d_in[11];
    float* out = (float*)d_out;

    float* S = nullptr;
    cudaGetSymbolAddress((void**)&S, g_scratch);
    float* xn   = S + OFF_XN;
    float* qn   = S + OFF_QN;
    float* qb   = S + OFF_Q;
    float* kb   = S + OFF_K;
    float* vb   = S + OFF_V;
    float* qd   = S + OFF_QD;
    float* kd   = S + OFF_KD;
    float* vd   = S + OFF_VD;
    float* part = S + OFF_PART;
    float* attn = S + OFF_ATTN;
    float* Mb   = S + OFF_M;

    // 1. LayerNorm both inputs
    ln_kernel<<<dim3(512, 2), 256>>>(xx, xn, q_in, qn, ln_w, ln_b);

    // 2. 1x1 convs (GEMMs, K=192)
    dim3 gg(HW_ / BN, C_ / BM, B_);
    gemm_k192<<<gg, 256>>>(qn, w_q, qb, nullptr, 0);
    gemm_k192<<<gg, 256>>>(xn, w_k, kb, nullptr, 0);
    gemm_k192<<<gg, 256>>>(xn, w_v, vb, nullptr, 0);

    // 3. depthwise 3x3
    dim3 gd(B_ * C_, HW_ / 256);
    dw_kernel<<<gd, 256>>>(qb, qd, wd_q);
    dw_kernel<<<gd, 256>>>(kb, kd, wd_k);
    dw_kernel<<<gd, 256>>>(vb, vd, wd_v);

    // 4. Gram + norms (L2-normalize folded into softmax input)
    gram_partial<<<dim3(16, 32), 256>>>(qd, kd, part);
    reduce_softmax<<<32, 256>>>(part, temp, attn);

    // 5. fold attn@v and proj into per-batch M, then one GEMM + residual
    build_M<<<8, 256>>>(attn, w_proj, Mb);
    gemm_k192<<<gg, 256>>>(vd, Mb, out, q_in, C_ * C_);
}

// round 2
// speedup vs baseline: 1.3416x; 1.3416x over previous
#include <cuda_runtime.h>
#include <cuda_bf16.h>
#include <cstddef>

#define B_    8
#define C_    192
#define H_    128
#define W_    128
#define HW_   16384
#define HEADS 4
#define DH    48

#define TEN   ((size_t)B_ * C_ * HW_)
#define OFF_XN   ((size_t)0)
#define OFF_QN   (TEN * 1)
#define OFF_Q    (TEN * 2)
#define OFF_K    (TEN * 3)
#define OFF_V    (TEN * 4)
#define OFF_QD   (TEN * 5)
#define OFF_KD   (TEN * 6)
#define OFF_VD   (TEN * 7)
#define OFF_PART (TEN * 8)
#define PART_SZ  ((size_t)32 * 16 * 2400)
#define OFF_ATTN (OFF_PART + PART_SZ)
#define ATTN_SZ  ((size_t)32 * 48 * 48)
#define OFF_M    (OFF_ATTN + ATTN_SZ)
#define M_SZ     ((size_t)8 * 192 * 192)
#define TOTAL_SCRATCH (OFF_M + M_SZ)

__device__ float g_scratch[TOTAL_SCRATCH];

// ---------------- LayerNorm over channel dim --------------------------------
__global__ void __launch_bounds__(256) ln_kernel(
    const float* __restrict__ in0, float* __restrict__ out0,
    const float* __restrict__ in1, float* __restrict__ out1,
    const float* __restrict__ gw, const float* __restrict__ gb)
{
    const float* in  = blockIdx.y ? in1  : in0;
    float*       out = blockIdx.y ? out1 : out0;
    int p = blockIdx.x * 256 + threadIdx.x;
    int b = p >> 14;
    int pix = p & (HW_ - 1);
    const float* base = in + (size_t)b * C_ * HW_ + pix;
    float s = 0.f, ss = 0.f;
    #pragma unroll 8
    for (int c = 0; c < C_; c++) {
        float v = base[(size_t)c * HW_];
        s += v; ss += v * v;
    }
    float mu  = s * (1.f / C_);
    float var = ss * (1.f / C_) - mu * mu;
    float rstd = rsqrtf(var + 1e-5f);
    float* ob = out + (size_t)b * C_ * HW_ + pix;
    #pragma unroll 8
    for (int c = 0; c < C_; c++) {
        float v = base[(size_t)c * HW_];
        ob[(size_t)c * HW_] = (v - mu) * rstd * __ldg(&gw[c]) + __ldg(&gb[c]);
    }
}

// ---------------- SGEMM: C[o,p] = sum_c W[o,c] * X[c,p] (+ resid) -----------
// K = 192. Block tile 64(M) x 128(N), BK=16, 128 threads, 8x8 per thread.
// B-fragment split into two 4-wide chunks (tx*4 and tx*4+64) so every
// 8-thread LDS.128 phase covers all 32 banks conflict-free.
#define BM 64
#define BN 128
#define BK 16
__global__ void __launch_bounds__(128) gemm_k192(
    const float* __restrict__ X,   // [b][192][HW]
    const float* __restrict__ W,   // [(b)][192][192] row-major (o,c)
    float* __restrict__ Cout,      // [b][192][HW]
    const float* __restrict__ R,   // optional residual
    int wBatchStride)
{
    int b  = blockIdx.z;
    int n0 = blockIdx.x * BN;
    int m0 = blockIdx.y * BM;
    const float* Xb = X + (size_t)b * C_ * HW_;
    const float* Wb = W + (size_t)b * wBatchStride;
    float*       Cb = Cout + (size_t)b * C_ * HW_;

    __shared__ float Ws[BK][BM + 4];
    __shared__ float Xs[BK][BN];

    int tid = threadIdx.x;          // 0..127
    int tx = tid & 15;              // n dim
    int ty = tid >> 4;              // m dim, 0..7
    int ml  = ty * 8;
    int nl0 = tx * 4;
    int nl1 = tx * 4 + 64;

    float acc[8][8];
    #pragma unroll
    for (int i = 0; i < 8; i++)
        #pragma unroll
        for (int j = 0; j < 8; j++) acc[i][j] = 0.f;

    for (int k0 = 0; k0 < C_; k0 += BK) {
        // Ws: 64 rows x 16 k = 1024 floats, 8 per thread
        #pragma unroll
        for (int r = 0; r < 8; r++) {
            int e = tid + 128 * r;
            int m = e >> 4, kk = e & 15;
            Ws[kk][m] = Wb[(size_t)(m0 + m) * C_ + k0 + kk];
        }
        // Xs: 16 k x 128 n = 512 float4, 4 per thread
        #pragma unroll
        for (int r = 0; r < 4; r++) {
            int e = tid + 128 * r;
            int kk = e >> 5, n4 = e & 31;
            *reinterpret_cast<float4*>(&Xs[kk][n4 * 4]) =
                *reinterpret_cast<const float4*>(
                    &Xb[(size_t)(k0 + kk) * HW_ + n0 + n4 * 4]);
        }
        __syncthreads();
        #pragma unroll
        for (int kk = 0; kk < BK; kk++) {
            float4 a0 = *reinterpret_cast<const float4*>(&Ws[kk][ml]);
            float4 a1 = *reinterpret_cast<const float4*>(&Ws[kk][ml + 4]);
            float4 b0 = *reinterpret_cast<const float4*>(&Xs[kk][nl0]);
            float4 b1 = *reinterpret_cast<const float4*>(&Xs[kk][nl1]);
            float av[8] = {a0.x, a0.y, a0.z, a0.w, a1.x, a1.y, a1.z, a1.w};
            float bv[8] = {b0.x, b0.y, b0.z, b0.w, b1.x, b1.y, b1.z, b1.w};
            #pragma unroll
            for (int i = 0; i < 8; i++)
                #pragma unroll
                for (int j = 0; j < 8; j++)
                    acc[i][j] = fmaf(av[i], bv[j], acc[i][j]);
        }
        __syncthreads();
    }

    #pragma unroll
    for (int i = 0; i < 8; i++) {
        int ch = m0 + ml + i;
        size_t off0 = (size_t)ch * HW_ + n0 + nl0;
        size_t off1 = (size_t)ch * HW_ + n0 + nl1;
        float4 o0, o1;
        o0.x = acc[i][0]; o0.y = acc[i][1]; o0.z = acc[i][2]; o0.w = acc[i][3];
        o1.x = acc[i][4]; o1.y = acc[i][5]; o1.z = acc[i][6]; o1.w = acc[i][7];
        if (R) {
            const float* rb = R + (size_t)b * C_ * HW_;
            float4 r0 = *reinterpret_cast<const float4*>(&rb[off0]);
            float4 r1 = *reinterpret_cast<const float4*>(&rb[off1]);
            o0.x += r0.x; o0.y += r0.y; o0.z += r0.z; o0.w += r0.w;
            o1.x += r1.x; o1.y += r1.y; o1.z += r1.z; o1.w += r1.w;
        }
        *reinterpret_cast<float4*>(&Cb[off0]) = o0;
        *reinterpret_cast<float4*>(&Cb[off1]) = o1;
    }
}

// ---------------- depthwise 3x3, SAME zero pad ------------------------------
__global__ void __launch_bounds__(256) dw_kernel(
    const float* __restrict__ in, float* __restrict__ out,
    const float* __restrict__ w)
{
    int bc = blockIdx.x;
    int c = bc % C_;
    const float* wp = w + c * 9;
    float w00 = __ldg(wp + 0), w01 = __ldg(wp + 1), w02 = __ldg(wp + 2);
    float w10 = __ldg(wp + 3), w11 = __ldg(wp + 4), w12 = __ldg(wp + 5);
    float w20 = __ldg(wp + 6), w21 = __ldg(wp + 7), w22 = __ldg(wp + 8);

    int p = blockIdx.y * 256 + threadIdx.x;
    int y = p >> 7, x = p & 127;
    const float* ib = in + (size_t)bc * HW_;
    bool xm = x > 0, xp = x < W_ - 1;
    float acc = 0.f;
    if (y > 0) {
        const float* r = ib + (y - 1) * W_;
        if (xm) acc = fmaf(r[x - 1], w00, acc);
        acc = fmaf(r[x], w01, acc);
        if (xp) acc = fmaf(r[x + 1], w02, acc);
    }
    {
        const float* r = ib + y * W_;
        if (xm) acc = fmaf(r[x - 1], w10, acc);
        acc = fmaf(r[x], w11, acc);
        if (xp) acc = fmaf(r[x + 1], w12, acc);
    }
    if (y < H_ - 1) {
        const float* r = ib + (y + 1) * W_;
        if (xm) acc = fmaf(r[x - 1], w20, acc);
        acc = fmaf(r[x], w21, acc);
        if (xp) acc = fmaf(r[x + 1], w22, acc);
    }
    out[(size_t)bc * HW_ + p] = acc;
}

// ---------------- Gram partial: G = q k^T (48x48) + row sumsq ---------------
__global__ void __launch_bounds__(256) gram_partial(
    const float* __restrict__ qd, const float* __restrict__ kd,
    float* __restrict__ part)
{
    int chunk = blockIdx.x;
    int bh    = blockIdx.y;
    int b = bh >> 2, h = bh & 3;
    size_t rowbase = ((size_t)b * C_ + h * DH) * HW_ + (size_t)chunk * 1024;
    const float* qb = qd + rowbase;
    const float* kb = kd + rowbase;

    __shared__ float qs[32][DH + 1];
    __shared__ float ks[32][DH + 1];

    int tid = threadIdx.x;
    int ti = tid & 15, tj = tid >> 4;
    int i0 = ti * 3, j0 = tj * 3;

    float acc[3][3];
    #pragma unroll
    for (int i = 0; i < 3; i++)
        #pragma unroll
        for (int j = 0; j < 3; j++) acc[i][j] = 0.f;
    float nacc = 0.f;

    for (int t = 0; t < 32; t++) {
        __syncthreads();
        #pragma unroll
        for (int r = 0; r < 6; r++) {
            int e = tid + 256 * r;
            int i = e >> 5, nlc = e & 31;
            qs[nlc][i] = qb[(size_t)i * HW_ + t * 32 + nlc];
            ks[nlc][i] = kb[(size_t)i * HW_ + t * 32 + nlc];
        }
        __syncthreads();
        #pragma unroll
        for (int kk = 0; kk < 32; kk++) {
            float a0 = qs[kk][i0], a1 = qs[kk][i0 + 1], a2 = qs[kk][i0 + 2];
            float b0 = ks[kk][j0], b1 = ks[kk][j0 + 1], b2 = ks[kk][j0 + 2];
            acc[0][0] = fmaf(a0, b0, acc[0][0]);
            acc[0][1] = fmaf(a0, b1, acc[0][1]);
            acc[0][2] = fmaf(a0, b2, acc[0][2]);
            acc[1][0] = fmaf(a1, b0, acc[1][0]);
            acc[1][1] = fmaf(a1, b1, acc[1][1]);
            acc[1][2] = fmaf(a1, b2, acc[1][2]);
            acc[2][0] = fmaf(a2, b0, acc[2][0]);
            acc[2][1] = fmaf(a2, b1, acc[2][1]);
            acc[2][2] = fmaf(a2, b2, acc[2][2]);
        }
        if (tid < DH) {
            #pragma unroll
            for (int kk = 0; kk < 32; kk++) {
                float v = qs[kk][tid]; nacc = fmaf(v, v, nacc);
            }
        } else if (tid < 2 * DH) {
            int i = tid - DH;
            #pragma unroll
            for (int kk = 0; kk < 32; kk++) {
                float v = ks[kk][i]; nacc = fmaf(v, v, nacc);
            }
        }
    }

    float* pb = part + ((size_t)bh * 16 + chunk) * 2400;
    #pragma unroll
    for (int i = 0; i < 3; i++)
        #pragma unroll
        for (int j = 0; j < 3; j++)
            pb[(i0 + i) * DH + j0 + j] = acc[i][j];
    if (tid < 2 * DH) pb[2304 + tid] = nacc;
}

// ---------------- reduce partials + norms + softmax -> attn -----------------
__global__ void __launch_bounds__(256) reduce_softmax(
    const float* __restrict__ part, const float* __restrict__ temp,
    float* __restrict__ attn)
{
    int bh = blockIdx.x;
    int h = bh & 3;
    __shared__ float G[DH * DH];
    __shared__ float nq[DH], nk[DH];
    int tid = threadIdx.x;

    for (int e = tid; e < 2400; e += 256) {
        float s = 0.f;
        #pragma unroll
        for (int c = 0; c < 16; c++)
            s += part[((size_t)bh * 16 + c) * 2400 + e];
        if (e < 2304)      G[e] = s;
        else if (e < 2352) nq[e - 2304] = fmaxf(sqrtf(s), 1e-12f);
        else               nk[e - 2352] = fmaxf(sqrtf(s), 1e-12f);
    }
    __syncthreads();

    if (tid < DH) {
        int i = tid;
        float sc = __ldg(&temp[h]) / nq[i];
        float m = -1e30f;
        #pragma unroll 4
        for (int j = 0; j < DH; j++) {
            float s = G[i * DH + j] * sc / nk[j];
            G[i * DH + j] = s;
            m = fmaxf(m, s);
        }
        float sum = 0.f;
        #pragma unroll 4
        for (int j = 0; j < DH; j++) {
            float e = __expf(G[i * DH + j] - m);
            G[i * DH + j] = e;
            sum += e;
        }
        float rs = 1.f / sum;
        #pragma unroll 4
        for (int j = 0; j < DH; j++)
            attn[(size_t)bh * DH * DH + i * DH + j] = G[i * DH + j] * rs;
    }
}

// ---------------- M_b = W_proj @ blockdiag(attn_b) --------------------------
__global__ void __launch_bounds__(256) build_M(
    const float* __restrict__ attn, const float* __restrict__ wp,
    float* __restrict__ M)
{
    int b = blockIdx.x;
    __shared__ float sA[HEADS * DH * DH];
    int tid = threadIdx.x;
    for (int e = tid; e < HEADS * DH * DH; e += 256)
        sA[e] = attn[(size_t)b * HEADS * DH * DH + e];
    __syncthreads();

    for (int e = tid; e < C_ * C_; e += 256) {
        int o = e / C_, cp = e % C_;
        int h = cp / DH, d = cp % DH;
        const float* wrow = wp + (size_t)o * C_ + h * DH;
        const float* arow = sA + h * DH * DH + d;
        float s = 0.f;
        #pragma unroll
        for (int i = 0; i < DH; i++)
            s = fmaf(__ldg(&wrow[i]), arow[i * DH], s);
        M[(size_t)b * C_ * C_ + e] = s;
    }
}

// ---------------- launch ----------------------------------------------------
extern "C" void kernel_launch(void* const* d_in, const int* in_sizes, int n_in,
                              void* d_out, int out_size)
{
    const float* xx     = (const float*)d_in[0];
    const float* q_in   = (const float*)d_in[1];
    const float* ln_w   = (const float*)d_in[2];
    const float* ln_b   = (const float*)d_in[3];
    const float* w_q    = (const float*)d_in[4];
    const float* w_k    = (const float*)d_in[5];
    const float* w_v    = (const float*)d_in[6];
    const float* wd_q   = (const float*)d_in[7];
    const float* wd_k   = (const float*)d_in[8];
    const float* wd_v   = (const float*)d_in[9];
    const float* w_proj = (const float*)d_in[10];
    const float* temp   = (const float*)d_in[11];
    float* out = (float*)d_out;

    float* S = nullptr;
    cudaGetSymbolAddress((void**)&S, g_scratch);
    float* xn   = S + OFF_XN;
    float* qn   = S + OFF_QN;
    float* qb   = S + OFF_Q;
    float* kb   = S + OFF_K;
    float* vb   = S + OFF_V;
    float* qd   = S + OFF_QD;
    float* kd   = S + OFF_KD;
    float* vd   = S + OFF_VD;
    float* part = S + OFF_PART;
    float* attn = S + OFF_ATTN;
    float* Mb   = S + OFF_M;

    ln_kernel<<<dim3(512, 2), 256>>>(xx, xn, q_in, qn, ln_w, ln_b);

    dim3 gg(HW_ / BN, C_ / BM, B_);
    gemm_k192<<<gg, 128>>>(qn, w_q, qb, nullptr, 0);
    gemm_k192<<<gg, 128>>>(xn, w_k, kb, nullptr, 0);
    gemm_k192<<<gg, 128>>>(xn, w_v, vb, nullptr, 0);

    dim3 gd(B_ * C_, HW_ / 256);
    dw_kernel<<<gd, 256>>>(qb, qd, wd_q);
    dw_kernel<<<gd, 256>>>(kb, kd, wd_k);
    dw_kernel<<<gd, 256>>>(vb, vd, wd_v);

    gram_partial<<<dim3(16, 32), 256>>>(qd, kd, part);
    reduce_softmax<<<32, 256>>>(part, temp, attn);

    build_M<<<8, 256>>>(attn, w_proj, Mb);
    gemm_k192<<<gg, 128>>>(vd, Mb, out, q_in, C_ * C_);
}

// round 3
// speedup vs baseline: 1.5088x; 1.1247x over previous
#include <cuda_runtime.h>
#include <cuda_bf16.h>
#include <cstddef>

#define B_    8
#define C_    192
#define H_    128
#define W_    128
#define HW_   16384
#define HEADS 4
#define DH    48

#define TEN   ((size_t)B_ * C_ * HW_)
#define OFF_Q    ((size_t)0)
#define OFF_K    (TEN * 1)
#define OFF_V    (TEN * 2)
#define OFF_QD   (TEN * 3)
#define OFF_KD   (TEN * 4)
#define OFF_VD   (TEN * 5)
#define OFF_PART (TEN * 6)
#define PART_SZ  ((size_t)32 * 16 * 2400)
#define OFF_ATTN (OFF_PART + PART_SZ)
#define ATTN_SZ  ((size_t)32 * 48 * 48)
#define OFF_M    (OFF_ATTN + ATTN_SZ)
#define M_SZ     ((size_t)8 * 192 * 192)
#define NPIX     ((size_t)B_ * HW_)
#define OFF_MUX  (OFF_M + M_SZ)
#define OFF_RSX  (OFF_MUX + NPIX)
#define OFF_MUQ  (OFF_RSX + NPIX)
#define OFF_RSQ  (OFF_MUQ + NPIX)
#define TOTAL_SCRATCH (OFF_RSQ + NPIX)

__device__ float g_scratch[TOTAL_SCRATCH];

// ---------------- LN stats: per-pixel mu, rstd ------------------------------
__global__ void __launch_bounds__(256) ln_stats(
    const float* __restrict__ in0, float* __restrict__ mu0, float* __restrict__ rs0,
    const float* __restrict__ in1, float* __restrict__ mu1, float* __restrict__ rs1)
{
    const float* in = blockIdx.y ? in1 : in0;
    float* mu = blockIdx.y ? mu1 : mu0;
    float* rs = blockIdx.y ? rs1 : rs0;
    int p = blockIdx.x * 256 + threadIdx.x;
    int b = p >> 14;
    int pix = p & (HW_ - 1);
    const float* base = in + (size_t)b * C_ * HW_ + pix;
    float s = 0.f, ss = 0.f;
    #pragma unroll 8
    for (int c = 0; c < C_; c++) {
        float v = base[(size_t)c * HW_];
        s += v; ss += v * v;
    }
    float m = s * (1.f / C_);
    float var = ss * (1.f / C_) - m * m;
    mu[p] = m;
    rs[p] = rsqrtf(var + 1e-5f);
}

// ---------------- SGEMM with fused LayerNorm on X, double-buffered ----------
// C[o,p] = sum_c W[o,c] * LN(X)[c,p]  (+ optional residual)
// K=192, tile 64x128, BK=16, 128 threads, 8x8/thread.
#define BM 64
#define BN 128
#define BK 16
#define NT (C_ / BK)
__global__ void __launch_bounds__(128) gemm_k192(
    const float* __restrict__ X,     // raw [b][192][HW]
    const float* __restrict__ W,     // [(b)][192][192]
    float* __restrict__ Cout,
    const float* __restrict__ R,     // optional residual
    const float* __restrict__ muA,   // per-pixel mu   (nullptr = no LN)
    const float* __restrict__ rsA,   // per-pixel rstd
    const float* __restrict__ gw,    // LN gamma [192]
    const float* __restrict__ gb,    // LN beta  [192]
    int wBatchStride)
{
    int b  = blockIdx.z;
    int n0 = blockIdx.x * BN;
    int m0 = blockIdx.y * BM;
    const float* Xb = X + (size_t)b * C_ * HW_;
    const float* Wb = W + (size_t)b * wBatchStride;
    float*       Cb = Cout + (size_t)b * C_ * HW_;
    const bool doLN = (muA != nullptr);

    __shared__ float Ws[2][BK][BM + 4];
    __shared__ float Xs[2][BK][BN];
    __shared__ float muS[BN], rsS[BN];
    __shared__ float gwS[C_], gbS[C_];

    int tid = threadIdx.x;
    int tx = tid & 15;
    int ty = tid >> 4;
    int ml  = ty * 8;
    int nl0 = tx * 4;
    int nl1 = tx * 4 + 64;

    // stage LN params
    if (doLN) {
        if (tid < BN) {
            muS[tid] = muA[(size_t)b * HW_ + n0 + tid];
            rsS[tid] = rsA[(size_t)b * HW_ + n0 + tid];
        }
        for (int e = tid; e < C_; e += 128) {
            gwS[e] = gw[e];
            gbS[e] = gb[e];
        }
    }

    float acc[8][8];
    #pragma unroll
    for (int i = 0; i < 8; i++)
        #pragma unroll
        for (int j = 0; j < 8; j++) acc[i][j] = 0.f;

    // ---- load tile 0 ----
    #pragma unroll
    for (int r = 0; r < 8; r++) {
        int e = tid + 128 * r;
        int m = e >> 4, kk = e & 15;
        Ws[0][kk][m] = Wb[(size_t)(m0 + m) * C_ + kk];
    }
    if (doLN) __syncthreads();   // muS/rsS/gwS ready before use
    #pragma unroll
    for (int r = 0; r < 4; r++) {
        int e = tid + 128 * r;
        int kk = e >> 5, n4 = e & 31;
        float4 v = *reinterpret_cast<const float4*>(
            &Xb[(size_t)kk * HW_ + n0 + n4 * 4]);
        if (doLN) {
            float g = gwS[kk], bb = gbS[kk];
            int n = n4 * 4;
            v.x = (v.x - muS[n + 0]) * rsS[n + 0] * g + bb;
            v.y = (v.y - muS[n + 1]) * rsS[n + 1] * g + bb;
            v.z = (v.z - muS[n + 2]) * rsS[n + 2] * g + bb;
            v.w = (v.w - muS[n + 3]) * rsS[n + 3] * g + bb;
        }
        *reinterpret_cast<float4*>(&Xs[0][kk][n4 * 4]) = v;
    }
    __syncthreads();

    int buf = 0;
    for (int kt = 0; kt < NT; kt++) {
        int k0n = (kt + 1) * BK;
        float wpre[8];
        float4 xpre[4];
        if (kt < NT - 1) {
            #pragma unroll
            for (int r = 0; r < 8; r++) {
                int e = tid + 128 * r;
                int m = e >> 4, kk = e & 15;
                wpre[r] = Wb[(size_t)(m0 + m) * C_ + k0n + kk];
            }
            #pragma unroll
            for (int r = 0; r < 4; r++) {
                int e = tid + 128 * r;
                int kk = e >> 5, n4 = e & 31;
                xpre[r] = *reinterpret_cast<const float4*>(
                    &Xb[(size_t)(k0n + kk) * HW_ + n0 + n4 * 4]);
            }
        }

        #pragma unroll
        for (int kk = 0; kk < BK; kk++) {
            float4 a0 = *reinterpret_cast<const float4*>(&Ws[buf][kk][ml]);
            float4 a1 = *reinterpret_cast<const float4*>(&Ws[buf][kk][ml + 4]);
            float4 b0 = *reinterpret_cast<const float4*>(&Xs[buf][kk][nl0]);
            float4 b1 = *reinterpret_cast<const float4*>(&Xs[buf][kk][nl1]);
            float av[8] = {a0.x, a0.y, a0.z, a0.w, a1.x, a1.y, a1.z, a1.w};
            float bv[8] = {b0.x, b0.y, b0.z, b0.w, b1.x, b1.y, b1.z, b1.w};
            #pragma unroll
            for (int i = 0; i < 8; i++)
                #pragma unroll
                for (int j = 0; j < 8; j++)
                    acc[i][j] = fmaf(av[i], bv[j], acc[i][j]);
        }

        if (kt < NT - 1) {
            buf ^= 1;
            #pragma unroll
            for (int r = 0; r < 8; r++) {
                int e = tid + 128 * r;
                int m = e >> 4, kk = e & 15;
                Ws[buf][kk][m] = wpre[r];
            }
            #pragma unroll
            for (int r = 0; r < 4; r++) {
                int e = tid + 128 * r;
                int kk = e >> 5, n4 = e & 31;
                float4 v = xpre[r];
                if (doLN) {
                    float g = gwS[k0n + kk], bb = gbS[k0n + kk];
                    int n = n4 * 4;
                    v.x = (v.x - muS[n + 0]) * rsS[n + 0] * g + bb;
                    v.y = (v.y - muS[n + 1]) * rsS[n + 1] * g + bb;
                    v.z = (v.z - muS[n + 2]) * rsS[n + 2] * g + bb;
                    v.w = (v.w - muS[n + 3]) * rsS[n + 3] * g + bb;
                }
                *reinterpret_cast<float4*>(&Xs[buf][kk][n4 * 4]) = v;
            }
            __syncthreads();
        }
    }

    #pragma unroll
    for (int i = 0; i < 8; i++) {
        int ch = m0 + ml + i;
        size_t off0 = (size_t)ch * HW_ + n0 + nl0;
        size_t off1 = (size_t)ch * HW_ + n0 + nl1;
        float4 o0, o1;
        o0.x = acc[i][0]; o0.y = acc[i][1]; o0.z = acc[i][2]; o0.w = acc[i][3];
        o1.x = acc[i][4]; o1.y = acc[i][5]; o1.z = acc[i][6]; o1.w = acc[i][7];
        if (R) {
            const float* rb = R + (size_t)b * C_ * HW_;
            float4 r0 = *reinterpret_cast<const float4*>(&rb[off0]);
            float4 r1 = *reinterpret_cast<const float4*>(&rb[off1]);
            o0.x += r0.x; o0.y += r0.y; o0.z += r0.z; o0.w += r0.w;
            o1.x += r1.x; o1.y += r1.y; o1.z += r1.z; o1.w += r1.w;
        }
        *reinterpret_cast<float4*>(&Cb[off0]) = o0;
        *reinterpret_cast<float4*>(&Cb[off1]) = o1;
    }
}

// ---------------- fused depthwise 3x3 (q,k,v in one launch) -----------------
// block: 256 threads -> 8 output rows of one (b,c) plane; smem halo staging.
__global__ void __launch_bounds__(256) dw3_kernel(
    const float* __restrict__ inq, const float* __restrict__ ink,
    const float* __restrict__ inv,
    float* __restrict__ outq, float* __restrict__ outk, float* __restrict__ outv,
    const float* __restrict__ wq, const float* __restrict__ wk,
    const float* __restrict__ wv)
{
    int which = blockIdx.z;
    const float* in  = which == 0 ? inq  : which == 1 ? ink  : inv;
    float*       out = which == 0 ? outq : which == 1 ? outk : outv;
    const float* wt  = which == 0 ? wq   : which == 1 ? wk   : wv;

    int bc = blockIdx.x;
    int c  = bc % C_;
    int y0 = blockIdx.y * 8;
    const float* ib = in + (size_t)bc * HW_;

    __shared__ float s[10][132];
    int tid = threadIdx.x;

    for (int e = tid; e < 10 * 128; e += 256) {
        int rr = e >> 7, col = e & 127;
        int y = y0 - 1 + rr;
        s[rr][col + 1] = (y >= 0 && y < H_) ? ib[(size_t)y * W_ + col] : 0.f;
    }
    if (tid < 10) { s[tid][0] = 0.f; s[tid][129] = 0.f; }

    const float* wp = wt + c * 9;
    float w00 = __ldg(wp + 0), w01 = __ldg(wp + 1), w02 = __ldg(wp + 2);
    float w10 = __ldg(wp + 3), w11 = __ldg(wp + 4), w12 = __ldg(wp + 5);
    float w20 = __ldg(wp + 6), w21 = __ldg(wp + 7), w22 = __ldg(wp + 8);
    __syncthreads();

    int r = tid >> 5;           // output row 0..7
    int cx = (tid & 31) * 4;    // output col base
    float o0 = 0.f, o1 = 0.f, o2 = 0.f, o3 = 0.f;
    #pragma unroll
    for (int ir = 0; ir < 3; ir++) {
        float wa = ir == 0 ? w00 : ir == 1 ? w10 : w20;
        float wb = ir == 0 ? w01 : ir == 1 ? w11 : w21;
        float wc = ir == 0 ? w02 : ir == 1 ? w12 : w22;
        const float* row = s[r + ir];
        float t0 = row[cx], t1 = row[cx + 1], t2 = row[cx + 2];
        float t3 = row[cx + 3], t4 = row[cx + 4], t5 = row[cx + 5];
        o0 = fmaf(t0, wa, fmaf(t1, wb, fmaf(t2, wc, o0)));
        o1 = fmaf(t1, wa, fmaf(t2, wb, fmaf(t3, wc, o1)));
        o2 = fmaf(t2, wa, fmaf(t3, wb, fmaf(t4, wc, o2)));
        o3 = fmaf(t3, wa, fmaf(t4, wb, fmaf(t5, wc, o3)));
    }
    float4 ov; ov.x = o0; ov.y = o1; ov.z = o2; ov.w = o3;
    *reinterpret_cast<float4*>(&out[(size_t)bc * HW_ + (size_t)(y0 + r) * W_ + cx]) = ov;
}

// ---------------- Gram partial: G = q k^T (48x48) + row sumsq ---------------
__global__ void __launch_bounds__(256) gram_partial(
    const float* __restrict__ qd, const float* __restrict__ kd,
    float* __restrict__ part)
{
    int chunk = blockIdx.x;
    int bh    = blockIdx.y;
    int b = bh >> 2, h = bh & 3;
    size_t rowbase = ((size_t)b * C_ + h * DH) * HW_ + (size_t)chunk * 1024;
    const float* qb = qd + rowbase;
    const float* kb = kd + rowbase;

    __shared__ float qs[32][DH + 1];
    __shared__ float ks[32][DH + 1];

    int tid = threadIdx.x;
    int ti = tid & 15, tj = tid >> 4;
    int i0 = ti * 3, j0 = tj * 3;

    float acc[3][3];
    #pragma unroll
    for (int i = 0; i < 3; i++)
        #pragma unroll
        for (int j = 0; j < 3; j++) acc[i][j] = 0.f;
    float nacc = 0.f;

    for (int t = 0; t < 32; t++) {
        __syncthreads();
        #pragma unroll
        for (int r = 0; r < 6; r++) {
            int e = tid + 256 * r;
            int i = e >> 5, nlc = e & 31;
            qs[nlc][i] = qb[(size_t)i * HW_ + t * 32 + nlc];
            ks[nlc][i] = kb[(size_t)i * HW_ + t * 32 + nlc];
        }
        __syncthreads();
        #pragma unroll
        for (int kk = 0; kk < 32; kk++) {
            float a0 = qs[kk][i0], a1 = qs[kk][i0 + 1], a2 = qs[kk][i0 + 2];
            float b0 = ks[kk][j0], b1 = ks[kk][j0 + 1], b2 = ks[kk][j0 + 2];
            acc[0][0] = fmaf(a0, b0, acc[0][0]);
            acc[0][1] = fmaf(a0, b1, acc[0][1]);
            acc[0][2] = fmaf(a0, b2, acc[0][2]);
            acc[1][0] = fmaf(a1, b0, acc[1][0]);
            acc[1][1] = fmaf(a1, b1, acc[1][1]);
            acc[1][2] = fmaf(a1, b2, acc[1][2]);
            acc[2][0] = fmaf(a2, b0, acc[2][0]);
            acc[2][1] = fmaf(a2, b1, acc[2][1]);
            acc[2][2] = fmaf(a2, b2, acc[2][2]);
        }
        if (tid < DH) {
            #pragma unroll
            for (int kk = 0; kk < 32; kk++) {
                float v = qs[kk][tid]; nacc = fmaf(v, v, nacc);
            }
        } else if (tid < 2 * DH) {
            int i = tid - DH;
            #pragma unroll
            for (int kk = 0; kk < 32; kk++) {
                float v = ks[kk][i]; nacc = fmaf(v, v, nacc);
            }
        }
    }

    float* pb = part + ((size_t)bh * 16 + chunk) * 2400;
    #pragma unroll
    for (int i = 0; i < 3; i++)
        #pragma unroll
        for (int j = 0; j < 3; j++)
            pb[(i0 + i) * DH + j0 + j] = acc[i][j];
    if (tid < 2 * DH) pb[2304 + tid] = nacc;
}

// ---------------- reduce partials + norms + softmax -> attn -----------------
__global__ void __launch_bounds__(256) reduce_softmax(
    const float* __restrict__ part, const float* __restrict__ temp,
    float* __restrict__ attn)
{
    int bh = blockIdx.x;
    int h = bh & 3;
    __shared__ float G[DH * DH];
    __shared__ float nq[DH], nk[DH];
    int tid = threadIdx.x;

    for (int e = tid; e < 2400; e += 256) {
        float s = 0.f;
        #pragma unroll
        for (int c = 0; c < 16; c++)
            s += part[((size_t)bh * 16 + c) * 2400 + e];
        if (e < 2304)      G[e] = s;
        else if (e < 2352) nq[e - 2304] = fmaxf(sqrtf(s), 1e-12f);
        else               nk[e - 2352] = fmaxf(sqrtf(s), 1e-12f);
    }
    __syncthreads();

    if (tid < DH) {
        int i = tid;
        float sc = __ldg(&temp[h]) / nq[i];
        float m = -1e30f;
        #pragma unroll 4
        for (int j = 0; j < DH; j++) {
            float s = G[i * DH + j] * sc / nk[j];
            G[i * DH + j] = s;
            m = fmaxf(m, s);
        }
        float sum = 0.f;
        #pragma unroll 4
        for (int j = 0; j < DH; j++) {
            float e = __expf(G[i * DH + j] - m);
            G[i * DH + j] = e;
            sum += e;
        }
        float rs = 1.f / sum;
        #pragma unroll 4
        for (int j = 0; j < DH; j++)
            attn[(size_t)bh * DH * DH + i * DH + j] = G[i * DH + j] * rs;
    }
}

// ---------------- M_b = W_proj @ blockdiag(attn_b) --------------------------
__global__ void __launch_bounds__(256) build_M(
    const float* __restrict__ attn, const float* __restrict__ wp,
    float* __restrict__ M)
{
    int b = blockIdx.x;
    __shared__ float sA[HEADS * DH * DH];
    int tid = threadIdx.x;
    for (int e = tid; e < HEADS * DH * DH; e += 256)
        sA[e] = attn[(size_t)b * HEADS * DH * DH + e];
    __syncthreads();

    for (int e = tid; e < C_ * C_; e += 256) {
        int o = e / C_, cp = e % C_;
        int h = cp / DH, d = cp % DH;
        const float* wrow = wp + (size_t)o * C_ + h * DH;
        const float* arow = sA + h * DH * DH + d;
        float s = 0.f;
        #pragma unroll
        for (int i = 0; i < DH; i++)
            s = fmaf(__ldg(&wrow[i]), arow[i * DH], s);
        M[(size_t)b * C_ * C_ + e] = s;
    }
}

// ---------------- launch ----------------------------------------------------
extern "C" void kernel_launch(void* const* d_in, const int* in_sizes, int n_in,
                              void* d_out, int out_size)
{
    const float* xx     = (const float*)d_in[0];
    const float* q_in   = (const float*)d_in[1];
    const float* ln_w   = (const float*)d_in[2];
    const float* ln_b   = (const float*)d_in[3];
    const float* w_q    = (const float*)d_in[4];
    const float* w_k    = (const float*)d_in[5];
    const float* w_v    = (const float*)d_in[6];
    const float* wd_q   = (const float*)d_in[7];
    const float* wd_k   = (const float*)d_in[8];
    const float* wd_v   = (const float*)d_in[9];
    const float* w_proj = (const float*)d_in[10];
    const float* temp   = (const float*)d_in[11];
    float* out = (float*)d_out;

    float* S = nullptr;
    cudaGetSymbolAddress((void**)&S, g_scratch);
    float* qb   = S + OFF_Q;
    float* kb   = S + OFF_K;
    float* vb   = S + OFF_V;
    float* qd   = S + OFF_QD;
    float* kd   = S + OFF_KD;
    float* vd   = S + OFF_VD;
    float* part = S + OFF_PART;
    float* attn = S + OFF_ATTN;
    float* Mb   = S + OFF_M;
    float* muX  = S + OFF_MUX;
    float* rsX  = S + OFF_RSX;
    float* muQ  = S + OFF_MUQ;
    float* rsQ  = S + OFF_RSQ;

    // 1. per-pixel LN stats for xx and q_in
    ln_stats<<<dim3(512, 2), 256>>>(xx, muX, rsX, q_in, muQ, rsQ);

    // 2. 1x1 convs with fused LN on the input
    dim3 gg(HW_ / BN, C_ / BM, B_);
    gemm_k192<<<gg, 128>>>(q_in, w_q, qb, nullptr, muQ, rsQ, ln_w, ln_b, 0);
    gemm_k192<<<gg, 128>>>(xx,   w_k, kb, nullptr, muX, rsX, ln_w, ln_b, 0);
    gemm_k192<<<gg, 128>>>(xx,   w_v, vb, nullptr, muX, rsX, ln_w, ln_b, 0);

    // 3. depthwise 3x3 (all three in one launch)
    dw3_kernel<<<dim3(B_ * C_, H_ / 8, 3), 256>>>(
        qb, kb, vb, qd, kd, vd, wd_q, wd_k, wd_v);

    // 4. Gram + norms + softmax
    gram_partial<<<dim3(16, 32), 256>>>(qd, kd, part);
    reduce_softmax<<<32, 256>>>(part, temp, attn);

    // 5. fold attn@v and proj into per-batch M, then one GEMM + residual
    build_M<<<8, 256>>>(attn, w_proj, Mb);
    gemm_k192<<<gg, 128>>>(vd, Mb, out, q_in, nullptr, nullptr, nullptr, nullptr,
                           C_ * C_);
}

// round 5
// speedup vs baseline: 1.9233x; 1.2747x over previous
#include <cuda_runtime.h>
#include <cuda_bf16.h>
#include <cstddef>
#include <cstdint>

#define B_    8
#define C_    192
#define H_    128
#define W_    128
#define HW_   16384
#define HEADS 4
#define DH    48

// ---------------- scratch ----------------------------------------------------
#define TEN   ((size_t)B_ * C_ * HW_)
#define OFF_Q    ((size_t)0)
#define OFF_K    (TEN * 1)
#define OFF_V    (TEN * 2)
#define OFF_QD   (TEN * 3)
#define OFF_KD   (TEN * 4)
#define OFF_VD   (TEN * 5)
#define OFF_PART (TEN * 6)
#define PART_SZ  ((size_t)32 * 16 * 2400)
#define OFF_ATTN (OFF_PART + PART_SZ)
#define ATTN_SZ  ((size_t)32 * 48 * 48)
#define OFF_M    (OFF_ATTN + ATTN_SZ)
#define M_SZ     ((size_t)8 * 192 * 192)
#define NPIX     ((size_t)B_ * HW_)
#define OFF_MUX  (OFF_M + M_SZ)
#define OFF_RSX  (OFF_MUX + NPIX)
#define OFF_MUQ  (OFF_RSX + NPIX)
#define OFF_RSQ  (OFF_MUQ + NPIX)
// bf16 weight planes: 11 matrices (wq,wk,wv,Mb[0..7]) x 36864 bf16 = 18432 floats
#define PLANE_FL 18432
#define OFF_WHI  (OFF_RSQ + NPIX)
#define OFF_WLO  (OFF_WHI + (size_t)11 * PLANE_FL)
#define TOTAL_SCRATCH (OFF_WLO + (size_t)11 * PLANE_FL)

__device__ __align__(256) float g_scratch[TOTAL_SCRATCH];

// ---------------- LN stats ----------------------------------------------------
__global__ void __launch_bounds__(256) ln_stats(
    const float* __restrict__ in0, float* __restrict__ mu0, float* __restrict__ rs0,
    const float* __restrict__ in1, float* __restrict__ mu1, float* __restrict__ rs1)
{
    const float* in = blockIdx.y ? in1 : in0;
    float* mu = blockIdx.y ? mu1 : mu0;
    float* rs = blockIdx.y ? rs1 : rs0;
    int p = blockIdx.x * 256 + threadIdx.x;
    int b = p >> 14;
    int pix = p & (HW_ - 1);
    const float* base = in + (size_t)b * C_ * HW_ + pix;
    float s = 0.f, ss = 0.f;
    #pragma unroll 8
    for (int c = 0; c < C_; c++) {
        float v = base[(size_t)c * HW_];
        s += v; ss += v * v;
    }
    float m = s * (1.f / C_);
    float var = ss * (1.f / C_) - m * m;
    mu[p] = m;
    rs[p] = rsqrtf(var + 1e-5f);
}

// ---------------- W -> row-major bf16 hi/lo planes ----------------------------
__global__ void __launch_bounds__(256) wconv(
    const float* __restrict__ src, __nv_bfloat16* __restrict__ dhi,
    __nv_bfloat16* __restrict__ dlo, size_t srcStride)
{
    int mat = blockIdx.y;
    src += (size_t)mat * srcStride;
    dhi += (size_t)mat * (C_ * C_);
    dlo += (size_t)mat * (C_ * C_);
    for (int idx = blockIdx.x * 256 + threadIdx.x; idx < C_ * C_;
         idx += gridDim.x * 256) {
        float v = src[idx];
        __nv_bfloat16 h = __float2bfloat16(v);
        __nv_bfloat16 l = __float2bfloat16(v - __bfloat162float(h));
        dhi[idx] = h;
        dlo[idx] = l;
    }
}

// ---------------- mma.sync bf16 helper -----------------------------------------
__device__ __forceinline__ void mma_bf16(float* c, const uint32_t* a,
                                         const uint32_t* b)
{
    asm volatile(
        "mma.sync.aligned.m16n8k16.row.col.f32.bf16.bf16.f32 "
        "{%0,%1,%2,%3}, {%4,%5,%6,%7}, {%8,%9}, {%0,%1,%2,%3};"
        : "+f"(c[0]), "+f"(c[1]), "+f"(c[2]), "+f"(c[3])
        : "r"(a[0]), "r"(a[1]), "r"(a[2]), "r"(a[3]), "r"(b[0]), "r"(b[1]));
}

__device__ __forceinline__ uint32_t pack_bf2(__nv_bfloat16 a, __nv_bfloat16 b) {
    union { __nv_bfloat16 h[2]; uint32_t u; } p;
    p.h[0] = a; p.h[1] = b;
    return p.u;
}

// ---------------- tensor-core GEMM via mma.sync --------------------------------
// C[m,p] = sum_k W[m,k] * LN(X)[k,p] (+ residual). fp32 via bf16 hi/lo split.
// Tile: BM=64, BN=128, BK=32. 128 threads / 4 warps (warp w: n in [w*32, w*32+32)).
__global__ void __launch_bounds__(128) mma_gemm(
    const float* __restrict__ X,
    const __nv_bfloat16* __restrict__ whi, const __nv_bfloat16* __restrict__ wlo,
    int wStride,                       // elems per matrix (0 = shared matrix)
    float* __restrict__ Out, const float* __restrict__ R,
    const float* __restrict__ muA, const float* __restrict__ rsA,
    const float* __restrict__ gw, const float* __restrict__ gb)
{
    int np0 = blockIdx.x * 128;
    int m0  = blockIdx.y * 64;
    int b   = blockIdx.z;
    const float* Xb = X + (size_t)b * C_ * HW_;
    const __nv_bfloat16* wH = whi + (size_t)b * wStride;
    const __nv_bfloat16* wL = wlo + (size_t)b * wStride;
    const bool doLN = (muA != nullptr);

    __shared__ uint32_t AsH[64][20], AsL[64][20];     // [m][k-pair], pad 20
    __shared__ uint32_t BsH[128][20], BsL[128][20];   // [n][k-pair], pad 20
    __shared__ float gwS[C_], gbS[C_];

    int tid = threadIdx.x;
    int w   = tid >> 5;
    int lid = tid & 31;
    int g   = lid >> 2;       // group row 0..7
    int t   = lid & 3;        // thread-in-group

    float mu_ = 0.f, rs_ = 0.f;
    if (doLN) {
        mu_ = muA[(size_t)b * HW_ + np0 + tid];
        rs_ = rsA[(size_t)b * HW_ + np0 + tid];
        if (tid < C_) { gwS[tid] = gw[tid]; gbS[tid] = gb[tid]; }
        if (tid < C_ - 128) { gwS[128 + tid] = gw[128 + tid]; gbS[128 + tid] = gb[128 + tid]; }
    }
    __syncthreads();

    float acc[16][4];
    #pragma unroll
    for (int i = 0; i < 16; i++)
        #pragma unroll
        for (int j = 0; j < 4; j++) acc[i][j] = 0.f;

    const float* xc = Xb + np0 + tid;   // this thread's pixel column

    for (int tile = 0; tile < 6; tile++) {
        int k0 = tile * 32;
        // ---- stage A (64 rows x 16 words, hi+lo) ----
        #pragma unroll
        for (int it = 0; it < 2; it++) {
            int idx = tid + 128 * it;          // 0..255
            int row = idx >> 2, w4 = idx & 3;
            const uint4 vh = *reinterpret_cast<const uint4*>(
                &wH[(size_t)(m0 + row) * C_ + k0 + w4 * 8]);
            const uint4 vl = *reinterpret_cast<const uint4*>(
                &wL[(size_t)(m0 + row) * C_ + k0 + w4 * 8]);
            AsH[row][w4 * 4 + 0] = vh.x; AsH[row][w4 * 4 + 1] = vh.y;
            AsH[row][w4 * 4 + 2] = vh.z; AsH[row][w4 * 4 + 3] = vh.w;
            AsL[row][w4 * 4 + 0] = vl.x; AsL[row][w4 * 4 + 1] = vl.y;
            AsL[row][w4 * 4 + 2] = vl.z; AsL[row][w4 * 4 + 3] = vl.w;
        }
        // ---- stage B (this thread's pixel, 32 k values -> 16 words) ----
        #pragma unroll
        for (int kk = 0; kk < 32; kk += 2) {
            int k = k0 + kk;
            float x0 = xc[(size_t)k * HW_];
            float x1 = xc[(size_t)(k + 1) * HW_];
            if (doLN) {
                x0 = (x0 - mu_) * rs_ * gwS[k] + gbS[k];
                x1 = (x1 - mu_) * rs_ * gwS[k + 1] + gbS[k + 1];
            }
            __nv_bfloat16 h0 = __float2bfloat16(x0);
            __nv_bfloat16 h1 = __float2bfloat16(x1);
            __nv_bfloat16 l0 = __float2bfloat16(x0 - __bfloat162float(h0));
            __nv_bfloat16 l1 = __float2bfloat16(x1 - __bfloat162float(h1));
            BsH[tid][kk >> 1] = pack_bf2(h0, h1);
            BsL[tid][kk >> 1] = pack_bf2(l0, l1);
        }
        __syncthreads();

        // ---- compute: 2 k-steps of 16 ----
        #pragma unroll
        for (int s = 0; s < 2; s++) {
            uint32_t ah[4][4], al[4][4];
            #pragma unroll
            for (int im = 0; im < 4; im++) {
                int r = im * 16 + g;
                ah[im][0] = AsH[r][s * 8 + t];
                ah[im][1] = AsH[r + 8][s * 8 + t];
                ah[im][2] = AsH[r][s * 8 + t + 4];
                ah[im][3] = AsH[r + 8][s * 8 + t + 4];
                al[im][0] = AsL[r][s * 8 + t];
                al[im][1] = AsL[r + 8][s * 8 + t];
                al[im][2] = AsL[r][s * 8 + t + 4];
                al[im][3] = AsL[r + 8][s * 8 + t + 4];
            }
            uint32_t bh[4][2], bl[4][2];
            #pragma unroll
            for (int in_ = 0; in_ < 4; in_++) {
                int n = w * 32 + in_ * 8 + g;
                bh[in_][0] = BsH[n][s * 8 + t];
                bh[in_][1] = BsH[n][s * 8 + t + 4];
                bl[in_][0] = BsL[n][s * 8 + t];
                bl[in_][1] = BsL[n][s * 8 + t + 4];
            }
            #pragma unroll
            for (int im = 0; im < 4; im++)
                #pragma unroll
                for (int in_ = 0; in_ < 4; in_++) {
                    float* c = acc[im * 4 + in_];
                    mma_bf16(c, ah[im], bh[in_]);
                    mma_bf16(c, ah[im], bl[in_]);
                    mma_bf16(c, al[im], bh[in_]);
                }
        }
        __syncthreads();
    }

    // ---- epilogue ----
    float* Ob = Out + (size_t)b * C_ * HW_;
    const float* Rb = R ? (R + (size_t)b * C_ * HW_) : nullptr;
    #pragma unroll
    for (int im = 0; im < 4; im++) {
        #pragma unroll
        for (int in_ = 0; in_ < 4; in_++) {
            const float* c = acc[im * 4 + in_];
            int row = m0 + im * 16 + g;
            int col = np0 + w * 32 + in_ * 8 + t * 2;
            float2 v0 = make_float2(c[0], c[1]);
            float2 v1 = make_float2(c[2], c[3]);
            size_t o0 = (size_t)row * HW_ + col;
            size_t o1 = (size_t)(row + 8) * HW_ + col;
            if (Rb) {
                float2 r0 = *reinterpret_cast<const float2*>(&Rb[o0]);
                float2 r1 = *reinterpret_cast<const float2*>(&Rb[o1]);
                v0.x += r0.x; v0.y += r0.y;
                v1.x += r1.x; v1.y += r1.y;
            }
            *reinterpret_cast<float2*>(&Ob[o0]) = v0;
            *reinterpret_cast<float2*>(&Ob[o1]) = v1;
        }
    }
}

// ---------------- depthwise 3x3 (q,k,v fused) ----------------------------------
__global__ void __launch_bounds__(256) dw3_kernel(
    const float* __restrict__ inq, const float* __restrict__ ink,
    const float* __restrict__ inv,
    float* __restrict__ outq, float* __restrict__ outk, float* __restrict__ outv,
    const float* __restrict__ wq, const float* __restrict__ wk,
    const float* __restrict__ wv)
{
    int which = blockIdx.z;
    const float* in  = which == 0 ? inq  : which == 1 ? ink  : inv;
    float*       out = which == 0 ? outq : which == 1 ? outk : outv;
    const float* wt  = which == 0 ? wq   : which == 1 ? wk   : wv;

    int bc = blockIdx.x;
    int c  = bc % C_;
    int y0 = blockIdx.y * 8;
    const float* ib = in + (size_t)bc * HW_;

    __shared__ float s[10][132];
    int tid = threadIdx.x;

    for (int e = tid; e < 10 * 128; e += 256) {
        int rr = e >> 7, col = e & 127;
        int y = y0 - 1 + rr;
        s[rr][col + 1] = (y >= 0 && y < H_) ? ib[(size_t)y * W_ + col] : 0.f;
    }
    if (tid < 10) { s[tid][0] = 0.f; s[tid][129] = 0.f; }

    const float* wp = wt + c * 9;
    float w00 = __ldg(wp + 0), w01 = __ldg(wp + 1), w02 = __ldg(wp + 2);
    float w10 = __ldg(wp + 3), w11 = __ldg(wp + 4), w12 = __ldg(wp + 5);
    float w20 = __ldg(wp + 6), w21 = __ldg(wp + 7), w22 = __ldg(wp + 8);
    __syncthreads();

    int r = tid >> 5;
    int cx = (tid & 31) * 4;
    float o0 = 0.f, o1 = 0.f, o2 = 0.f, o3 = 0.f;
    #pragma unroll
    for (int ir = 0; ir < 3; ir++) {
        float wa = ir == 0 ? w00 : ir == 1 ? w10 : w20;
        float wb = ir == 0 ? w01 : ir == 1 ? w11 : w21;
        float wc = ir == 0 ? w02 : ir == 1 ? w12 : w22;
        const float* row = s[r + ir];
        float t0 = row[cx], t1 = row[cx + 1], t2 = row[cx + 2];
        float t3 = row[cx + 3], t4 = row[cx + 4], t5 = row[cx + 5];
        o0 = fmaf(t0, wa, fmaf(t1, wb, fmaf(t2, wc, o0)));
        o1 = fmaf(t1, wa, fmaf(t2, wb, fmaf(t3, wc, o1)));
        o2 = fmaf(t2, wa, fmaf(t3, wb, fmaf(t4, wc, o2)));
        o3 = fmaf(t3, wa, fmaf(t4, wb, fmaf(t5, wc, o3)));
    }
    float4 ov; ov.x = o0; ov.y = o1; ov.z = o2; ov.w = o3;
    *reinterpret_cast<float4*>(&out[(size_t)bc * HW_ + (size_t)(y0 + r) * W_ + cx]) = ov;
}

// ---------------- Gram partial --------------------------------------------------
__global__ void __launch_bounds__(256) gram_partial(
    const float* __restrict__ qd, const float* __restrict__ kd,
    float* __restrict__ part)
{
    int chunk = blockIdx.x;
    int bh    = blockIdx.y;
    int b = bh >> 2, h = bh & 3;
    size_t rowbase = ((size_t)b * C_ + h * DH) * HW_ + (size_t)chunk * 1024;
    const float* qb = qd + rowbase;
    const float* kb = kd + rowbase;

    __shared__ float qs[32][DH + 1];
    __shared__ float ks[32][DH + 1];

    int tid = threadIdx.x;
    int ti = tid & 15, tj = tid >> 4;
    int i0 = ti * 3, j0 = tj * 3;

    float acc[3][3];
    #pragma unroll
    for (int i = 0; i < 3; i++)
        #pragma unroll
        for (int j = 0; j < 3; j++) acc[i][j] = 0.f;
    float nacc = 0.f;

    for (int t = 0; t < 32; t++) {
        __syncthreads();
        #pragma unroll
        for (int r = 0; r < 6; r++) {
            int e = tid + 256 * r;
            int i = e >> 5, nlc = e & 31;
            qs[nlc][i] = qb[(size_t)i * HW_ + t * 32 + nlc];
            ks[nlc][i] = kb[(size_t)i * HW_ + t * 32 + nlc];
        }
        __syncthreads();
        #pragma unroll
        for (int kk = 0; kk < 32; kk++) {
            float a0 = qs[kk][i0], a1 = qs[kk][i0 + 1], a2 = qs[kk][i0 + 2];
            float b0 = ks[kk][j0], b1 = ks[kk][j0 + 1], b2 = ks[kk][j0 + 2];
            acc[0][0] = fmaf(a0, b0, acc[0][0]);
            acc[0][1] = fmaf(a0, b1, acc[0][1]);
            acc[0][2] = fmaf(a0, b2, acc[0][2]);
            acc[1][0] = fmaf(a1, b0, acc[1][0]);
            acc[1][1] = fmaf(a1, b1, acc[1][1]);
            acc[1][2] = fmaf(a1, b2, acc[1][2]);
            acc[2][0] = fmaf(a2, b0, acc[2][0]);
            acc[2][1] = fmaf(a2, b1, acc[2][1]);
            acc[2][2] = fmaf(a2, b2, acc[2][2]);
        }
        if (tid < DH) {
            #pragma unroll
            for (int kk = 0; kk < 32; kk++) {
                float v = qs[kk][tid]; nacc = fmaf(v, v, nacc);
            }
        } else if (tid < 2 * DH) {
            int i = tid - DH;
            #pragma unroll
            for (int kk = 0; kk < 32; kk++) {
                float v = ks[kk][i]; nacc = fmaf(v, v, nacc);
            }
        }
    }

    float* pb = part + ((size_t)bh * 16 + chunk) * 2400;
    #pragma unroll
    for (int i = 0; i < 3; i++)
        #pragma unroll
        for (int j = 0; j < 3; j++)
            pb[(i0 + i) * DH + j0 + j] = acc[i][j];
    if (tid < 2 * DH) pb[2304 + tid] = nacc;
}

// ---------------- reduce partials + norms + softmax -----------------------------
__global__ void __launch_bounds__(256) reduce_softmax(
    const float* __restrict__ part, const float* __restrict__ temp,
    float* __restrict__ attn)
{
    int bh = blockIdx.x;
    int h = bh & 3;
    __shared__ float G[DH * DH];
    __shared__ float nq[DH], nk[DH];
    int tid = threadIdx.x;

    for (int e = tid; e < 2400; e += 256) {
        float s = 0.f;
        #pragma unroll
        for (int c = 0; c < 16; c++)
            s += part[((size_t)bh * 16 + c) * 2400 + e];
        if (e < 2304)      G[e] = s;
        else if (e < 2352) nq[e - 2304] = fmaxf(sqrtf(s), 1e-12f);
        else               nk[e - 2352] = fmaxf(sqrtf(s), 1e-12f);
    }
    __syncthreads();

    if (tid < DH) {
        int i = tid;
        float sc = __ldg(&temp[h]) / nq[i];
        float m = -1e30f;
        #pragma unroll 4
        for (int j = 0; j < DH; j++) {
            float s = G[i * DH + j] * sc / nk[j];
            G[i * DH + j] = s;
            m = fmaxf(m, s);
        }
        float sum = 0.f;
        #pragma unroll 4
        for (int j = 0; j < DH; j++) {
            float e = __expf(G[i * DH + j] - m);
            G[i * DH + j] = e;
            sum += e;
        }
        float rs = 1.f / sum;
        #pragma unroll 4
        for (int j = 0; j < DH; j++)
            attn[(size_t)bh * DH * DH + i * DH + j] = G[i * DH + j] * rs;
    }
}

// ---------------- M_b = W_proj @ blockdiag(attn_b) ------------------------------
__global__ void __launch_bounds__(256) build_M(
    const float* __restrict__ attn, const float* __restrict__ wp,
    float* __restrict__ M)
{
    int b = blockIdx.x;
    __shared__ float sA[HEADS * DH * DH];
    int tid = threadIdx.x;
    for (int e = tid; e < HEADS * DH * DH; e += 256)
        sA[e] = attn[(size_t)b * HEADS * DH * DH + e];
    __syncthreads();

    for (int e = tid; e < C_ * C_; e += 256) {
        int o = e / C_, cp = e % C_;
        int h = cp / DH, d = cp % DH;
        const float* wrow = wp + (size_t)o * C_ + h * DH;
        const float* arow = sA + h * DH * DH + d;
        float s = 0.f;
        #pragma unroll
        for (int i = 0; i < DH; i++)
            s = fmaf(__ldg(&wrow[i]), arow[i * DH], s);
        M[(size_t)b * C_ * C_ + e] = s;
    }
}

// ---------------- launch --------------------------------------------------------
extern "C" void kernel_launch(void* const* d_in, const int* in_sizes, int n_in,
                              void* d_out, int out_size)
{
    const float* xx     = (const float*)d_in[0];
    const float* q_in   = (const float*)d_in[1];
    const float* ln_w   = (const float*)d_in[2];
    const float* ln_b   = (const float*)d_in[3];
    const float* w_q    = (const float*)d_in[4];
    const float* w_k    = (const float*)d_in[5];
    const float* w_v    = (const float*)d_in[6];
    const float* wd_q   = (const float*)d_in[7];
    const float* wd_k   = (const float*)d_in[8];
    const float* wd_v   = (const float*)d_in[9];
    const float* w_proj = (const float*)d_in[10];
    const float* temp   = (const float*)d_in[11];
    float* out = (float*)d_out;

    float* S = nullptr;
    cudaGetSymbolAddress((void**)&S, g_scratch);
    float* qb   = S + OFF_Q;
    float* kb   = S + OFF_K;
    float* vb   = S + OFF_V;
    float* qd   = S + OFF_QD;
    float* kd   = S + OFF_KD;
    float* vd   = S + OFF_VD;
    float* part = S + OFF_PART;
    float* attn = S + OFF_ATTN;
    float* Mb   = S + OFF_M;
    float* muX  = S + OFF_MUX;
    float* rsX  = S + OFF_RSX;
    float* muQ  = S + OFF_MUQ;
    float* rsQ  = S + OFF_RSQ;
    __nv_bfloat16* whi = (__nv_bfloat16*)(S + OFF_WHI);
    __nv_bfloat16* wlo = (__nv_bfloat16*)(S + OFF_WLO);
    const int PLANE = C_ * C_;   // 36864 bf16 elems per matrix

    // 1. LN stats
    ln_stats<<<dim3(512, 2), 256>>>(xx, muX, rsX, q_in, muQ, rsQ);

    // 2. weight split (slots 0..2)
    wconv<<<dim3(36, 1), 256>>>(w_q, whi + 0 * PLANE, wlo + 0 * PLANE, 0);
    wconv<<<dim3(36, 1), 256>>>(w_k, whi + 1 * PLANE, wlo + 1 * PLANE, 0);
    wconv<<<dim3(36, 1), 256>>>(w_v, whi + 2 * PLANE, wlo + 2 * PLANE, 0);

    // 3. tensor-core 1x1 convs with fused LN
    dim3 gg(HW_ / 128, C_ / 64, B_);
    mma_gemm<<<gg, 128>>>(q_in, whi + 0 * PLANE, wlo + 0 * PLANE, 0,
                          qb, nullptr, muQ, rsQ, ln_w, ln_b);
    mma_gemm<<<gg, 128>>>(xx,   whi + 1 * PLANE, wlo + 1 * PLANE, 0,
                          kb, nullptr, muX, rsX, ln_w, ln_b);
    mma_gemm<<<gg, 128>>>(xx,   whi + 2 * PLANE, wlo + 2 * PLANE, 0,
                          vb, nullptr, muX, rsX, ln_w, ln_b);

    // 4. depthwise 3x3
    dw3_kernel<<<dim3(B_ * C_, H_ / 8, 3), 256>>>(
        qb, kb, vb, qd, kd, vd, wd_q, wd_k, wd_v);

    // 5. Gram + softmax
    gram_partial<<<dim3(16, 32), 256>>>(qd, kd, part);
    reduce_softmax<<<32, 256>>>(part, temp, attn);

    // 6. fold attn@v with proj, split per-batch Mb (slots 3..10), final GEMM
    build_M<<<8, 256>>>(attn, w_proj, Mb);
    wconv<<<dim3(36, 8), 256>>>(Mb, whi + 3 * PLANE, wlo + 3 * PLANE,
                                (size_t)C_ * C_);
    mma_gemm<<<gg, 128>>>(vd, whi + 3 * PLANE, wlo + 3 * PLANE, PLANE,
                          out, q_in, nullptr, nullptr, nullptr, nullptr);
}

// round 6
// speedup vs baseline: 2.0983x; 1.0910x over previous
#include <cuda_runtime.h>
#include <cuda_bf16.h>
#include <cstddef>
#include <cstdint>

#define B_    8
#define C_    192
#define H_    128
#define W_    128
#define HW_   16384
#define HEADS 4
#define DH    48

// ---------------- scratch ----------------------------------------------------
#define TEN   ((size_t)B_ * C_ * HW_)
#define OFF_Q    ((size_t)0)
#define OFF_K    (TEN * 1)
#define OFF_V    (TEN * 2)
#define OFF_QD   (TEN * 3)
#define OFF_KD   (TEN * 4)
#define OFF_VD   (TEN * 5)
#define OFF_PART (TEN * 6)
#define PART_SZ  ((size_t)32 * 16 * 2400)
#define OFF_ATTN (OFF_PART + PART_SZ)
#define ATTN_SZ  ((size_t)32 * 48 * 48)
#define OFF_M    (OFF_ATTN + ATTN_SZ)
#define M_SZ     ((size_t)8 * 192 * 192)
#define NPIX     ((size_t)B_ * HW_)
#define OFF_MUX  (OFF_M + M_SZ)
#define OFF_RSX  (OFF_MUX + NPIX)
#define OFF_MUQ  (OFF_RSX + NPIX)
#define OFF_RSQ  (OFF_MUQ + NPIX)
// bf16 planes: slots 0=wq, 1=wk, 2=wv, 3..10=Mb[8]; each 36864 bf16 = 18432 fl
#define PLANE_FL 18432
#define OFF_WHI  (OFF_RSQ + NPIX)
#define OFF_WLO  (OFF_WHI + (size_t)11 * PLANE_FL)
#define TOTAL_SCRATCH (OFF_WLO + (size_t)11 * PLANE_FL)

__device__ __align__(256) float g_scratch[TOTAL_SCRATCH];

// ---------------- LN stats ----------------------------------------------------
__global__ void __launch_bounds__(256) ln_stats(
    const float* __restrict__ in0, float* __restrict__ mu0, float* __restrict__ rs0,
    const float* __restrict__ in1, float* __restrict__ mu1, float* __restrict__ rs1)
{
    const float* in = blockIdx.y ? in1 : in0;
    float* mu = blockIdx.y ? mu1 : mu0;
    float* rs = blockIdx.y ? rs1 : rs0;
    int p = blockIdx.x * 256 + threadIdx.x;
    int b = p >> 14;
    int pix = p & (HW_ - 1);
    const float* base = in + (size_t)b * C_ * HW_ + pix;
    float s = 0.f, ss = 0.f;
    #pragma unroll 8
    for (int c = 0; c < C_; c++) {
        float v = base[(size_t)c * HW_];
        s += v; ss += v * v;
    }
    float m = s * (1.f / C_);
    float var = ss * (1.f / C_) - m * m;
    mu[p] = m;
    rs[p] = rsqrtf(var + 1e-5f);
}

// ---------------- W -> row-major bf16 hi/lo planes ----------------------------
__global__ void __launch_bounds__(256) wconv(
    const float* __restrict__ src, __nv_bfloat16* __restrict__ dhi,
    __nv_bfloat16* __restrict__ dlo, size_t srcStride)
{
    int mat = blockIdx.y;
    src += (size_t)mat * srcStride;
    dhi += (size_t)mat * (C_ * C_);
    dlo += (size_t)mat * (C_ * C_);
    for (int idx = blockIdx.x * 256 + threadIdx.x; idx < C_ * C_;
         idx += gridDim.x * 256) {
        float v = src[idx];
        __nv_bfloat16 h = __float2bfloat16(v);
        __nv_bfloat16 l = __float2bfloat16(v - __bfloat162float(h));
        dhi[idx] = h;
        dlo[idx] = l;
    }
}

// ---------------- mma helpers ---------------------------------------------------
__device__ __forceinline__ void mma_bf16(float* c, const uint32_t* a,
                                         const uint32_t* b)
{
    asm volatile(
        "mma.sync.aligned.m16n8k16.row.col.f32.bf16.bf16.f32 "
        "{%0,%1,%2,%3}, {%4,%5,%6,%7}, {%8,%9}, {%0,%1,%2,%3};"
        : "+f"(c[0]), "+f"(c[1]), "+f"(c[2]), "+f"(c[3])
        : "r"(a[0]), "r"(a[1]), "r"(a[2]), "r"(a[3]), "r"(b[0]), "r"(b[1]));
}
__device__ __forceinline__ void ldsm_x4(uint32_t* r, uint32_t addr)
{
    asm volatile("ldmatrix.sync.aligned.m8n8.x4.shared.b16 {%0,%1,%2,%3}, [%4];"
        : "=r"(r[0]), "=r"(r[1]), "=r"(r[2]), "=r"(r[3]) : "r"(addr));
}
__device__ __forceinline__ uint32_t pack_bf2(__nv_bfloat16 a, __nv_bfloat16 b) {
    union { __nv_bfloat16 h[2]; uint32_t u; } p;
    p.h[0] = a; p.h[1] = b;
    return p.u;
}

// ---------------- tensor-core GEMM v2 -------------------------------------------
// C[m,p] = sum_k W[m,k] * LN(X)[k,p] (+ residual), bf16 hi/lo 3-product split.
// One CTA: 128 pixels x ALL M rows (mTiles x 64). B staged once (hi/lo, smem),
// A per m-tile. 256 threads / 8 warps: wm = w>>2 (m 32), wn = w&3 (n 32).
// smem word layout (stride 100/row, conflict-free for LDSM):
//   Bh[128][100] @0, Bl @12800, Ah[64][100] @25600, Al @32000  (153600 bytes)
__global__ void __launch_bounds__(256) mma_gemm2(
    const float* __restrict__ X,
    const __nv_bfloat16* __restrict__ whi, const __nv_bfloat16* __restrict__ wlo,
    int wStride, int mTiles,
    float* __restrict__ Out0, float* __restrict__ Out1,
    const float* __restrict__ R,
    const float* __restrict__ muA, const float* __restrict__ rsA,
    const float* __restrict__ gw, const float* __restrict__ gb)
{
    extern __shared__ uint32_t sm[];
    uint32_t* Bh = sm;
    uint32_t* Bl = sm + 12800;
    uint32_t* Ah = sm + 25600;
    uint32_t* Al = sm + 32000;

    int tid  = threadIdx.x;
    int w    = tid >> 5, lane = tid & 31;
    int wm   = w >> 2,  wn = w & 3;
    int g    = lane >> 2, t = lane & 3;
    int np0  = blockIdx.x * 128;
    int b    = blockIdx.y;
    const float* Xb = X + (size_t)b * C_ * HW_;
    const __nv_bfloat16* wH = whi + (size_t)b * wStride;
    const __nv_bfloat16* wL = wlo + (size_t)b * wStride;
    const bool doLN = (muA != nullptr);

    // ---- stage B once: 128 pixels x 192 k, LN + hi/lo split ----
    {
        int p = tid & 127, kh = tid >> 7;      // 2 threads per pixel
        float mu_ = 0.f, rs_ = 0.f;
        if (doLN) {
            mu_ = muA[(size_t)b * HW_ + np0 + p];
            rs_ = rsA[(size_t)b * HW_ + np0 + p];
        }
        const float* xc = Xb + np0 + p;
        #pragma unroll
        for (int i = 0; i < 48; i++) {
            int kp = kh * 48 + i, k = kp * 2;
            float x0 = xc[(size_t)k * HW_];
            float x1 = xc[(size_t)(k + 1) * HW_];
            if (doLN) {
                x0 = (x0 - mu_) * rs_ * __ldg(&gw[k])     + __ldg(&gb[k]);
                x1 = (x1 - mu_) * rs_ * __ldg(&gw[k + 1]) + __ldg(&gb[k + 1]);
            }
            __nv_bfloat16 h0 = __float2bfloat16(x0);
            __nv_bfloat16 h1 = __float2bfloat16(x1);
            __nv_bfloat16 l0 = __float2bfloat16(x0 - __bfloat162float(h0));
            __nv_bfloat16 l1 = __float2bfloat16(x1 - __bfloat162float(h1));
            Bh[p * 100 + kp] = pack_bf2(h0, h1);
            Bl[p * 100 + kp] = pack_bf2(l0, l1);
        }
    }
    __syncthreads();

    // ---- lane-level ldmatrix base addresses ----
    uint32_t BhA = (uint32_t)__cvta_generic_to_shared(Bh);
    uint32_t AhA = (uint32_t)__cvta_generic_to_shared(Ah);
    uint32_t baseB[2], baseA[2];
    #pragma unroll
    for (int in2 = 0; in2 < 2; in2++) {
        int row = wn * 32 + in2 * 16 + ((lane >> 4) << 3) + (lane & 7);
        baseB[in2] = BhA + (uint32_t)((row * 100 + ((lane >> 3) & 1) * 4) * 4);
    }
    #pragma unroll
    for (int im = 0; im < 2; im++) {
        int row = wm * 32 + im * 16 + (lane & 15);
        baseA[im] = AhA + (uint32_t)((row * 100 + (lane >> 4) * 4) * 4);
    }

    for (int mt = 0; mt < mTiles; mt++) {
        // ---- stage A tile (64 rows x 192 k, hi/lo) ----
        #pragma unroll
        for (int i = 0; i < 6; i++) {
            int idx = tid + 256 * i;              // 0..1535
            int row = idx / 24, j = idx % 24;
            size_t go = (size_t)(mt * 64 + row) * C_ + j * 8;
            uint4 vh = *reinterpret_cast<const uint4*>(&wH[go]);
            uint4 vl = *reinterpret_cast<const uint4*>(&wL[go]);
            uint32_t* dh = &Ah[row * 100 + j * 4];
            dh[0] = vh.x; dh[1] = vh.y; dh[2] = vh.z; dh[3] = vh.w;
            uint32_t* dl = &Al[row * 100 + j * 4];
            dl[0] = vl.x; dl[1] = vl.y; dl[2] = vl.z; dl[3] = vl.w;
        }
        __syncthreads();

        float acc[8][4];
        #pragma unroll
        for (int i = 0; i < 8; i++)
            #pragma unroll
            for (int j = 0; j < 4; j++) acc[i][j] = 0.f;

        #pragma unroll
        for (int s = 0; s < 12; s++) {
            uint32_t ah[2][4], al[2][4], bh[2][4], bl[2][4];
            #pragma unroll
            for (int im = 0; im < 2; im++) {
                ldsm_x4(ah[im], baseA[im] + s * 32);
                ldsm_x4(al[im], baseA[im] + 25600 + s * 32);
            }
            #pragma unroll
            for (int in2 = 0; in2 < 2; in2++) {
                ldsm_x4(bh[in2], baseB[in2] + s * 32);
                ldsm_x4(bl[in2], baseB[in2] + 51200 + s * 32);
            }
            #pragma unroll
            for (int im = 0; im < 2; im++)
                #pragma unroll
                for (int in_ = 0; in_ < 4; in_++) {
                    const uint32_t* bhf = &bh[in_ >> 1][(in_ & 1) * 2];
                    const uint32_t* blf = &bl[in_ >> 1][(in_ & 1) * 2];
                    float* c = acc[im * 4 + in_];
                    mma_bf16(c, ah[im], bhf);
                    mma_bf16(c, ah[im], blf);
                    mma_bf16(c, al[im], bhf);
                }
        }

        // ---- epilogue ----
        #pragma unroll
        for (int im = 0; im < 2; im++) {
            #pragma unroll
            for (int in_ = 0; in_ < 4; in_++) {
                const float* c = acc[im * 4 + in_];
                int grow = mt * 64 + wm * 32 + im * 16 + g;
                int col  = np0 + wn * 32 + in_ * 8 + t * 2;
                #pragma unroll
                for (int half = 0; half < 2; half++) {
                    int rr = grow + half * 8;
                    float2 v = make_float2(c[half * 2], c[half * 2 + 1]);
                    float* base = (rr < C_)
                        ? Out0 + (size_t)b * C_ * HW_ + (size_t)rr * HW_
                        : Out1 + (size_t)b * C_ * HW_ + (size_t)(rr - C_) * HW_;
                    if (R && rr < C_) {
                        const float2 r2 = *reinterpret_cast<const float2*>(
                            &R[(size_t)b * C_ * HW_ + (size_t)rr * HW_ + col]);
                        v.x += r2.x; v.y += r2.y;
                    }
                    *reinterpret_cast<float2*>(&base[col]) = v;
                }
            }
        }
        __syncthreads();
    }
}

// ---------------- depthwise 3x3 (q,k,v fused) ----------------------------------
__global__ void __launch_bounds__(256) dw3_kernel(
    const float* __restrict__ inq, const float* __restrict__ ink,
    const float* __restrict__ inv,
    float* __restrict__ outq, float* __restrict__ outk, float* __restrict__ outv,
    const float* __restrict__ wq, const float* __restrict__ wk,
    const float* __restrict__ wv)
{
    int which = blockIdx.z;
    const float* in  = which == 0 ? inq  : which == 1 ? ink  : inv;
    float*       out = which == 0 ? outq : which == 1 ? outk : outv;
    const float* wt  = which == 0 ? wq   : which == 1 ? wk   : wv;

    int bc = blockIdx.x;
    int c  = bc % C_;
    int y0 = blockIdx.y * 8;
    const float* ib = in + (size_t)bc * HW_;

    __shared__ float s[10][132];
    int tid = threadIdx.x;

    for (int e = tid; e < 10 * 128; e += 256) {
        int rr = e >> 7, col = e & 127;
        int y = y0 - 1 + rr;
        s[rr][col + 1] = (y >= 0 && y < H_) ? ib[(size_t)y * W_ + col] : 0.f;
    }
    if (tid < 10) { s[tid][0] = 0.f; s[tid][129] = 0.f; }

    const float* wp = wt + c * 9;
    float w00 = __ldg(wp + 0), w01 = __ldg(wp + 1), w02 = __ldg(wp + 2);
    float w10 = __ldg(wp + 3), w11 = __ldg(wp + 4), w12 = __ldg(wp + 5);
    float w20 = __ldg(wp + 6), w21 = __ldg(wp + 7), w22 = __ldg(wp + 8);
    __syncthreads();

    int r = tid >> 5;
    int cx = (tid & 31) * 4;
    float o0 = 0.f, o1 = 0.f, o2 = 0.f, o3 = 0.f;
    #pragma unroll
    for (int ir = 0; ir < 3; ir++) {
        float wa = ir == 0 ? w00 : ir == 1 ? w10 : w20;
        float wb = ir == 0 ? w01 : ir == 1 ? w11 : w21;
        float wc = ir == 0 ? w02 : ir == 1 ? w12 : w22;
        const float* row = s[r + ir];
        float t0 = row[cx], t1 = row[cx + 1], t2 = row[cx + 2];
        float t3 = row[cx + 3], t4 = row[cx + 4], t5 = row[cx + 5];
        o0 = fmaf(t0, wa, fmaf(t1, wb, fmaf(t2, wc, o0)));
        o1 = fmaf(t1, wa, fmaf(t2, wb, fmaf(t3, wc, o1)));
        o2 = fmaf(t2, wa, fmaf(t3, wb, fmaf(t4, wc, o2)));
        o3 = fmaf(t3, wa, fmaf(t4, wb, fmaf(t5, wc, o3)));
    }
    float4 ov; ov.x = o0; ov.y = o1; ov.z = o2; ov.w = o3;
    *reinterpret_cast<float4*>(&out[(size_t)bc * HW_ + (size_t)(y0 + r) * W_ + cx]) = ov;
}

// ---------------- Gram partial --------------------------------------------------
__global__ void __launch_bounds__(256) gram_partial(
    const float* __restrict__ qd, const float* __restrict__ kd,
    float* __restrict__ part)
{
    int chunk = blockIdx.x;
    int bh    = blockIdx.y;
    int b = bh >> 2, h = bh & 3;
    size_t rowbase = ((size_t)b * C_ + h * DH) * HW_ + (size_t)chunk * 1024;
    const float* qb = qd + rowbase;
    const float* kb = kd + rowbase;

    __shared__ float qs[32][DH + 1];
    __shared__ float ks[32][DH + 1];

    int tid = threadIdx.x;
    int ti = tid & 15, tj = tid >> 4;
    int i0 = ti * 3, j0 = tj * 3;

    float acc[3][3];
    #pragma unroll
    for (int i = 0; i < 3; i++)
        #pragma unroll
        for (int j = 0; j < 3; j++) acc[i][j] = 0.f;
    float nacc = 0.f;

    for (int t = 0; t < 32; t++) {
        __syncthreads();
        #pragma unroll
        for (int r = 0; r < 6; r++) {
            int e = tid + 256 * r;
            int i = e >> 5, nlc = e & 31;
            qs[nlc][i] = qb[(size_t)i * HW_ + t * 32 + nlc];
            ks[nlc][i] = kb[(size_t)i * HW_ + t * 32 + nlc];
        }
        __syncthreads();
        #pragma unroll
        for (int kk = 0; kk < 32; kk++) {
            float a0 = qs[kk][i0], a1 = qs[kk][i0 + 1], a2 = qs[kk][i0 + 2];
            float b0 = ks[kk][j0], b1 = ks[kk][j0 + 1], b2 = ks[kk][j0 + 2];
            acc[0][0] = fmaf(a0, b0, acc[0][0]);
            acc[0][1] = fmaf(a0, b1, acc[0][1]);
            acc[0][2] = fmaf(a0, b2, acc[0][2]);
            acc[1][0] = fmaf(a1, b0, acc[1][0]);
            acc[1][1] = fmaf(a1, b1, acc[1][1]);
            acc[1][2] = fmaf(a1, b2, acc[1][2]);
            acc[2][0] = fmaf(a2, b0, acc[2][0]);
            acc[2][1] = fmaf(a2, b1, acc[2][1]);
            acc[2][2] = fmaf(a2, b2, acc[2][2]);
        }
        if (tid < DH) {
            #pragma unroll
            for (int kk = 0; kk < 32; kk++) {
                float v = qs[kk][tid]; nacc = fmaf(v, v, nacc);
            }
        } else if (tid < 2 * DH) {
            int i = tid - DH;
            #pragma unroll
            for (int kk = 0; kk < 32; kk++) {
                float v = ks[kk][i]; nacc = fmaf(v, v, nacc);
            }
        }
    }

    float* pb = part + ((size_t)bh * 16 + chunk) * 2400;
    #pragma unroll
    for (int i = 0; i < 3; i++)
        #pragma unroll
        for (int j = 0; j < 3; j++)
            pb[(i0 + i) * DH + j0 + j] = acc[i][j];
    if (tid < 2 * DH) pb[2304 + tid] = nacc;
}

// ---------------- reduce partials + norms + softmax -----------------------------
__global__ void __launch_bounds__(256) reduce_softmax(
    const float* __restrict__ part, const float* __restrict__ temp,
    float* __restrict__ attn)
{
    int bh = blockIdx.x;
    int h = bh & 3;
    __shared__ float G[DH * DH];
    __shared__ float nq[DH], nk[DH];
    int tid = threadIdx.x;

    for (int e = tid; e < 2400; e += 256) {
        float s = 0.f;
        #pragma unroll
        for (int c = 0; c < 16; c++)
            s += part[((size_t)bh * 16 + c) * 2400 + e];
        if (e < 2304)      G[e] = s;
        else if (e < 2352) nq[e - 2304] = fmaxf(sqrtf(s), 1e-12f);
        else               nk[e - 2352] = fmaxf(sqrtf(s), 1e-12f);
    }
    __syncthreads();

    if (tid < DH) {
        int i = tid;
        float sc = __ldg(&temp[h]) / nq[i];
        float m = -1e30f;
        #pragma unroll 4
        for (int j = 0; j < DH; j++) {
            float s = G[i * DH + j] * sc / nk[j];
            G[i * DH + j] = s;
            m = fmaxf(m, s);
        }
        float sum = 0.f;
        #pragma unroll 4
        for (int j = 0; j < DH; j++) {
            float e = __expf(G[i * DH + j] - m);
            G[i * DH + j] = e;
            sum += e;
        }
        float rs = 1.f / sum;
        #pragma unroll 4
        for (int j = 0; j < DH; j++)
            attn[(size_t)bh * DH * DH + i * DH + j] = G[i * DH + j] * rs;
    }
}

// ---------------- M_b = W_proj @ blockdiag(attn_b) ------------------------------
__global__ void __launch_bounds__(256) build_M(
    const float* __restrict__ attn, const float* __restrict__ wp,
    float* __restrict__ M)
{
    int b = blockIdx.x;
    __shared__ float sA[HEADS * DH * DH];
    int tid = threadIdx.x;
    for (int e = tid; e < HEADS * DH * DH; e += 256)
        sA[e] = attn[(size_t)b * HEADS * DH * DH + e];
    __syncthreads();

    for (int e = tid; e < C_ * C_; e += 256) {
        int o = e / C_, cp = e % C_;
        int h = cp / DH, d = cp % DH;
        const float* wrow = wp + (size_t)o * C_ + h * DH;
        const float* arow = sA + h * DH * DH + d;
        float s = 0.f;
        #pragma unroll
        for (int i = 0; i < DH; i++)
            s = fmaf(__ldg(&wrow[i]), arow[i * DH], s);
        M[(size_t)b * C_ * C_ + e] = s;
    }
}

// ---------------- launch --------------------------------------------------------
#define GEMM_SMEM 153600

extern "C" void kernel_launch(void* const* d_in, const int* in_sizes, int n_in,
                              void* d_out, int out_size)
{
    const float* xx     = (const float*)d_in[0];
    const float* q_in   = (const float*)d_in[1];
    const float* ln_w   = (const float*)d_in[2];
    const float* ln_b   = (const float*)d_in[3];
    const float* w_q    = (const float*)d_in[4];
    const float* w_k    = (const float*)d_in[5];
    const float* w_v    = (const float*)d_in[6];
    const float* wd_q   = (const float*)d_in[7];
    const float* wd_k   = (const float*)d_in[8];
    const float* wd_v   = (const float*)d_in[9];
    const float* w_proj = (const float*)d_in[10];
    const float* temp   = (const float*)d_in[11];
    float* out = (float*)d_out;

    float* S = nullptr;
    cudaGetSymbolAddress((void**)&S, g_scratch);
    float* qb   = S + OFF_Q;
    float* kb   = S + OFF_K;
    float* vb   = S + OFF_V;
    float* qd   = S + OFF_QD;
    float* kd   = S + OFF_KD;
    float* vd   = S + OFF_VD;
    float* part = S + OFF_PART;
    float* attn = S + OFF_ATTN;
    float* Mb   = S + OFF_M;
    float* muX  = S + OFF_MUX;
    float* rsX  = S + OFF_RSX;
    float* muQ  = S + OFF_MUQ;
    float* rsQ  = S + OFF_RSQ;
    __nv_bfloat16* whi = (__nv_bfloat16*)(S + OFF_WHI);
    __nv_bfloat16* wlo = (__nv_bfloat16*)(S + OFF_WLO);
    const int PLANE = C_ * C_;

    cudaFuncSetAttribute(mma_gemm2,
                         cudaFuncAttributeMaxDynamicSharedMemorySize, GEMM_SMEM);

    // 1. LN stats
    ln_stats<<<dim3(512, 2), 256>>>(xx, muX, rsX, q_in, muQ, rsQ);

    // 2. weight split (slots 0..2; wk/wv contiguous for stacked M=384 GEMM)
    wconv<<<dim3(36, 1), 256>>>(w_q, whi + 0 * PLANE, wlo + 0 * PLANE, 0);
    wconv<<<dim3(36, 1), 256>>>(w_k, whi + 1 * PLANE, wlo + 1 * PLANE, 0);
    wconv<<<dim3(36, 1), 256>>>(w_v, whi + 2 * PLANE, wlo + 2 * PLANE, 0);

    // 3. 1x1 convs with fused LN (q: M=192; k+v stacked: M=384)
    dim3 gg(HW_ / 128, B_);
    mma_gemm2<<<gg, 256, GEMM_SMEM>>>(q_in, whi + 0 * PLANE, wlo + 0 * PLANE,
                                      0, 3, qb, qb, nullptr,
                                      muQ, rsQ, ln_w, ln_b);
    mma_gemm2<<<gg, 256, GEMM_SMEM>>>(xx, whi + 1 * PLANE, wlo + 1 * PLANE,
                                      0, 6, kb, vb, nullptr,
                                      muX, rsX, ln_w, ln_b);

    // 4. depthwise 3x3
    dw3_kernel<<<dim3(B_ * C_, H_ / 8, 3), 256>>>(
        qb, kb, vb, qd, kd, vd, wd_q, wd_k, wd_v);

    // 5. Gram + softmax
    gram_partial<<<dim3(16, 32), 256>>>(qd, kd, part);
    reduce_softmax<<<32, 256>>>(part, temp, attn);

    // 6. fold attn@v with proj (per-batch Mb planes, slots 3..10), final GEMM
    build_M<<<8, 256>>>(attn, w_proj, Mb);
    wconv<<<dim3(36, 8), 256>>>(Mb, whi + 3 * PLANE, wlo + 3 * PLANE,
                                (size_t)C_ * C_);
    mma_gemm2<<<gg, 256, GEMM_SMEM>>>(vd, whi + 3 * PLANE, wlo + 3 * PLANE,
                                      PLANE, 3, out, out, q_in,
                                      nullptr, nullptr, nullptr, nullptr);
}

// round 7
// speedup vs baseline: 2.1904x; 1.0439x over previous
#include <cuda_runtime.h>
#include <cuda_bf16.h>
#include <cstddef>
#include <cstdint>

#define B_    8
#define C_    192
#define H_    128
#define W_    128
#define HW_   16384
#define HEADS 4
#define DH    48

// ---------------- scratch ----------------------------------------------------
#define TEN   ((size_t)B_ * C_ * HW_)
#define OFF_Q    ((size_t)0)
#define OFF_K    (TEN * 1)
#define OFF_V    (TEN * 2)
#define OFF_QD   (TEN * 3)
#define OFF_KD   (TEN * 4)
#define OFF_VD   (TEN * 5)
#define OFF_PART (TEN * 6)
#define PART_SZ  ((size_t)32 * 16 * 2400)
#define OFF_ATTN (OFF_PART + PART_SZ)
#define ATTN_SZ  ((size_t)32 * 48 * 48)
#define OFF_M    (OFF_ATTN + ATTN_SZ)
#define M_SZ     ((size_t)8 * 192 * 192)
// bf16 planes: slots 0=wq, 1=wk, 2=wv, 3..10=Mb[8]; each 36864 bf16 = 18432 fl
#define PLANE_FL 18432
#define OFF_WHI  (OFF_M + M_SZ)
#define OFF_WLO  (OFF_WHI + (size_t)11 * PLANE_FL)
#define TOTAL_SCRATCH (OFF_WLO + (size_t)11 * PLANE_FL)

__device__ __align__(256) float g_scratch[TOTAL_SCRATCH];

// ---------------- W -> row-major bf16 hi/lo planes ----------------------------
__global__ void __launch_bounds__(256) wconv(
    const float* __restrict__ src, __nv_bfloat16* __restrict__ dhi,
    __nv_bfloat16* __restrict__ dlo, size_t srcStride)
{
    int mat = blockIdx.y;
    src += (size_t)mat * srcStride;
    dhi += (size_t)mat * (C_ * C_);
    dlo += (size_t)mat * (C_ * C_);
    for (int idx = blockIdx.x * 256 + threadIdx.x; idx < C_ * C_;
         idx += gridDim.x * 256) {
        float v = src[idx];
        __nv_bfloat16 h = __float2bfloat16(v);
        __nv_bfloat16 l = __float2bfloat16(v - __bfloat162float(h));
        dhi[idx] = h;
        dlo[idx] = l;
    }
}

// ---------------- mma / async helpers -------------------------------------------
__device__ __forceinline__ void mma_bf16(float* c, const uint32_t* a,
                                         const uint32_t* b)
{
    asm volatile(
        "mma.sync.aligned.m16n8k16.row.col.f32.bf16.bf16.f32 "
        "{%0,%1,%2,%3}, {%4,%5,%6,%7}, {%8,%9}, {%0,%1,%2,%3};"
        : "+f"(c[0]), "+f"(c[1]), "+f"(c[2]), "+f"(c[3])
        : "r"(a[0]), "r"(a[1]), "r"(a[2]), "r"(a[3]), "r"(b[0]), "r"(b[1]));
}
__device__ __forceinline__ void ldsm_x4(uint32_t* r, uint32_t addr)
{
    asm volatile("ldmatrix.sync.aligned.m8n8.x4.shared.b16 {%0,%1,%2,%3}, [%4];"
        : "=r"(r[0]), "=r"(r[1]), "=r"(r[2]), "=r"(r[3]) : "r"(addr));
}
__device__ __forceinline__ void cp_async16(uint32_t dst, const void* src)
{
    asm volatile("cp.async.cg.shared.global [%0], [%1], 16;"
        :: "r"(dst), "l"(src) : "memory");
}
#define CP_COMMIT() asm volatile("cp.async.commit_group;" ::: "memory")
#define CP_WAIT(n)  asm volatile("cp.async.wait_group %0;" :: "n"(n) : "memory")

__device__ __forceinline__ uint32_t pack_bf2(__nv_bfloat16 a, __nv_bfloat16 b) {
    union { __nv_bfloat16 h[2]; uint32_t u; } p;
    p.h[0] = a; p.h[1] = b;
    return p.u;
}

// ---------------- tensor-core GEMM v3 -------------------------------------------
// C[m,p] = sum_k W[m,k] * LN(X)[k,p] (+ residual), bf16 hi/lo 3-product split.
// One CTA: 128 pixels x ALL M rows (mTiles x 64). B staged once with FUSED LN
// stats (two-pass over L2-hot data). A double-buffered via cp.async.
// smem words (stride 100/row): Bh @0 (12800), Bl @12800,
//   A buf b @ 25600 + b*12800 (Ah 6400 | Al 6400). Total 51200 w = 204800 B.
__global__ void __launch_bounds__(256) mma_gemm3(
    const float* __restrict__ X,
    const __nv_bfloat16* __restrict__ whi, const __nv_bfloat16* __restrict__ wlo,
    int wStride, int mTiles,
    float* __restrict__ Out0, float* __restrict__ Out1,
    const float* __restrict__ R,
    const float* __restrict__ gw, const float* __restrict__ gb)
{
    extern __shared__ uint32_t sm[];
    uint32_t* Bh = sm;
    uint32_t* Bl = sm + 12800;
    __shared__ float sP[256], ssP[256];

    int tid  = threadIdx.x;
    int w    = tid >> 5, lane = tid & 31;
    int wm   = w >> 2,  wn = w & 3;
    int g    = lane >> 2, t = lane & 3;
    int np0  = blockIdx.x * 128;
    int b    = blockIdx.y;
    const float* Xb = X + (size_t)b * C_ * HW_;
    const __nv_bfloat16* wH = whi + (size_t)b * wStride;
    const __nv_bfloat16* wL = wlo + (size_t)b * wStride;
    const bool doLN = (gw != nullptr);
    uint32_t smBase = (uint32_t)__cvta_generic_to_shared(sm);

    // ---- stage B once: fused LN stats (pass1) + normalize/split (pass2) ----
    {
        int p = tid & 127, kh = tid >> 7;      // 2 threads per pixel
        const float* xc = Xb + np0 + p;
        float mu_ = 0.f, rs_ = 0.f;
        if (doLN) {
            float s = 0.f, ss = 0.f;
            #pragma unroll
            for (int i = 0; i < 48; i++) {
                int k = kh * 96 + i * 2;
                float x0 = xc[(size_t)k * HW_];
                float x1 = xc[(size_t)(k + 1) * HW_];
                s += x0 + x1;
                ss = fmaf(x0, x0, fmaf(x1, x1, ss));
            }
            sP[tid] = s; ssP[tid] = ss;
            __syncthreads();
            float st  = sP[p] + sP[p + 128];
            float sst = ssP[p] + ssP[p + 128];
            mu_ = st * (1.f / C_);
            rs_ = rsqrtf(sst * (1.f / C_) - mu_ * mu_ + 1e-5f);
        }
        #pragma unroll
        for (int i = 0; i < 48; i++) {
            int kp = kh * 48 + i, k = kp * 2;
            float x0 = xc[(size_t)k * HW_];
            float x1 = xc[(size_t)(k + 1) * HW_];
            if (doLN) {
                x0 = (x0 - mu_) * rs_ * __ldg(&gw[k])     + __ldg(&gb[k]);
                x1 = (x1 - mu_) * rs_ * __ldg(&gw[k + 1]) + __ldg(&gb[k + 1]);
            }
            __nv_bfloat16 h0 = __float2bfloat16(x0);
            __nv_bfloat16 h1 = __float2bfloat16(x1);
            __nv_bfloat16 l0 = __float2bfloat16(x0 - __bfloat162float(h0));
            __nv_bfloat16 l1 = __float2bfloat16(x1 - __bfloat162float(h1));
            Bh[p * 100 + kp] = pack_bf2(h0, h1);
            Bl[p * 100 + kp] = pack_bf2(l0, l1);
        }
    }

    // ---- lane-level ldmatrix base addresses for B ----
    uint32_t baseB[2];
    #pragma unroll
    for (int in2 = 0; in2 < 2; in2++) {
        int row = wn * 32 + in2 * 16 + ((lane >> 4) << 3) + (lane & 7);
        baseB[in2] = smBase + (uint32_t)((row * 100 + ((lane >> 3) & 1) * 4) * 4);
    }

    // ---- A prefetch helper (cp.async, 12 x 16B per thread per mtile) ----
    auto copyA = [&](int mt, int buf) {
        #pragma unroll
        for (int i = 0; i < 6; i++) {
            int idx = tid + 256 * i;              // 0..1535
            int row = idx / 24, j = idx % 24;
            size_t go = (size_t)(mt * 64 + row) * C_ + j * 8;
            uint32_t dst = smBase +
                (uint32_t)((25600 + buf * 12800 + row * 100 + j * 4) * 4);
            cp_async16(dst, &wH[go]);
            cp_async16(dst + 25600, &wL[go]);     // Al = Ah + 6400 words
        }
    };

    copyA(0, 0);
    CP_COMMIT();

    for (int mt = 0; mt < mTiles; mt++) {
        int buf = mt & 1;
        if (mt + 1 < mTiles) {
            copyA(mt + 1, buf ^ 1);
            CP_COMMIT();
            CP_WAIT(1);
        } else {
            CP_WAIT(0);
        }
        __syncthreads();

        uint32_t aB = smBase + (uint32_t)((25600 + buf * 12800) * 4);
        uint32_t baseA[2];
        #pragma unroll
        for (int im = 0; im < 2; im++) {
            int row = wm * 32 + im * 16 + (lane & 15);
            baseA[im] = aB + (uint32_t)(row * 400 + (lane >> 4) * 16);
        }

        float acc[8][4];
        #pragma unroll
        for (int i = 0; i < 8; i++)
            #pragma unroll
            for (int j = 0; j < 4; j++) acc[i][j] = 0.f;

        #pragma unroll
        for (int s = 0; s < 12; s++) {
            uint32_t ah[2][4], al[2][4], bh[2][4], bl[2][4];
            #pragma unroll
            for (int im = 0; im < 2; im++) {
                ldsm_x4(ah[im], baseA[im] + s * 32);
                ldsm_x4(al[im], baseA[im] + 25600 + s * 32);
            }
            #pragma unroll
            for (int in2 = 0; in2 < 2; in2++) {
                ldsm_x4(bh[in2], baseB[in2] + s * 32);
                ldsm_x4(bl[in2], baseB[in2] + 51200 + s * 32);
            }
            #pragma unroll
            for (int im = 0; im < 2; im++)
                #pragma unroll
                for (int in_ = 0; in_ < 4; in_++) {
                    const uint32_t* bhf = &bh[in_ >> 1][(in_ & 1) * 2];
                    const uint32_t* blf = &bl[in_ >> 1][(in_ & 1) * 2];
                    float* c = acc[im * 4 + in_];
                    mma_bf16(c, ah[im], bhf);
                    mma_bf16(c, ah[im], blf);
                    mma_bf16(c, al[im], bhf);
                }
        }

        // ---- epilogue ----
        #pragma unroll
        for (int im = 0; im < 2; im++) {
            #pragma unroll
            for (int in_ = 0; in_ < 4; in_++) {
                const float* c = acc[im * 4 + in_];
                int grow = mt * 64 + wm * 32 + im * 16 + g;
                int col  = np0 + wn * 32 + in_ * 8 + t * 2;
                #pragma unroll
                for (int half = 0; half < 2; half++) {
                    int rr = grow + half * 8;
                    float2 v = make_float2(c[half * 2], c[half * 2 + 1]);
                    float* base = (rr < C_)
                        ? Out0 + (size_t)b * C_ * HW_ + (size_t)rr * HW_
                        : Out1 + (size_t)b * C_ * HW_ + (size_t)(rr - C_) * HW_;
                    if (R && rr < C_) {
                        const float2 r2 = *reinterpret_cast<const float2*>(
                            &R[(size_t)b * C_ * HW_ + (size_t)rr * HW_ + col]);
                        v.x += r2.x; v.y += r2.y;
                    }
                    *reinterpret_cast<float2*>(&base[col]) = v;
                }
            }
        }
        __syncthreads();
    }
}

// ---------------- depthwise 3x3 (q,k,v fused) ----------------------------------
__global__ void __launch_bounds__(256) dw3_kernel(
    const float* __restrict__ inq, const float* __restrict__ ink,
    const float* __restrict__ inv,
    float* __restrict__ outq, float* __restrict__ outk, float* __restrict__ outv,
    const float* __restrict__ wq, const float* __restrict__ wk,
    const float* __restrict__ wv)
{
    int which = blockIdx.z;
    const float* in  = which == 0 ? inq  : which == 1 ? ink  : inv;
    float*       out = which == 0 ? outq : which == 1 ? outk : outv;
    const float* wt  = which == 0 ? wq   : which == 1 ? wk   : wv;

    int bc = blockIdx.x;
    int c  = bc % C_;
    int y0 = blockIdx.y * 8;
    const float* ib = in + (size_t)bc * HW_;

    __shared__ float s[10][132];
    int tid = threadIdx.x;

    for (int e = tid; e < 10 * 128; e += 256) {
        int rr = e >> 7, col = e & 127;
        int y = y0 - 1 + rr;
        s[rr][col + 1] = (y >= 0 && y < H_) ? ib[(size_t)y * W_ + col] : 0.f;
    }
    if (tid < 10) { s[tid][0] = 0.f; s[tid][129] = 0.f; }

    const float* wp = wt + c * 9;
    float w00 = __ldg(wp + 0), w01 = __ldg(wp + 1), w02 = __ldg(wp + 2);
    float w10 = __ldg(wp + 3), w11 = __ldg(wp + 4), w12 = __ldg(wp + 5);
    float w20 = __ldg(wp + 6), w21 = __ldg(wp + 7), w22 = __ldg(wp + 8);
    __syncthreads();

    int r = tid >> 5;
    int cx = (tid & 31) * 4;
    float o0 = 0.f, o1 = 0.f, o2 = 0.f, o3 = 0.f;
    #pragma unroll
    for (int ir = 0; ir < 3; ir++) {
        float wa = ir == 0 ? w00 : ir == 1 ? w10 : w20;
        float wb = ir == 0 ? w01 : ir == 1 ? w11 : w21;
        float wc = ir == 0 ? w02 : ir == 1 ? w12 : w22;
        const float* row = s[r + ir];
        float t0 = row[cx], t1 = row[cx + 1], t2 = row[cx + 2];
        float t3 = row[cx + 3], t4 = row[cx + 4], t5 = row[cx + 5];
        o0 = fmaf(t0, wa, fmaf(t1, wb, fmaf(t2, wc, o0)));
        o1 = fmaf(t1, wa, fmaf(t2, wb, fmaf(t3, wc, o1)));
        o2 = fmaf(t2, wa, fmaf(t3, wb, fmaf(t4, wc, o2)));
        o3 = fmaf(t3, wa, fmaf(t4, wb, fmaf(t5, wc, o3)));
    }
    float4 ov; ov.x = o0; ov.y = o1; ov.z = o2; ov.w = o3;
    *reinterpret_cast<float4*>(&out[(size_t)bc * HW_ + (size_t)(y0 + r) * W_ + cx]) = ov;
}

// ---------------- Gram partial --------------------------------------------------
__global__ void __launch_bounds__(256) gram_partial(
    const float* __restrict__ qd, const float* __restrict__ kd,
    float* __restrict__ part)
{
    int chunk = blockIdx.x;
    int bh    = blockIdx.y;
    int b = bh >> 2, h = bh & 3;
    size_t rowbase = ((size_t)b * C_ + h * DH) * HW_ + (size_t)chunk * 1024;
    const float* qb = qd + rowbase;
    const float* kb = kd + rowbase;

    __shared__ float qs[32][DH + 1];
    __shared__ float ks[32][DH + 1];

    int tid = threadIdx.x;
    int ti = tid & 15, tj = tid >> 4;
    int i0 = ti * 3, j0 = tj * 3;

    float acc[3][3];
    #pragma unroll
    for (int i = 0; i < 3; i++)
        #pragma unroll
        for (int j = 0; j < 3; j++) acc[i][j] = 0.f;
    float nacc = 0.f;

    for (int t = 0; t < 32; t++) {
        __syncthreads();
        #pragma unroll
        for (int r = 0; r < 6; r++) {
            int e = tid + 256 * r;
            int i = e >> 5, nlc = e & 31;
            qs[nlc][i] = qb[(size_t)i * HW_ + t * 32 + nlc];
            ks[nlc][i] = kb[(size_t)i * HW_ + t * 32 + nlc];
        }
        __syncthreads();
        #pragma unroll
        for (int kk = 0; kk < 32; kk++) {
            float a0 = qs[kk][i0], a1 = qs[kk][i0 + 1], a2 = qs[kk][i0 + 2];
            float b0 = ks[kk][j0], b1 = ks[kk][j0 + 1], b2 = ks[kk][j0 + 2];
            acc[0][0] = fmaf(a0, b0, acc[0][0]);
            acc[0][1] = fmaf(a0, b1, acc[0][1]);
            acc[0][2] = fmaf(a0, b2, acc[0][2]);
            acc[1][0] = fmaf(a1, b0, acc[1][0]);
            acc[1][1] = fmaf(a1, b1, acc[1][1]);
            acc[1][2] = fmaf(a1, b2, acc[1][2]);
            acc[2][0] = fmaf(a2, b0, acc[2][0]);
            acc[2][1] = fmaf(a2, b1, acc[2][1]);
            acc[2][2] = fmaf(a2, b2, acc[2][2]);
        }
        if (tid < DH) {
            #pragma unroll
            for (int kk = 0; kk < 32; kk++) {
                float v = qs[kk][tid]; nacc = fmaf(v, v, nacc);
            }
        } else if (tid < 2 * DH) {
            int i = tid - DH;
            #pragma unroll
            for (int kk = 0; kk < 32; kk++) {
                float v = ks[kk][i]; nacc = fmaf(v, v, nacc);
            }
        }
    }

    float* pb = part + ((size_t)bh * 16 + chunk) * 2400;
    #pragma unroll
    for (int i = 0; i < 3; i++)
        #pragma unroll
        for (int j = 0; j < 3; j++)
            pb[(i0 + i) * DH + j0 + j] = acc[i][j];
    if (tid < 2 * DH) pb[2304 + tid] = nacc;
}

// ---------------- reduce partials + norms + softmax -----------------------------
__global__ void __launch_bounds__(256) reduce_softmax(
    const float* __restrict__ part, const float* __restrict__ temp,
    float* __restrict__ attn)
{
    int bh = blockIdx.x;
    int h = bh & 3;
    __shared__ float G[DH * DH];
    __shared__ float nq[DH], nk[DH];
    int tid = threadIdx.x;

    for (int e = tid; e < 2400; e += 256) {
        float s = 0.f;
        #pragma unroll
        for (int c = 0; c < 16; c++)
            s += part[((size_t)bh * 16 + c) * 2400 + e];
        if (e < 2304)      G[e] = s;
        else if (e < 2352) nq[e - 2304] = fmaxf(sqrtf(s), 1e-12f);
        else               nk[e - 2352] = fmaxf(sqrtf(s), 1e-12f);
    }
    __syncthreads();

    if (tid < DH) {
        int i = tid;
        float sc = __ldg(&temp[h]) / nq[i];
        float m = -1e30f;
        #pragma unroll 4
        for (int j = 0; j < DH; j++) {
            float s = G[i * DH + j] * sc / nk[j];
            G[i * DH + j] = s;
            m = fmaxf(m, s);
        }
        float sum = 0.f;
        #pragma unroll 4
        for (int j = 0; j < DH; j++) {
            float e = __expf(G[i * DH + j] - m);
            G[i * DH + j] = e;
            sum += e;
        }
        float rs = 1.f / sum;
        #pragma unroll 4
        for (int j = 0; j < DH; j++)
            attn[(size_t)bh * DH * DH + i * DH + j] = G[i * DH + j] * rs;
    }
}

// ---------------- M_b = W_proj @ blockdiag(attn_b) ------------------------------
__global__ void __launch_bounds__(256) build_M(
    const float* __restrict__ attn, const float* __restrict__ wp,
    float* __restrict__ M)
{
    int b = blockIdx.x;
    __shared__ float sA[HEADS * DH * DH];
    int tid = threadIdx.x;
    for (int e = tid; e < HEADS * DH * DH; e += 256)
        sA[e] = attn[(size_t)b * HEADS * DH * DH + e];
    __syncthreads();

    for (int e = tid; e < C_ * C_; e += 256) {
        int o = e / C_, cp = e % C_;
        int h = cp / DH, d = cp % DH;
        const float* wrow = wp + (size_t)o * C_ + h * DH;
        const float* arow = sA + h * DH * DH + d;
        float s = 0.f;
        #pragma unroll
        for (int i = 0; i < DH; i++)
            s = fmaf(__ldg(&wrow[i]), arow[i * DH], s);
        M[(size_t)b * C_ * C_ + e] = s;
    }
}

// ---------------- launch --------------------------------------------------------
#define GEMM_SMEM 204800

extern "C" void kernel_launch(void* const* d_in, const int* in_sizes, int n_in,
                              void* d_out, int out_size)
{
    const float* xx     = (const float*)d_in[0];
    const float* q_in   = (const float*)d_in[1];
    const float* ln_w   = (const float*)d_in[2];
    const float* ln_b   = (const float*)d_in[3];
    const float* w_q    = (const float*)d_in[4];
    const float* w_k    = (const float*)d_in[5];
    const float* w_v    = (const float*)d_in[6];
    const float* wd_q   = (const float*)d_in[7];
    const float* wd_k   = (const float*)d_in[8];
    const float* wd_v   = (const float*)d_in[9];
    const float* w_proj = (const float*)d_in[10];
    const float* temp   = (const float*)d_in[11];
    float* out = (float*)d_out;

    float* S = nullptr;
    cudaGetSymbolAddress((void**)&S, g_scratch);
    float* qb   = S + OFF_Q;
    float* kb   = S + OFF_K;
    float* vb   = S + OFF_V;
    float* qd   = S + OFF_QD;
    float* kd   = S + OFF_KD;
    float* vd   = S + OFF_VD;
    float* part = S + OFF_PART;
    float* attn = S + OFF_ATTN;
    float* Mb   = S + OFF_M;
    __nv_bfloat16* whi = (__nv_bfloat16*)(S + OFF_WHI);
    __nv_bfloat16* wlo = (__nv_bfloat16*)(S + OFF_WLO);
    const int PLANE = C_ * C_;

    cudaFuncSetAttribute(mma_gemm3,
                         cudaFuncAttributeMaxDynamicSharedMemorySize, GEMM_SMEM);

    // 1. weight split (slots 0..2; wk/wv contiguous for stacked M=384 GEMM)
    wconv<<<dim3(36, 1), 256>>>(w_q, whi + 0 * PLANE, wlo + 0 * PLANE, 0);
    wconv<<<dim3(36, 1), 256>>>(w_k, whi + 1 * PLANE, wlo + 1 * PLANE, 0);
    wconv<<<dim3(36, 1), 256>>>(w_v, whi + 2 * PLANE, wlo + 2 * PLANE, 0);

    // 2. 1x1 convs with fused LN stats (q: M=192; k+v stacked: M=384)
    dim3 gg(HW_ / 128, B_);
    mma_gemm3<<<gg, 256, GEMM_SMEM>>>(q_in, whi + 0 * PLANE, wlo + 0 * PLANE,
                                      0, 3, qb, qb, nullptr, ln_w, ln_b);
    mma_gemm3<<<gg, 256, GEMM_SMEM>>>(xx, whi + 1 * PLANE, wlo + 1 * PLANE,
                                      0, 6, kb, vb, nullptr, ln_w, ln_b);

    // 3. depthwise 3x3
    dw3_kernel<<<dim3(B_ * C_, H_ / 8, 3), 256>>>(
        qb, kb, vb, qd, kd, vd, wd_q, wd_k, wd_v);

    // 4. Gram + softmax
    gram_partial<<<dim3(16, 32), 256>>>(qd, kd, part);
    reduce_softmax<<<32, 256>>>(part, temp, attn);

    // 5. fold attn@v with proj (per-batch Mb planes, slots 3..10), final GEMM
    build_M<<<8, 256>>>(attn, w_proj, Mb);
    wconv<<<dim3(36, 8), 256>>>(Mb, whi + 3 * PLANE, wlo + 3 * PLANE,
                                (size_t)C_ * C_);
    mma_gemm3<<<gg, 256, GEMM_SMEM>>>(vd, whi + 3 * PLANE, wlo + 3 * PLANE,
                                      PLANE, 3, out, out, q_in,
                                      nullptr, nullptr);
}

// round 8
// speedup vs baseline: 2.7156x; 1.2397x over previous
#include <cuda_runtime.h>
#include <cuda_bf16.h>
#include <cstddef>
#include <cstdint>

#define B_    8
#define C_    192
#define H_    128
#define W_    128
#define HW_   16384
#define HEADS 4
#define DH    48

// ---------------- scratch ----------------------------------------------------
#define TEN   ((size_t)B_ * C_ * HW_)
#define OFF_Q    ((size_t)0)
#define OFF_K    (TEN * 1)
#define OFF_V    (TEN * 2)
#define OFF_QD   (TEN * 3)
#define OFF_KD   (TEN * 4)
#define OFF_VD   (TEN * 5)
#define OFF_PART (TEN * 6)
#define PART_SZ  ((size_t)32 * 16 * 2400)
#define OFF_ATTN (OFF_PART + PART_SZ)
#define ATTN_SZ  ((size_t)32 * 48 * 48)
#define OFF_M    (OFF_ATTN + ATTN_SZ)
#define M_SZ     ((size_t)8 * 192 * 192)
// bf16 planes: slots 0=wq, 1=wk, 2=wv, 3..10=Mb[8]; each 36864 bf16 = 18432 fl
#define PLANE_FL 18432
#define OFF_WHI  (OFF_M + M_SZ)
#define TOTAL_SCRATCH (OFF_WHI + (size_t)11 * PLANE_FL)

__device__ __align__(256) float g_scratch[TOTAL_SCRATCH];

// ---------------- W -> row-major bf16 plane ------------------------------------
__global__ void __launch_bounds__(256) wconv(
    const float* __restrict__ src, __nv_bfloat16* __restrict__ dhi,
    size_t srcStride)
{
    int mat = blockIdx.y;
    src += (size_t)mat * srcStride;
    dhi += (size_t)mat * (C_ * C_);
    for (int idx = blockIdx.x * 256 + threadIdx.x; idx < C_ * C_;
         idx += gridDim.x * 256) {
        dhi[idx] = __float2bfloat16(src[idx]);
    }
}

// ---------------- mma / async helpers -------------------------------------------
__device__ __forceinline__ void mma_bf16(float* c, const uint32_t* a,
                                         const uint32_t* b)
{
    asm volatile(
        "mma.sync.aligned.m16n8k16.row.col.f32.bf16.bf16.f32 "
        "{%0,%1,%2,%3}, {%4,%5,%6,%7}, {%8,%9}, {%0,%1,%2,%3};"
        : "+f"(c[0]), "+f"(c[1]), "+f"(c[2]), "+f"(c[3])
        : "r"(a[0]), "r"(a[1]), "r"(a[2]), "r"(a[3]), "r"(b[0]), "r"(b[1]));
}
__device__ __forceinline__ void ldsm_x4(uint32_t* r, uint32_t addr)
{
    asm volatile("ldmatrix.sync.aligned.m8n8.x4.shared.b16 {%0,%1,%2,%3}, [%4];"
        : "=r"(r[0]), "=r"(r[1]), "=r"(r[2]), "=r"(r[3]) : "r"(addr));
}
__device__ __forceinline__ void cp_async16(uint32_t dst, const void* src)
{
    asm volatile("cp.async.cg.shared.global [%0], [%1], 16;"
        :: "r"(dst), "l"(src) : "memory");
}
#define CP_COMMIT() asm volatile("cp.async.commit_group;" ::: "memory")
#define CP_WAIT(n)  asm volatile("cp.async.wait_group %0;" :: "n"(n) : "memory")

__device__ __forceinline__ uint32_t pack_bf2(__nv_bfloat16 a, __nv_bfloat16 b) {
    union { __nv_bfloat16 h[2]; uint32_t u; } p;
    p.h[0] = a; p.h[1] = b;
    return p.u;
}

// ---------------- tensor-core GEMM v4 (single bf16 product) ---------------------
// C[m,p] = sum_k W[m,k] * LN(X)[k,p] (+ residual). Residual-dominated output
// dilutes bf16 rounding 20-50x -> single product is well within the 1e-3 gate.
// One CTA: 128 pixels x ALL M rows (mTiles x 64). B staged once with fused LN
// stats. A double-buffered via cp.async.
// smem words (stride 100/row): Bh[128] @0 (12800), A buf b @ 12800 + b*6400.
// Total 25600 words = 102400 B -> 2 CTAs/SM.
__global__ void __launch_bounds__(256) mma_gemm4(
    const float* __restrict__ X,
    const __nv_bfloat16* __restrict__ whi,
    int wStride, int mTiles,
    float* __restrict__ Out0, float* __restrict__ Out1,
    const float* __restrict__ R,
    const float* __restrict__ gw, const float* __restrict__ gb)
{
    extern __shared__ uint32_t sm[];
    uint32_t* Bh = sm;
    __shared__ float sP[256], ssP[256];

    int tid  = threadIdx.x;
    int w    = tid >> 5, lane = tid & 31;
    int wm   = w >> 2,  wn = w & 3;
    int g    = lane >> 2, t = lane & 3;
    int np0  = blockIdx.x * 128;
    int b    = blockIdx.y;
    const float* Xb = X + (size_t)b * C_ * HW_;
    const __nv_bfloat16* wH = whi + (size_t)b * wStride;
    const bool doLN = (gw != nullptr);
    uint32_t smBase = (uint32_t)__cvta_generic_to_shared(sm);

    // ---- stage B once: fused LN stats (pass1) + normalize (pass2) ----
    {
        int p = tid & 127, kh = tid >> 7;      // 2 threads per pixel
        const float* xc = Xb + np0 + p;
        float mu_ = 0.f, rs_ = 0.f;
        if (doLN) {
            float s = 0.f, ss = 0.f;
            #pragma unroll
            for (int i = 0; i < 48; i++) {
                int k = kh * 96 + i * 2;
                float x0 = xc[(size_t)k * HW_];
                float x1 = xc[(size_t)(k + 1) * HW_];
                s += x0 + x1;
                ss = fmaf(x0, x0, fmaf(x1, x1, ss));
            }
            sP[tid] = s; ssP[tid] = ss;
            __syncthreads();
            float st  = sP[p] + sP[p + 128];
            float sst = ssP[p] + ssP[p + 128];
            mu_ = st * (1.f / C_);
            rs_ = rsqrtf(sst * (1.f / C_) - mu_ * mu_ + 1e-5f);
        }
        #pragma unroll
        for (int i = 0; i < 48; i++) {
            int kp = kh * 48 + i, k = kp * 2;
            float x0 = xc[(size_t)k * HW_];
            float x1 = xc[(size_t)(k + 1) * HW_];
            if (doLN) {
                x0 = (x0 - mu_) * rs_ * __ldg(&gw[k])     + __ldg(&gb[k]);
                x1 = (x1 - mu_) * rs_ * __ldg(&gw[k + 1]) + __ldg(&gb[k + 1]);
            }
            Bh[p * 100 + kp] = pack_bf2(__float2bfloat16(x0),
                                        __float2bfloat16(x1));
        }
    }

    // ---- lane-level ldmatrix base addresses for B ----
    uint32_t baseB[2];
    #pragma unroll
    for (int in2 = 0; in2 < 2; in2++) {
        int row = wn * 32 + in2 * 16 + ((lane >> 4) << 3) + (lane & 7);
        baseB[in2] = smBase + (uint32_t)((row * 100 + ((lane >> 3) & 1) * 4) * 4);
    }

    // ---- A prefetch helper (cp.async, 6 x 16B per thread per mtile) ----
    auto copyA = [&](int mt, int buf) {
        #pragma unroll
        for (int i = 0; i < 6; i++) {
            int idx = tid + 256 * i;              // 0..1535
            int row = idx / 24, j = idx % 24;
            size_t go = (size_t)(mt * 64 + row) * C_ + j * 8;
            uint32_t dst = smBase +
                (uint32_t)((12800 + buf * 6400 + row * 100 + j * 4) * 4);
            cp_async16(dst, &wH[go]);
        }
    };

    copyA(0, 0);
    CP_COMMIT();

    for (int mt = 0; mt < mTiles; mt++) {
        int buf = mt & 1;
        if (mt + 1 < mTiles) {
            copyA(mt + 1, buf ^ 1);
            CP_COMMIT();
            CP_WAIT(1);
        } else {
            CP_WAIT(0);
        }
        __syncthreads();

        uint32_t aB = smBase + (uint32_t)((12800 + buf * 6400) * 4);
        uint32_t baseA[2];
        #pragma unroll
        for (int im = 0; im < 2; im++) {
            int row = wm * 32 + im * 16 + (lane & 15);
            baseA[im] = aB + (uint32_t)(row * 400 + (lane >> 4) * 16);
        }

        float acc[8][4];
        #pragma unroll
        for (int i = 0; i < 8; i++)
            #pragma unroll
            for (int j = 0; j < 4; j++) acc[i][j] = 0.f;

        #pragma unroll
        for (int s = 0; s < 12; s++) {
            uint32_t ah[2][4], bh[2][4];
            #pragma unroll
            for (int im = 0; im < 2; im++)
                ldsm_x4(ah[im], baseA[im] + s * 32);
            #pragma unroll
            for (int in2 = 0; in2 < 2; in2++)
                ldsm_x4(bh[in2], baseB[in2] + s * 32);
            #pragma unroll
            for (int im = 0; im < 2; im++)
                #pragma unroll
                for (int in_ = 0; in_ < 4; in_++)
                    mma_bf16(acc[im * 4 + in_], ah[im],
                             &bh[in_ >> 1][(in_ & 1) * 2]);
        }

        // ---- epilogue ----
        #pragma unroll
        for (int im = 0; im < 2; im++) {
            #pragma unroll
            for (int in_ = 0; in_ < 4; in_++) {
                const float* c = acc[im * 4 + in_];
                int grow = mt * 64 + wm * 32 + im * 16 + g;
                int col  = np0 + wn * 32 + in_ * 8 + t * 2;
                #pragma unroll
                for (int half = 0; half < 2; half++) {
                    int rr = grow + half * 8;
                    float2 v = make_float2(c[half * 2], c[half * 2 + 1]);
                    float* base = (rr < C_)
                        ? Out0 + (size_t)b * C_ * HW_ + (size_t)rr * HW_
                        : Out1 + (size_t)b * C_ * HW_ + (size_t)(rr - C_) * HW_;
                    if (R && rr < C_) {
                        const float2 r2 = *reinterpret_cast<const float2*>(
                            &R[(size_t)b * C_ * HW_ + (size_t)rr * HW_ + col]);
                        v.x += r2.x; v.y += r2.y;
                    }
                    *reinterpret_cast<float2*>(&base[col]) = v;
                }
            }
        }
        __syncthreads();
    }
}

// ---------------- depthwise 3x3 (q,k,v fused) ----------------------------------
__global__ void __launch_bounds__(256) dw3_kernel(
    const float* __restrict__ inq, const float* __restrict__ ink,
    const float* __restrict__ inv,
    float* __restrict__ outq, float* __restrict__ outk, float* __restrict__ outv,
    const float* __restrict__ wq, const float* __restrict__ wk,
    const float* __restrict__ wv)
{
    int which = blockIdx.z;
    const float* in  = which == 0 ? inq  : which == 1 ? ink  : inv;
    float*       out = which == 0 ? outq : which == 1 ? outk : outv;
    const float* wt  = which == 0 ? wq   : which == 1 ? wk   : wv;

    int bc = blockIdx.x;
    int c  = bc % C_;
    int y0 = blockIdx.y * 8;
    const float* ib = in + (size_t)bc * HW_;

    __shared__ float s[10][132];
    int tid = threadIdx.x;

    for (int e = tid; e < 10 * 128; e += 256) {
        int rr = e >> 7, col = e & 127;
        int y = y0 - 1 + rr;
        s[rr][col + 1] = (y >= 0 && y < H_) ? ib[(size_t)y * W_ + col] : 0.f;
    }
    if (tid < 10) { s[tid][0] = 0.f; s[tid][129] = 0.f; }

    const float* wp = wt + c * 9;
    float w00 = __ldg(wp + 0), w01 = __ldg(wp + 1), w02 = __ldg(wp + 2);
    float w10 = __ldg(wp + 3), w11 = __ldg(wp + 4), w12 = __ldg(wp + 5);
    float w20 = __ldg(wp + 6), w21 = __ldg(wp + 7), w22 = __ldg(wp + 8);
    __syncthreads();

    int r = tid >> 5;
    int cx = (tid & 31) * 4;
    float o0 = 0.f, o1 = 0.f, o2 = 0.f, o3 = 0.f;
    #pragma unroll
    for (int ir = 0; ir < 3; ir++) {
        float wa = ir == 0 ? w00 : ir == 1 ? w10 : w20;
        float wb = ir == 0 ? w01 : ir == 1 ? w11 : w21;
        float wc = ir == 0 ? w02 : ir == 1 ? w12 : w22;
        const float* row = s[r + ir];
        float t0 = row[cx], t1 = row[cx + 1], t2 = row[cx + 2];
        float t3 = row[cx + 3], t4 = row[cx + 4], t5 = row[cx + 5];
        o0 = fmaf(t0, wa, fmaf(t1, wb, fmaf(t2, wc, o0)));
        o1 = fmaf(t1, wa, fmaf(t2, wb, fmaf(t3, wc, o1)));
        o2 = fmaf(t2, wa, fmaf(t3, wb, fmaf(t4, wc, o2)));
        o3 = fmaf(t3, wa, fmaf(t4, wb, fmaf(t5, wc, o3)));
    }
    float4 ov; ov.x = o0; ov.y = o1; ov.z = o2; ov.w = o3;
    *reinterpret_cast<float4*>(&out[(size_t)bc * HW_ + (size_t)(y0 + r) * W_ + cx]) = ov;
}

// ---------------- Gram partial --------------------------------------------------
__global__ void __launch_bounds__(256) gram_partial(
    const float* __restrict__ qd, const float* __restrict__ kd,
    float* __restrict__ part)
{
    int chunk = blockIdx.x;
    int bh    = blockIdx.y;
    int b = bh >> 2, h = bh & 3;
    size_t rowbase = ((size_t)b * C_ + h * DH) * HW_ + (size_t)chunk * 1024;
    const float* qb = qd + rowbase;
    const float* kb = kd + rowbase;

    __shared__ float qs[32][DH + 1];
    __shared__ float ks[32][DH + 1];

    int tid = threadIdx.x;
    int ti = tid & 15, tj = tid >> 4;
    int i0 = ti * 3, j0 = tj * 3;

    float acc[3][3];
    #pragma unroll
    for (int i = 0; i < 3; i++)
        #pragma unroll
        for (int j = 0; j < 3; j++) acc[i][j] = 0.f;
    float nacc = 0.f;

    for (int t = 0; t < 32; t++) {
        __syncthreads();
        #pragma unroll
        for (int r = 0; r < 6; r++) {
            int e = tid + 256 * r;
            int i = e >> 5, nlc = e & 31;
            qs[nlc][i] = qb[(size_t)i * HW_ + t * 32 + nlc];
            ks[nlc][i] = kb[(size_t)i * HW_ + t * 32 + nlc];
        }
        __syncthreads();
        #pragma unroll
        for (int kk = 0; kk < 32; kk++) {
            float a0 = qs[kk][i0], a1 = qs[kk][i0 + 1], a2 = qs[kk][i0 + 2];
            float b0 = ks[kk][j0], b1 = ks[kk][j0 + 1], b2 = ks[kk][j0 + 2];
            acc[0][0] = fmaf(a0, b0, acc[0][0]);
            acc[0][1] = fmaf(a0, b1, acc[0][1]);
            acc[0][2] = fmaf(a0, b2, acc[0][2]);
            acc[1][0] = fmaf(a1, b0, acc[1][0]);
            acc[1][1] = fmaf(a1, b1, acc[1][1]);
            acc[1][2] = fmaf(a1, b2, acc[1][2]);
            acc[2][0] = fmaf(a2, b0, acc[2][0]);
            acc[2][1] = fmaf(a2, b1, acc[2][1]);
            acc[2][2] = fmaf(a2, b2, acc[2][2]);
        }
        if (tid < DH) {
            #pragma unroll
            for (int kk = 0; kk < 32; kk++) {
                float v = qs[kk][tid]; nacc = fmaf(v, v, nacc);
            }
        } else if (tid < 2 * DH) {
            int i = tid - DH;
            #pragma unroll
            for (int kk = 0; kk < 32; kk++) {
                float v = ks[kk][i]; nacc = fmaf(v, v, nacc);
            }
        }
    }

    float* pb = part + ((size_t)bh * 16 + chunk) * 2400;
    #pragma unroll
    for (int i = 0; i < 3; i++)
        #pragma unroll
        for (int j = 0; j < 3; j++)
            pb[(i0 + i) * DH + j0 + j] = acc[i][j];
    if (tid < 2 * DH) pb[2304 + tid] = nacc;
}

// ---------------- reduce partials + norms + softmax -----------------------------
__global__ void __launch_bounds__(256) reduce_softmax(
    const float* __restrict__ part, const float* __restrict__ temp,
    float* __restrict__ attn)
{
    int bh = blockIdx.x;
    int h = bh & 3;
    __shared__ float G[DH * DH];
    __shared__ float nq[DH], nk[DH];
    int tid = threadIdx.x;

    for (int e = tid; e < 2400; e += 256) {
        float s = 0.f;
        #pragma unroll
        for (int c = 0; c < 16; c++)
            s += part[((size_t)bh * 16 + c) * 2400 + e];
        if (e < 2304)      G[e] = s;
        else if (e < 2352) nq[e - 2304] = fmaxf(sqrtf(s), 1e-12f);
        else               nk[e - 2352] = fmaxf(sqrtf(s), 1e-12f);
    }
    __syncthreads();

    if (tid < DH) {
        int i = tid;
        float sc = __ldg(&temp[h]) / nq[i];
        float m = -1e30f;
        #pragma unroll 4
        for (int j = 0; j < DH; j++) {
            float s = G[i * DH + j] * sc / nk[j];
            G[i * DH + j] = s;
            m = fmaxf(m, s);
        }
        float sum = 0.f;
        #pragma unroll 4
        for (int j = 0; j < DH; j++) {
            float e = __expf(G[i * DH + j] - m);
            G[i * DH + j] = e;
            sum += e;
        }
        float rs = 1.f / sum;
        #pragma unroll 4
        for (int j = 0; j < DH; j++)
            attn[(size_t)bh * DH * DH + i * DH + j] = G[i * DH + j] * rs;
    }
}

// ---------------- M_b = W_proj @ blockdiag(attn_b) ------------------------------
__global__ void __launch_bounds__(256) build_M(
    const float* __restrict__ attn, const float* __restrict__ wp,
    float* __restrict__ M)
{
    int b = blockIdx.x;
    __shared__ float sA[HEADS * DH * DH];
    int tid = threadIdx.x;
    for (int e = tid; e < HEADS * DH * DH; e += 256)
        sA[e] = attn[(size_t)b * HEADS * DH * DH + e];
    __syncthreads();

    for (int e = tid; e < C_ * C_; e += 256) {
        int o = e / C_, cp = e % C_;
        int h = cp / DH, d = cp % DH;
        const float* wrow = wp + (size_t)o * C_ + h * DH;
        const float* arow = sA + h * DH * DH + d;
        float s = 0.f;
        #pragma unroll
        for (int i = 0; i < DH; i++)
            s = fmaf(__ldg(&wrow[i]), arow[i * DH], s);
        M[(size_t)b * C_ * C_ + e] = s;
    }
}

// ---------------- launch --------------------------------------------------------
#define GEMM_SMEM 102400

extern "C" void kernel_launch(void* const* d_in, const int* in_sizes, int n_in,
                              void* d_out, int out_size)
{
    const float* xx     = (const float*)d_in[0];
    const float* q_in   = (const float*)d_in[1];
    const float* ln_w   = (const float*)d_in[2];
    const float* ln_b   = (const float*)d_in[3];
    const float* w_q    = (const float*)d_in[4];
    const float* w_k    = (const float*)d_in[5];
    const float* w_v    = (const float*)d_in[6];
    const float* wd_q   = (const float*)d_in[7];
    const float* wd_k   = (const float*)d_in[8];
    const float* wd_v   = (const float*)d_in[9];
    const float* w_proj = (const float*)d_in[10];
    const float* temp   = (const float*)d_in[11];
    float* out = (float*)d_out;

    float* S = nullptr;
    cudaGetSymbolAddress((void**)&S, g_scratch);
    float* qb   = S + OFF_Q;
    float* kb   = S + OFF_K;
    float* vb   = S + OFF_V;
    float* qd   = S + OFF_QD;
    float* kd   = S + OFF_KD;
    float* vd   = S + OFF_VD;
    float* part = S + OFF_PART;
    float* attn = S + OFF_ATTN;
    float* Mb   = S + OFF_M;
    __nv_bfloat16* whi = (__nv_bfloat16*)(S + OFF_WHI);
    const int PLANE = C_ * C_;

    cudaFuncSetAttribute(mma_gemm4,
                         cudaFuncAttributeMaxDynamicSharedMemorySize, GEMM_SMEM);

    // 1. weight -> bf16 (slots 0..2; wk/wv contiguous for stacked M=384 GEMM)
    wconv<<<dim3(36, 1), 256>>>(w_q, whi + 0 * PLANE, 0);
    wconv<<<dim3(36, 1), 256>>>(w_k, whi + 1 * PLANE, 0);
    wconv<<<dim3(36, 1), 256>>>(w_v, whi + 2 * PLANE, 0);

    // 2. 1x1 convs with fused LN stats (q: M=192; k+v stacked: M=384)
    dim3 gg(HW_ / 128, B_);
    mma_gemm4<<<gg, 256, GEMM_SMEM>>>(q_in, whi + 0 * PLANE,
                                      0, 3, qb, qb, nullptr, ln_w, ln_b);
    mma_gemm4<<<gg, 256, GEMM_SMEM>>>(xx, whi + 1 * PLANE,
                                      0, 6, kb, vb, nullptr, ln_w, ln_b);

    // 3. depthwise 3x3
    dw3_kernel<<<dim3(B_ * C_, H_ / 8, 3), 256>>>(
        qb, kb, vb, qd, kd, vd, wd_q, wd_k, wd_v);

    // 4. Gram + softmax
    gram_partial<<<dim3(16, 32), 256>>>(qd, kd, part);
    reduce_softmax<<<32, 256>>>(part, temp, attn);

    // 5. fold attn@v with proj (per-batch Mb planes, slots 3..10), final GEMM
    build_M<<<8, 256>>>(attn, w_proj, Mb);
    wconv<<<dim3(36, 8), 256>>>(Mb, whi + 3 * PLANE, (size_t)C_ * C_);
    mma_gemm4<<<gg, 256, GEMM_SMEM>>>(vd, whi + 3 * PLANE,
                                      PLANE, 3, out, out, q_in,
                                      nullptr, nullptr);
}

// round 9
// speedup vs baseline: 3.2637x; 1.2018x over previous
#include <cuda_runtime.h>
#include <cuda_bf16.h>
#include <cstddef>
#include <cstdint>

#define B_    8
#define C_    192
#define H_    128
#define W_    128
#define HW_   16384
#define HEADS 4
#define DH    48

// ---------------- scratch ----------------------------------------------------
#define TEN   ((size_t)B_ * C_ * HW_)
#define OFF_Q    ((size_t)0)
#define OFF_K    (TEN * 1)
#define OFF_V    (TEN * 2)
#define OFF_QD   (TEN * 3)
#define OFF_KD   (TEN * 4)
#define OFF_VD   (TEN * 5)
#define OFF_PART (TEN * 6)
#define PART_SZ  ((size_t)32 * 16 * 2400)
#define OFF_ATTN (OFF_PART + PART_SZ)
#define ATTN_SZ  ((size_t)32 * 48 * 48)
// bf16 planes: slots 0=wq, 1=wk, 2=wv, 3..10=Mb[8]; each 36864 bf16 = 18432 fl
#define PLANE_FL 18432
#define OFF_WHI  (OFF_ATTN + ATTN_SZ)
#define TOTAL_SCRATCH (OFF_WHI + (size_t)11 * PLANE_FL)

__device__ __align__(256) float g_scratch[TOTAL_SCRATCH];

// ---------------- 3 weights -> bf16 planes (one launch) -------------------------
__global__ void __launch_bounds__(256) wconv3(
    const float* __restrict__ w_q, const float* __restrict__ w_k,
    const float* __restrict__ w_v, __nv_bfloat16* __restrict__ dst)
{
    int mat = blockIdx.y;
    const float* src = mat == 0 ? w_q : mat == 1 ? w_k : w_v;
    dst += (size_t)mat * (C_ * C_);
    for (int idx = blockIdx.x * 256 + threadIdx.x; idx < C_ * C_;
         idx += gridDim.x * 256)
        dst[idx] = __float2bfloat16(src[idx]);
}

// ---------------- mma / async helpers -------------------------------------------
__device__ __forceinline__ void mma_bf16(float* c, const uint32_t* a,
                                         const uint32_t* b)
{
    asm volatile(
        "mma.sync.aligned.m16n8k16.row.col.f32.bf16.bf16.f32 "
        "{%0,%1,%2,%3}, {%4,%5,%6,%7}, {%8,%9}, {%0,%1,%2,%3};"
        : "+f"(c[0]), "+f"(c[1]), "+f"(c[2]), "+f"(c[3])
        : "r"(a[0]), "r"(a[1]), "r"(a[2]), "r"(a[3]), "r"(b[0]), "r"(b[1]));
}
__device__ __forceinline__ void ldsm_x4(uint32_t* r, uint32_t addr)
{
    asm volatile("ldmatrix.sync.aligned.m8n8.x4.shared.b16 {%0,%1,%2,%3}, [%4];"
        : "=r"(r[0]), "=r"(r[1]), "=r"(r[2]), "=r"(r[3]) : "r"(addr));
}
__device__ __forceinline__ void cp_async16(uint32_t dst, const void* src)
{
    asm volatile("cp.async.cg.shared.global [%0], [%1], 16;"
        :: "r"(dst), "l"(src) : "memory");
}
#define CP_COMMIT() asm volatile("cp.async.commit_group;" ::: "memory")
#define CP_WAIT(n)  asm volatile("cp.async.wait_group %0;" :: "n"(n) : "memory")

__device__ __forceinline__ uint32_t pack_bf2(float a, float b) {
    union { __nv_bfloat16 h[2]; uint32_t u; } p;
    p.h[0] = __float2bfloat16(a); p.h[1] = __float2bfloat16(b);
    return p.u;
}

// ---------------- tensor-core GEMM v5 (single global pass) ----------------------
// C[m,p] = sum_k W[m,k] * LN(X)[k,p] (+ residual), single bf16 product.
// B staged ONCE from global as raw bf16 (stats accumulated in fp32 on the fly),
// then normalized in-place in smem. A double-buffered via cp.async.
// smem words (stride 100/row): Bh[128] @0 (12800), A buf b @ 12800 + b*6400.
// Total 25600 words = 102400 B -> 2 CTAs/SM.
__global__ void __launch_bounds__(256) mma_gemm5(
    const float* __restrict__ X,
    const __nv_bfloat16* __restrict__ whi,
    int wStride, int mTiles,
    float* __restrict__ Out0, float* __restrict__ Out1,
    const float* __restrict__ R,
    const float* __restrict__ gw, const float* __restrict__ gb)
{
    extern __shared__ uint32_t sm[];
    uint32_t* Bh = sm;
    __shared__ float sP[256], ssP[256];

    int tid  = threadIdx.x;
    int w    = tid >> 5, lane = tid & 31;
    int wm   = w >> 2,  wn = w & 3;
    int g    = lane >> 2, t = lane & 3;
    int np0  = blockIdx.x * 128;
    int b    = blockIdx.y;
    const float* Xb = X + (size_t)b * C_ * HW_;
    const __nv_bfloat16* wH = whi + (size_t)b * wStride;
    const bool doLN = (gw != nullptr);
    uint32_t smBase = (uint32_t)__cvta_generic_to_shared(sm);

    // ---- stage B: one global pass; LN applied in smem afterwards ----
    {
        int p = tid & 127, kh = tid >> 7;      // 2 threads per pixel
        const float* xc = Xb + np0 + p;
        if (doLN) {
            float s = 0.f, ss = 0.f;
            #pragma unroll
            for (int i = 0; i < 48; i++) {
                int k = kh * 96 + i * 2;
                float x0 = xc[(size_t)k * HW_];
                float x1 = xc[(size_t)(k + 1) * HW_];
                s += x0 + x1;
                ss = fmaf(x0, x0, fmaf(x1, x1, ss));
                Bh[p * 100 + kh * 48 + i] = pack_bf2(x0, x1);
            }
            sP[tid] = s; ssP[tid] = ss;
            __syncthreads();
            float st  = sP[p] + sP[p + 128];
            float sst = ssP[p] + ssP[p + 128];
            float mu_ = st * (1.f / C_);
            float rs_ = rsqrtf(sst * (1.f / C_) - mu_ * mu_ + 1e-5f);
            #pragma unroll
            for (int i = 0; i < 48; i++) {
                int kp = kh * 48 + i, k = kp * 2;
                uint32_t u = Bh[p * 100 + kp];
                __nv_bfloat162 hv = *reinterpret_cast<__nv_bfloat162*>(&u);
                float x0 = __bfloat162float(hv.x);
                float x1 = __bfloat162float(hv.y);
                x0 = (x0 - mu_) * rs_ * __ldg(&gw[k])     + __ldg(&gb[k]);
                x1 = (x1 - mu_) * rs_ * __ldg(&gw[k + 1]) + __ldg(&gb[k + 1]);
                Bh[p * 100 + kp] = pack_bf2(x0, x1);
            }
        } else {
            #pragma unroll
            for (int i = 0; i < 48; i++) {
                int kp = kh * 48 + i, k = kp * 2;
                Bh[p * 100 + kp] = pack_bf2(xc[(size_t)k * HW_],
                                            xc[(size_t)(k + 1) * HW_]);
            }
        }
    }

    // ---- lane-level ldmatrix base addresses for B ----
    uint32_t baseB[2];
    #pragma unroll
    for (int in2 = 0; in2 < 2; in2++) {
        int row = wn * 32 + in2 * 16 + ((lane >> 4) << 3) + (lane & 7);
        baseB[in2] = smBase + (uint32_t)((row * 100 + ((lane >> 3) & 1) * 4) * 4);
    }

    // ---- A prefetch helper (cp.async, 6 x 16B per thread per mtile) ----
    auto copyA = [&](int mt, int buf) {
        #pragma unroll
        for (int i = 0; i < 6; i++) {
            int idx = tid + 256 * i;              // 0..1535
            int row = idx / 24, j = idx % 24;
            size_t go = (size_t)(mt * 64 + row) * C_ + j * 8;
            uint32_t dst = smBase +
                (uint32_t)((12800 + buf * 6400 + row * 100 + j * 4) * 4);
            cp_async16(dst, &wH[go]);
        }
    };

    copyA(0, 0);
    CP_COMMIT();

    for (int mt = 0; mt < mTiles; mt++) {
        int buf = mt & 1;
        if (mt + 1 < mTiles) {
            copyA(mt + 1, buf ^ 1);
            CP_COMMIT();
            CP_WAIT(1);
        } else {
            CP_WAIT(0);
        }
        __syncthreads();

        uint32_t aB = smBase + (uint32_t)((12800 + buf * 6400) * 4);
        uint32_t baseA[2];
        #pragma unroll
        for (int im = 0; im < 2; im++) {
            int row = wm * 32 + im * 16 + (lane & 15);
            baseA[im] = aB + (uint32_t)(row * 400 + (lane >> 4) * 16);
        }

        float acc[8][4];
        #pragma unroll
        for (int i = 0; i < 8; i++)
            #pragma unroll
            for (int j = 0; j < 4; j++) acc[i][j] = 0.f;

        #pragma unroll
        for (int s = 0; s < 12; s++) {
            uint32_t ah[2][4], bh[2][4];
            #pragma unroll
            for (int im = 0; im < 2; im++)
                ldsm_x4(ah[im], baseA[im] + s * 32);
            #pragma unroll
            for (int in2 = 0; in2 < 2; in2++)
                ldsm_x4(bh[in2], baseB[in2] + s * 32);
            #pragma unroll
            for (int im = 0; im < 2; im++)
                #pragma unroll
                for (int in_ = 0; in_ < 4; in_++)
                    mma_bf16(acc[im * 4 + in_], ah[im],
                             &bh[in_ >> 1][(in_ & 1) * 2]);
        }

        // ---- epilogue ----
        #pragma unroll
        for (int im = 0; im < 2; im++) {
            #pragma unroll
            for (int in_ = 0; in_ < 4; in_++) {
                const float* c = acc[im * 4 + in_];
                int grow = mt * 64 + wm * 32 + im * 16 + g;
                int col  = np0 + wn * 32 + in_ * 8 + t * 2;
                #pragma unroll
                for (int half = 0; half < 2; half++) {
                    int rr = grow + half * 8;
                    float2 v = make_float2(c[half * 2], c[half * 2 + 1]);
                    float* base = (rr < C_)
                        ? Out0 + (size_t)b * C_ * HW_ + (size_t)rr * HW_
                        : Out1 + (size_t)b * C_ * HW_ + (size_t)(rr - C_) * HW_;
                    if (R && rr < C_) {
                        const float2 r2 = *reinterpret_cast<const float2*>(
                            &R[(size_t)b * C_ * HW_ + (size_t)rr * HW_ + col]);
                        v.x += r2.x; v.y += r2.y;
                    }
                    *reinterpret_cast<float2*>(&base[col]) = v;
                }
            }
        }
        __syncthreads();
    }
}

// ---------------- depthwise 3x3 v2: warp-strip, shuffle halos, no smem ----------
__device__ __forceinline__ void dw_load_row(
    const float* __restrict__ ib, int y, int lane,
    float& l, float4& f, float& r)
{
    if ((unsigned)y < (unsigned)H_) {
        f = *reinterpret_cast<const float4*>(ib + (size_t)y * W_ + lane * 4);
    } else {
        f = make_float4(0.f, 0.f, 0.f, 0.f);
    }
    float lw = __shfl_up_sync(0xffffffffu, f.w, 1);
    float rx = __shfl_down_sync(0xffffffffu, f.x, 1);
    l = (lane == 0)  ? 0.f : lw;
    r = (lane == 31) ? 0.f : rx;
}

__global__ void __launch_bounds__(256) dw3v2(
    const float* __restrict__ inq, const float* __restrict__ ink,
    const float* __restrict__ inv,
    float* __restrict__ outq, float* __restrict__ outk, float* __restrict__ outv,
    const float* __restrict__ wq, const float* __restrict__ wk,
    const float* __restrict__ wv)
{
    int which = blockIdx.y;
    const float* in  = which == 0 ? inq  : which == 1 ? ink  : inv;
    float*       out = which == 0 ? outq : which == 1 ? outk : outv;
    const float* wt  = which == 0 ? wq   : which == 1 ? wk   : wv;

    int bc = blockIdx.x;
    int c  = bc % C_;
    const float* wp = wt + c * 9;
    float w00 = __ldg(wp + 0), w01 = __ldg(wp + 1), w02 = __ldg(wp + 2);
    float w10 = __ldg(wp + 3), w11 = __ldg(wp + 4), w12 = __ldg(wp + 5);
    float w20 = __ldg(wp + 6), w21 = __ldg(wp + 7), w22 = __ldg(wp + 8);

    int warp = threadIdx.x >> 5, lane = threadIdx.x & 31;
    int y0 = warp * 16;
    const float* ib = in + (size_t)bc * HW_;
    float* ob = out + (size_t)bc * HW_;

    float pl, pr, cl, cr, nl, nr;
    float4 pf, cf, nf;
    dw_load_row(ib, y0 - 1, lane, pl, pf, pr);
    dw_load_row(ib, y0,     lane, cl, cf, cr);

    #pragma unroll
    for (int r = 0; r < 16; r++) {
        int y = y0 + r;
        dw_load_row(ib, y + 1, lane, nl, nf, nr);
        float4 o;
        o.x = fmaf(pl,   w00, fmaf(pf.x, w01, fmaf(pf.y, w02,
              fmaf(cl,   w10, fmaf(cf.x, w11, fmaf(cf.y, w12,
              fmaf(nl,   w20, fmaf(nf.x, w21, nf.y * w22))))))));
        o.y = fmaf(pf.x, w00, fmaf(pf.y, w01, fmaf(pf.z, w02,
              fmaf(cf.x, w10, fmaf(cf.y, w11, fmaf(cf.z, w12,
              fmaf(nf.x, w20, fmaf(nf.y, w21, nf.z * w22))))))));
        o.z = fmaf(pf.y, w00, fmaf(pf.z, w01, fmaf(pf.w, w02,
              fmaf(cf.y, w10, fmaf(cf.z, w11, fmaf(cf.w, w12,
              fmaf(nf.y, w20, fmaf(nf.z, w21, nf.w * w22))))))));
        o.w = fmaf(pf.z, w00, fmaf(pf.w, w01, fmaf(pr,   w02,
              fmaf(cf.z, w10, fmaf(cf.w, w11, fmaf(cr,   w12,
              fmaf(nf.z, w20, fmaf(nf.w, w21, nr * w22))))))));
        *reinterpret_cast<float4*>(ob + (size_t)y * W_ + lane * 4) = o;
        pl = cl; pr = cr; pf = cf;
        cl = nl; cr = nr; cf = nf;
    }
}

// ---------------- Gram partial --------------------------------------------------
__global__ void __launch_bounds__(256) gram_partial(
    const float* __restrict__ qd, const float* __restrict__ kd,
    float* __restrict__ part)
{
    int chunk = blockIdx.x;
    int bh    = blockIdx.y;
    int b = bh >> 2, h = bh & 3;
    size_t rowbase = ((size_t)b * C_ + h * DH) * HW_ + (size_t)chunk * 1024;
    const float* qb = qd + rowbase;
    const float* kb = kd + rowbase;

    __shared__ float qs[32][DH + 1];
    __shared__ float ks[32][DH + 1];

    int tid = threadIdx.x;
    int ti = tid & 15, tj = tid >> 4;
    int i0 = ti * 3, j0 = tj * 3;

    float acc[3][3];
    #pragma unroll
    for (int i = 0; i < 3; i++)
        #pragma unroll
        for (int j = 0; j < 3; j++) acc[i][j] = 0.f;
    float nacc = 0.f;

    for (int t = 0; t < 32; t++) {
        __syncthreads();
        #pragma unroll
        for (int r = 0; r < 6; r++) {
            int e = tid + 256 * r;
            int i = e >> 5, nlc = e & 31;
            qs[nlc][i] = qb[(size_t)i * HW_ + t * 32 + nlc];
            ks[nlc][i] = kb[(size_t)i * HW_ + t * 32 + nlc];
        }
        __syncthreads();
        #pragma unroll
        for (int kk = 0; kk < 32; kk++) {
            float a0 = qs[kk][i0], a1 = qs[kk][i0 + 1], a2 = qs[kk][i0 + 2];
            float b0 = ks[kk][j0], b1 = ks[kk][j0 + 1], b2 = ks[kk][j0 + 2];
            acc[0][0] = fmaf(a0, b0, acc[0][0]);
            acc[0][1] = fmaf(a0, b1, acc[0][1]);
            acc[0][2] = fmaf(a0, b2, acc[0][2]);
            acc[1][0] = fmaf(a1, b0, acc[1][0]);
            acc[1][1] = fmaf(a1, b1, acc[1][1]);
            acc[1][2] = fmaf(a1, b2, acc[1][2]);
            acc[2][0] = fmaf(a2, b0, acc[2][0]);
            acc[2][1] = fmaf(a2, b1, acc[2][1]);
            acc[2][2] = fmaf(a2, b2, acc[2][2]);
        }
        if (tid < DH) {
            #pragma unroll
            for (int kk = 0; kk < 32; kk++) {
                float v = qs[kk][tid]; nacc = fmaf(v, v, nacc);
            }
        } else if (tid < 2 * DH) {
            int i = tid - DH;
            #pragma unroll
            for (int kk = 0; kk < 32; kk++) {
                float v = ks[kk][i]; nacc = fmaf(v, v, nacc);
            }
        }
    }

    float* pb = part + ((size_t)bh * 16 + chunk) * 2400;
    #pragma unroll
    for (int i = 0; i < 3; i++)
        #pragma unroll
        for (int j = 0; j < 3; j++)
            pb[(i0 + i) * DH + j0 + j] = acc[i][j];
    if (tid < 2 * DH) pb[2304 + tid] = nacc;
}

// ---------------- reduce partials + norms + softmax -----------------------------
__global__ void __launch_bounds__(256) reduce_softmax(
    const float* __restrict__ part, const float* __restrict__ temp,
    float* __restrict__ attn)
{
    int bh = blockIdx.x;
    int h = bh & 3;
    __shared__ float G[DH * DH];
    __shared__ float nq[DH], nk[DH];
    int tid = threadIdx.x;

    for (int e = tid; e < 2400; e += 256) {
        float s = 0.f;
        #pragma unroll
        for (int c = 0; c < 16; c++)
            s += part[((size_t)bh * 16 + c) * 2400 + e];
        if (e < 2304)      G[e] = s;
        else if (e < 2352) nq[e - 2304] = fmaxf(sqrtf(s), 1e-12f);
        else               nk[e - 2352] = fmaxf(sqrtf(s), 1e-12f);
    }
    __syncthreads();

    if (tid < DH) {
        int i = tid;
        float sc = __ldg(&temp[h]) / nq[i];
        float m = -1e30f;
        #pragma unroll 4
        for (int j = 0; j < DH; j++) {
            float s = G[i * DH + j] * sc / nk[j];
            G[i * DH + j] = s;
            m = fmaxf(m, s);
        }
        float sum = 0.f;
        #pragma unroll 4
        for (int j = 0; j < DH; j++) {
            float e = __expf(G[i * DH + j] - m);
            G[i * DH + j] = e;
            sum += e;
        }
        float rs = 1.f / sum;
        #pragma unroll 4
        for (int j = 0; j < DH; j++)
            attn[(size_t)bh * DH * DH + i * DH + j] = G[i * DH + j] * rs;
    }
}

// ---------------- M_b = W_proj @ blockdiag(attn_b), bf16 out --------------------
__global__ void __launch_bounds__(256) build_Mb(
    const float* __restrict__ attn, const float* __restrict__ wp,
    __nv_bfloat16* __restrict__ M)
{
    int b = blockIdx.x;
    __shared__ float sA[HEADS * DH * DH];
    int tid = threadIdx.x;
    for (int e = tid; e < HEADS * DH * DH; e += 256)
        sA[e] = attn[(size_t)b * HEADS * DH * DH + e];
    __syncthreads();

    for (int e = tid; e < C_ * C_; e += 256) {
        int o = e / C_, cp = e % C_;
        int h = cp / DH, d = cp % DH;
        const float* wrow = wp + (size_t)o * C_ + h * DH;
        const float* arow = sA + h * DH * DH + d;
        float s = 0.f;
        #pragma unroll
        for (int i = 0; i < DH; i++)
            s = fmaf(__ldg(&wrow[i]), arow[i * DH], s);
        M[(size_t)b * C_ * C_ + e] = __float2bfloat16(s);
    }
}

// ---------------- launch --------------------------------------------------------
#define GEMM_SMEM 102400

extern "C" void kernel_launch(void* const* d_in, const int* in_sizes, int n_in,
                              void* d_out, int out_size)
{
    const float* xx     = (const float*)d_in[0];
    const float* q_in   = (const float*)d_in[1];
    const float* ln_w   = (const float*)d_in[2];
    const float* ln_b   = (const float*)d_in[3];
    const float* w_q    = (const float*)d_in[4];
    const float* w_k    = (const float*)d_in[5];
    const float* w_v    = (const float*)d_in[6];
    const float* wd_q   = (const float*)d_in[7];
    const float* wd_k   = (const float*)d_in[8];
    const float* wd_v   = (const float*)d_in[9];
    const float* w_proj = (const float*)d_in[10];
    const float* temp   = (const float*)d_in[11];
    float* out = (float*)d_out;

    float* S = nullptr;
    cudaGetSymbolAddress((void**)&S, g_scratch);
    float* qb   = S + OFF_Q;
    float* kb   = S + OFF_K;
    float* vb   = S + OFF_V;
    float* qd   = S + OFF_QD;
    float* kd   = S + OFF_KD;
    float* vd   = S + OFF_VD;
    float* part = S + OFF_PART;
    float* attn = S + OFF_ATTN;
    __nv_bfloat16* whi = (__nv_bfloat16*)(S + OFF_WHI);
    const int PLANE = C_ * C_;

    cudaFuncSetAttribute(mma_gemm5,
                         cudaFuncAttributeMaxDynamicSharedMemorySize, GEMM_SMEM);

    // 1. weights -> bf16 planes (slots 0..2), single launch
    wconv3<<<dim3(36, 3), 256>>>(w_q, w_k, w_v, whi);

    // 2. 1x1 convs with fused LN (q: M=192; k+v stacked: M=384)
    dim3 gg(HW_ / 128, B_);
    mma_gemm5<<<gg, 256, GEMM_SMEM>>>(q_in, whi + 0 * PLANE,
                                      0, 3, qb, qb, nullptr, ln_w, ln_b);
    mma_gemm5<<<gg, 256, GEMM_SMEM>>>(xx, whi + 1 * PLANE,
                                      0, 6, kb, vb, nullptr, ln_w, ln_b);

    // 3. depthwise 3x3 (warp-strip, shuffle halos)
    dw3v2<<<dim3(B_ * C_, 3), 256>>>(qb, kb, vb, qd, kd, vd, wd_q, wd_k, wd_v);

    // 4. Gram + softmax
    gram_partial<<<dim3(16, 32), 256>>>(qd, kd, part);
    reduce_softmax<<<32, 256>>>(part, temp, attn);

    // 5. fold attn@v with proj (bf16 planes slots 3..10), final GEMM + residual
    build_Mb<<<8, 256>>>(attn, w_proj, whi + 3 * PLANE);
    mma_gemm5<<<gg, 256, GEMM_SMEM>>>(vd, whi + 3 * PLANE,
                                      PLANE, 3, out, out, q_in,
                                      nullptr, nullptr);
}

// round 10
// speedup vs baseline: 3.5904x; 1.1001x over previous
#include <cuda_runtime.h>
#include <cuda_bf16.h>
#include <cstddef>
#include <cstdint>

#define B_    8
#define C_    192
#define H_    128
#define W_    128
#define HW_   16384
#define HEADS 4
#define DH    48

// ---------------- scratch ----------------------------------------------------
// bf16 tensors (each B*C*HW bf16 = TEN/2 floats): qb kb vb qd kd vd
#define TEN    ((size_t)B_ * C_ * HW_)
#define BFTEN  (TEN / 2)                  // floats per bf16 tensor
#define OFF_QB   ((size_t)0)
#define OFF_KB   (BFTEN * 1)
#define OFF_VB   (BFTEN * 2)
#define OFF_QD   (BFTEN * 3)
#define OFF_KD   (BFTEN * 4)
#define OFF_VD   (BFTEN * 5)
#define OFF_PART (BFTEN * 6)
#define PART_SZ  ((size_t)32 * 16 * 2400)
#define OFF_ATTN (OFF_PART + PART_SZ)
#define ATTN_SZ  ((size_t)32 * 48 * 48)
// bf16 weight planes: slots 0=wq, 1=wk, 2=wv, 3..10=Mb[8]
#define PLANE_FL 18432
#define OFF_WHI  (OFF_ATTN + ATTN_SZ)
#define TOTAL_SCRATCH (OFF_WHI + (size_t)11 * PLANE_FL)

__device__ __align__(256) float g_scratch[TOTAL_SCRATCH];

// ---------------- 3 weights -> bf16 planes (one launch) -------------------------
__global__ void __launch_bounds__(256) wconv3(
    const float* __restrict__ w_q, const float* __restrict__ w_k,
    const float* __restrict__ w_v, __nv_bfloat16* __restrict__ dst)
{
    int mat = blockIdx.y;
    const float* src = mat == 0 ? w_q : mat == 1 ? w_k : w_v;
    dst += (size_t)mat * (C_ * C_);
    for (int idx = blockIdx.x * 256 + threadIdx.x; idx < C_ * C_;
         idx += gridDim.x * 256)
        dst[idx] = __float2bfloat16(src[idx]);
}

// ---------------- mma / async helpers -------------------------------------------
__device__ __forceinline__ void mma_bf16(float* c, const uint32_t* a,
                                         const uint32_t* b)
{
    asm volatile(
        "mma.sync.aligned.m16n8k16.row.col.f32.bf16.bf16.f32 "
        "{%0,%1,%2,%3}, {%4,%5,%6,%7}, {%8,%9}, {%0,%1,%2,%3};"
        : "+f"(c[0]), "+f"(c[1]), "+f"(c[2]), "+f"(c[3])
        : "r"(a[0]), "r"(a[1]), "r"(a[2]), "r"(a[3]), "r"(b[0]), "r"(b[1]));
}
__device__ __forceinline__ void ldsm_x4(uint32_t* r, uint32_t addr)
{
    asm volatile("ldmatrix.sync.aligned.m8n8.x4.shared.b16 {%0,%1,%2,%3}, [%4];"
        : "=r"(r[0]), "=r"(r[1]), "=r"(r[2]), "=r"(r[3]) : "r"(addr));
}
__device__ __forceinline__ void cp_async16(uint32_t dst, const void* src)
{
    asm volatile("cp.async.cg.shared.global [%0], [%1], 16;"
        :: "r"(dst), "l"(src) : "memory");
}
#define CP_COMMIT() asm volatile("cp.async.commit_group;" ::: "memory")
#define CP_WAIT(n)  asm volatile("cp.async.wait_group %0;" :: "n"(n) : "memory")

__device__ __forceinline__ uint32_t pack_bf2(float a, float b) {
    __nv_bfloat162 h = __floats2bfloat162_rn(a, b);
    return *reinterpret_cast<uint32_t*>(&h);
}

// ---------------- tensor-core GEMM v6 -------------------------------------------
// C[m,p] = sum_k W[m,k] * LN(X)[k,p] (+ residual), single bf16 product.
// inBf16: X is bf16 (no LN). outBf16: outputs stored bf16.
// B staged once (LN stats fused, normalize in smem). A double-buffered cp.async.
// smem words (stride 100/row): Bh[128] @0 (12800), A buf b @ 12800 + b*6400.
__global__ void __launch_bounds__(256) mma_gemm6(
    const void* __restrict__ Xv, int inBf16,
    const __nv_bfloat16* __restrict__ whi,
    int wStride, int mTiles,
    void* __restrict__ Out0, void* __restrict__ Out1, int outBf16,
    const float* __restrict__ R,
    const float* __restrict__ gw, const float* __restrict__ gb)
{
    extern __shared__ uint32_t sm[];
    uint32_t* Bh = sm;
    __shared__ float sP[256], ssP[256];

    int tid  = threadIdx.x;
    int w    = tid >> 5, lane = tid & 31;
    int wm   = w >> 2,  wn = w & 3;
    int g    = lane >> 2, t = lane & 3;
    int np0  = blockIdx.x * 128;
    int b    = blockIdx.y;
    const __nv_bfloat16* wH = whi + (size_t)b * wStride;
    uint32_t smBase = (uint32_t)__cvta_generic_to_shared(sm);

    // ---- stage B: one global pass ----
    {
        int p = tid & 127, kh = tid >> 7;      // 2 threads per pixel
        if (inBf16) {
            const __nv_bfloat16* xc =
                (const __nv_bfloat16*)Xv + (size_t)b * C_ * HW_ + np0 + p;
            #pragma unroll
            for (int i = 0; i < 48; i++) {
                int kp = kh * 48 + i, k = kp * 2;
                union { __nv_bfloat16 h[2]; uint32_t u; } pk;
                pk.h[0] = xc[(size_t)k * HW_];
                pk.h[1] = xc[(size_t)(k + 1) * HW_];
                Bh[p * 100 + kp] = pk.u;
            }
        } else {
            const float* xc = (const float*)Xv + (size_t)b * C_ * HW_ + np0 + p;
            float s = 0.f, ss = 0.f;
            #pragma unroll
            for (int i = 0; i < 48; i++) {
                int k = kh * 96 + i * 2;
                float x0 = xc[(size_t)k * HW_];
                float x1 = xc[(size_t)(k + 1) * HW_];
                s += x0 + x1;
                ss = fmaf(x0, x0, fmaf(x1, x1, ss));
                Bh[p * 100 + kh * 48 + i] = pack_bf2(x0, x1);
            }
            sP[tid] = s; ssP[tid] = ss;
            __syncthreads();
            float st  = sP[p] + sP[p + 128];
            float sst = ssP[p] + ssP[p + 128];
            float mu_ = st * (1.f / C_);
            float rs_ = rsqrtf(sst * (1.f / C_) - mu_ * mu_ + 1e-5f);
            #pragma unroll
            for (int i = 0; i < 48; i++) {
                int kp = kh * 48 + i, k = kp * 2;
                uint32_t u = Bh[p * 100 + kp];
                __nv_bfloat162 hv = *reinterpret_cast<__nv_bfloat162*>(&u);
                float x0 = __bfloat162float(hv.x);
                float x1 = __bfloat162float(hv.y);
                x0 = (x0 - mu_) * rs_ * __ldg(&gw[k])     + __ldg(&gb[k]);
                x1 = (x1 - mu_) * rs_ * __ldg(&gw[k + 1]) + __ldg(&gb[k + 1]);
                Bh[p * 100 + kp] = pack_bf2(x0, x1);
            }
        }
    }

    // ---- lane-level ldmatrix base addresses for B ----
    uint32_t baseB[2];
    #pragma unroll
    for (int in2 = 0; in2 < 2; in2++) {
        int row = wn * 32 + in2 * 16 + ((lane >> 4) << 3) + (lane & 7);
        baseB[in2] = smBase + (uint32_t)((row * 100 + ((lane >> 3) & 1) * 4) * 4);
    }

    // ---- A prefetch helper ----
    auto copyA = [&](int mt, int buf) {
        #pragma unroll
        for (int i = 0; i < 6; i++) {
            int idx = tid + 256 * i;
            int row = idx / 24, j = idx % 24;
            size_t go = (size_t)(mt * 64 + row) * C_ + j * 8;
            uint32_t dst = smBase +
                (uint32_t)((12800 + buf * 6400 + row * 100 + j * 4) * 4);
            cp_async16(dst, &wH[go]);
        }
    };

    copyA(0, 0);
    CP_COMMIT();

    for (int mt = 0; mt < mTiles; mt++) {
        int buf = mt & 1;
        if (mt + 1 < mTiles) {
            copyA(mt + 1, buf ^ 1);
            CP_COMMIT();
            CP_WAIT(1);
        } else {
            CP_WAIT(0);
        }
        __syncthreads();

        uint32_t aB = smBase + (uint32_t)((12800 + buf * 6400) * 4);
        uint32_t baseA[2];
        #pragma unroll
        for (int im = 0; im < 2; im++) {
            int row = wm * 32 + im * 16 + (lane & 15);
            baseA[im] = aB + (uint32_t)(row * 400 + (lane >> 4) * 16);
        }

        float acc[8][4];
        #pragma unroll
        for (int i = 0; i < 8; i++)
            #pragma unroll
            for (int j = 0; j < 4; j++) acc[i][j] = 0.f;

        #pragma unroll
        for (int s = 0; s < 12; s++) {
            uint32_t ah[2][4], bh[2][4];
            #pragma unroll
            for (int im = 0; im < 2; im++)
                ldsm_x4(ah[im], baseA[im] + s * 32);
            #pragma unroll
            for (int in2 = 0; in2 < 2; in2++)
                ldsm_x4(bh[in2], baseB[in2] + s * 32);
            #pragma unroll
            for (int im = 0; im < 2; im++)
                #pragma unroll
                for (int in_ = 0; in_ < 4; in_++)
                    mma_bf16(acc[im * 4 + in_], ah[im],
                             &bh[in_ >> 1][(in_ & 1) * 2]);
        }

        // ---- epilogue ----
        #pragma unroll
        for (int im = 0; im < 2; im++) {
            #pragma unroll
            for (int in_ = 0; in_ < 4; in_++) {
                const float* c = acc[im * 4 + in_];
                int grow = mt * 64 + wm * 32 + im * 16 + g;
                int col  = np0 + wn * 32 + in_ * 8 + t * 2;
                #pragma unroll
                for (int half = 0; half < 2; half++) {
                    int rr = grow + half * 8;
                    float2 v = make_float2(c[half * 2], c[half * 2 + 1]);
                    if (outBf16) {
                        size_t off = (size_t)b * C_ * HW_ +
                            (size_t)((rr < C_) ? rr : rr - C_) * HW_ + col;
                        __nv_bfloat16* o = (rr < C_)
                            ? (__nv_bfloat16*)Out0 + off
                            : (__nv_bfloat16*)Out1 + off;
                        *reinterpret_cast<uint32_t*>(o) = pack_bf2(v.x, v.y);
                    } else {
                        size_t off = (size_t)b * C_ * HW_ +
                            (size_t)((rr < C_) ? rr : rr - C_) * HW_ + col;
                        float* o = (rr < C_) ? (float*)Out0 + off
                                             : (float*)Out1 + off;
                        if (R && rr < C_) {
                            const float2 r2 = *reinterpret_cast<const float2*>(
                                &R[(size_t)b * C_ * HW_ + (size_t)rr * HW_ + col]);
                            v.x += r2.x; v.y += r2.y;
                        }
                        *reinterpret_cast<float2*>(o) = v;
                    }
                }
            }
        }
        __syncthreads();
    }
}

// ---------------- depthwise 3x3 bf16: warp-strip, shuffle halos -----------------
__device__ __forceinline__ void dw_load_row_bf(
    const __nv_bfloat16* __restrict__ ib, int y, int lane,
    float& l, float4& f, float& r)
{
    if ((unsigned)y < (unsigned)H_) {
        uint2 u = *reinterpret_cast<const uint2*>(ib + (size_t)y * W_ + lane * 4);
        __nv_bfloat162 lo = *reinterpret_cast<__nv_bfloat162*>(&u.x);
        __nv_bfloat162 hi = *reinterpret_cast<__nv_bfloat162*>(&u.y);
        f = make_float4(__bfloat162float(lo.x), __bfloat162float(lo.y),
                        __bfloat162float(hi.x), __bfloat162float(hi.y));
    } else {
        f = make_float4(0.f, 0.f, 0.f, 0.f);
    }
    float lw = __shfl_up_sync(0xffffffffu, f.w, 1);
    float rx = __shfl_down_sync(0xffffffffu, f.x, 1);
    l = (lane == 0)  ? 0.f : lw;
    r = (lane == 31) ? 0.f : rx;
}

__global__ void __launch_bounds__(256) dw3v3(
    const __nv_bfloat16* __restrict__ inq, const __nv_bfloat16* __restrict__ ink,
    const __nv_bfloat16* __restrict__ inv,
    __nv_bfloat16* __restrict__ outq, __nv_bfloat16* __restrict__ outk,
    __nv_bfloat16* __restrict__ outv,
    const float* __restrict__ wq, const float* __restrict__ wk,
    const float* __restrict__ wv)
{
    int which = blockIdx.y;
    const __nv_bfloat16* in  = which == 0 ? inq  : which == 1 ? ink  : inv;
    __nv_bfloat16*       out = which == 0 ? outq : which == 1 ? outk : outv;
    const float*         wt  = which == 0 ? wq   : which == 1 ? wk   : wv;

    int bc = blockIdx.x;
    int c  = bc % C_;
    const float* wp = wt + c * 9;
    float w00 = __ldg(wp + 0), w01 = __ldg(wp + 1), w02 = __ldg(wp + 2);
    float w10 = __ldg(wp + 3), w11 = __ldg(wp + 4), w12 = __ldg(wp + 5);
    float w20 = __ldg(wp + 6), w21 = __ldg(wp + 7), w22 = __ldg(wp + 8);

    int warp = threadIdx.x >> 5, lane = threadIdx.x & 31;
    int y0 = warp * 16;
    const __nv_bfloat16* ib = in + (size_t)bc * HW_;
    __nv_bfloat16* ob = out + (size_t)bc * HW_;

    float pl, pr, cl, cr, nl, nr;
    float4 pf, cf, nf;
    dw_load_row_bf(ib, y0 - 1, lane, pl, pf, pr);
    dw_load_row_bf(ib, y0,     lane, cl, cf, cr);

    #pragma unroll
    for (int r = 0; r < 16; r++) {
        int y = y0 + r;
        dw_load_row_bf(ib, y + 1, lane, nl, nf, nr);
        float4 o;
        o.x = fmaf(pl,   w00, fmaf(pf.x, w01, fmaf(pf.y, w02,
              fmaf(cl,   w10, fmaf(cf.x, w11, fmaf(cf.y, w12,
              fmaf(nl,   w20, fmaf(nf.x, w21, nf.y * w22))))))));
        o.y = fmaf(pf.x, w00, fmaf(pf.y, w01, fmaf(pf.z, w02,
              fmaf(cf.x, w10, fmaf(cf.y, w11, fmaf(cf.z, w12,
              fmaf(nf.x, w20, fmaf(nf.y, w21, nf.z * w22))))))));
        o.z = fmaf(pf.y, w00, fmaf(pf.z, w01, fmaf(pf.w, w02,
              fmaf(cf.y, w10, fmaf(cf.z, w11, fmaf(cf.w, w12,
              fmaf(nf.y, w20, fmaf(nf.z, w21, nf.w * w22))))))));
        o.w = fmaf(pf.z, w00, fmaf(pf.w, w01, fmaf(pr,   w02,
              fmaf(cf.z, w10, fmaf(cf.w, w11, fmaf(cr,   w12,
              fmaf(nf.z, w20, fmaf(nf.w, w21, nr * w22))))))));
        uint2 st;
        st.x = pack_bf2(o.x, o.y);
        st.y = pack_bf2(o.z, o.w);
        *reinterpret_cast<uint2*>(ob + (size_t)y * W_ + lane * 4) = st;
        pl = cl; pr = cr; pf = cf;
        cl = nl; cr = nr; cf = nf;
    }
}

// ---------------- Gram partial (bf16 inputs) ------------------------------------
__global__ void __launch_bounds__(256) gram_partial(
    const __nv_bfloat16* __restrict__ qd, const __nv_bfloat16* __restrict__ kd,
    float* __restrict__ part)
{
    int chunk = blockIdx.x;
    int bh    = blockIdx.y;
    int b = bh >> 2, h = bh & 3;
    size_t rowbase = ((size_t)b * C_ + h * DH) * HW_ + (size_t)chunk * 1024;
    const __nv_bfloat16* qb = qd + rowbase;
    const __nv_bfloat16* kb = kd + rowbase;

    __shared__ float qs[32][DH + 1];
    __shared__ float ks[32][DH + 1];

    int tid = threadIdx.x;
    int ti = tid & 15, tj = tid >> 4;
    int i0 = ti * 3, j0 = tj * 3;

    float acc[3][3];
    #pragma unroll
    for (int i = 0; i < 3; i++)
        #pragma unroll
        for (int j = 0; j < 3; j++) acc[i][j] = 0.f;
    float nacc = 0.f;

    for (int t = 0; t < 32; t++) {
        __syncthreads();
        #pragma unroll
        for (int r = 0; r < 6; r++) {
            int e = tid + 256 * r;
            int i = e >> 5, nlc = e & 31;
            qs[nlc][i] = __bfloat162float(qb[(size_t)i * HW_ + t * 32 + nlc]);
            ks[nlc][i] = __bfloat162float(kb[(size_t)i * HW_ + t * 32 + nlc]);
        }
        __syncthreads();
        #pragma unroll
        for (int kk = 0; kk < 32; kk++) {
            float a0 = qs[kk][i0], a1 = qs[kk][i0 + 1], a2 = qs[kk][i0 + 2];
            float b0 = ks[kk][j0], b1 = ks[kk][j0 + 1], b2 = ks[kk][j0 + 2];
            acc[0][0] = fmaf(a0, b0, acc[0][0]);
            acc[0][1] = fmaf(a0, b1, acc[0][1]);
            acc[0][2] = fmaf(a0, b2, acc[0][2]);
            acc[1][0] = fmaf(a1, b0, acc[1][0]);
            acc[1][1] = fmaf(a1, b1, acc[1][1]);
            acc[1][2] = fmaf(a1, b2, acc[1][2]);
            acc[2][0] = fmaf(a2, b0, acc[2][0]);
            acc[2][1] = fmaf(a2, b1, acc[2][1]);
            acc[2][2] = fmaf(a2, b2, acc[2][2]);
        }
        if (tid < DH) {
            #pragma unroll
            for (int kk = 0; kk < 32; kk++) {
                float v = qs[kk][tid]; nacc = fmaf(v, v, nacc);
            }
        } else if (tid < 2 * DH) {
            int i = tid - DH;
            #pragma unroll
            for (int kk = 0; kk < 32; kk++) {
                float v = ks[kk][i]; nacc = fmaf(v, v, nacc);
            }
        }
    }

    float* pb = part + ((size_t)bh * 16 + chunk) * 2400;
    #pragma unroll
    for (int i = 0; i < 3; i++)
        #pragma unroll
        for (int j = 0; j < 3; j++)
            pb[(i0 + i) * DH + j0 + j] = acc[i][j];
    if (tid < 2 * DH) pb[2304 + tid] = nacc;
}

// ---------------- reduce partials + norms + softmax -----------------------------
__global__ void __launch_bounds__(256) reduce_softmax(
    const float* __restrict__ part, const float* __restrict__ temp,
    float* __restrict__ attn)
{
    int bh = blockIdx.x;
    int h = bh & 3;
    __shared__ float G[DH * DH];
    __shared__ float nq[DH], nk[DH];
    int tid = threadIdx.x;

    for (int e = tid; e < 2400; e += 256) {
        float s = 0.f;
        #pragma unroll
        for (int c = 0; c < 16; c++)
            s += part[((size_t)bh * 16 + c) * 2400 + e];
        if (e < 2304)      G[e] = s;
        else if (e < 2352) nq[e - 2304] = fmaxf(sqrtf(s), 1e-12f);
        else               nk[e - 2352] = fmaxf(sqrtf(s), 1e-12f);
    }
    __syncthreads();

    if (tid < DH) {
        int i = tid;
        float sc = __ldg(&temp[h]) / nq[i];
        float m = -1e30f;
        #pragma unroll 4
        for (int j = 0; j < DH; j++) {
            float s = G[i * DH + j] * sc / nk[j];
            G[i * DH + j] = s;
            m = fmaxf(m, s);
        }
        float sum = 0.f;
        #pragma unroll 4
        for (int j = 0; j < DH; j++) {
            float e = __expf(G[i * DH + j] - m);
            G[i * DH + j] = e;
            sum += e;
        }
        float rs = 1.f / sum;
        #pragma unroll 4
        for (int j = 0; j < DH; j++)
            attn[(size_t)bh * DH * DH + i * DH + j] = G[i * DH + j] * rs;
    }
}

// ---------------- M_b = W_proj @ blockdiag(attn_b), bf16 out --------------------
__global__ void __launch_bounds__(256) build_Mb(
    const float* __restrict__ attn, const float* __restrict__ wp,
    __nv_bfloat16* __restrict__ M)
{
    int b = blockIdx.x;
    __shared__ float sA[HEADS * DH * DH];
    int tid = threadIdx.x;
    for (int e = tid; e < HEADS * DH * DH; e += 256)
        sA[e] = attn[(size_t)b * HEADS * DH * DH + e];
    __syncthreads();

    for (int e = tid; e < C_ * C_; e += 256) {
        int o = e / C_, cp = e % C_;
        int h = cp / DH, d = cp % DH;
        const float* wrow = wp + (size_t)o * C_ + h * DH;
        const float* arow = sA + h * DH * DH + d;
        float s = 0.f;
        #pragma unroll
        for (int i = 0; i < DH; i++)
            s = fmaf(__ldg(&wrow[i]), arow[i * DH], s);
        M[(size_t)b * C_ * C_ + e] = __float2bfloat16(s);
    }
}

// ---------------- launch --------------------------------------------------------
#define GEMM_SMEM 102400

extern "C" void kernel_launch(void* const* d_in, const int* in_sizes, int n_in,
                              void* d_out, int out_size)
{
    const float* xx     = (const float*)d_in[0];
    const float* q_in   = (const float*)d_in[1];
    const float* ln_w   = (const float*)d_in[2];
    const float* ln_b   = (const float*)d_in[3];
    const float* w_q    = (const float*)d_in[4];
    const float* w_k    = (const float*)d_in[5];
    const float* w_v    = (const float*)d_in[6];
    const float* wd_q   = (const float*)d_in[7];
    const float* wd_k   = (const float*)d_in[8];
    const float* wd_v   = (const float*)d_in[9];
    const float* w_proj = (const float*)d_in[10];
    const float* temp   = (const float*)d_in[11];
    float* out = (float*)d_out;

    float* S = nullptr;
    cudaGetSymbolAddress((void**)&S, g_scratch);
    __nv_bfloat16* qb = (__nv_bfloat16*)(S + OFF_QB);
    __nv_bfloat16* kb = (__nv_bfloat16*)(S + OFF_KB);
    __nv_bfloat16* vb = (__nv_bfloat16*)(S + OFF_VB);
    __nv_bfloat16* qd = (__nv_bfloat16*)(S + OFF_QD);
    __nv_bfloat16* kd = (__nv_bfloat16*)(S + OFF_KD);
    __nv_bfloat16* vd = (__nv_bfloat16*)(S + OFF_VD);
    float* part = S + OFF_PART;
    float* attn = S + OFF_ATTN;
    __nv_bfloat16* whi = (__nv_bfloat16*)(S + OFF_WHI);
    const int PLANE = C_ * C_;

    cudaFuncSetAttribute(mma_gemm6,
                         cudaFuncAttributeMaxDynamicSharedMemorySize, GEMM_SMEM);

    // 1. weights -> bf16 planes (slots 0..2)
    wconv3<<<dim3(36, 3), 256>>>(w_q, w_k, w_v, whi);

    // 2. 1x1 convs with fused LN (q: M=192; k+v stacked: M=384), bf16 out
    dim3 gg(HW_ / 128, B_);
    mma_gemm6<<<gg, 256, GEMM_SMEM>>>(q_in, 0, whi + 0 * PLANE, 0, 3,
                                      qb, qb, 1, nullptr, ln_w, ln_b);
    mma_gemm6<<<gg, 256, GEMM_SMEM>>>(xx, 0, whi + 1 * PLANE, 0, 6,
                                      kb, vb, 1, nullptr, ln_w, ln_b);

    // 3. depthwise 3x3 (bf16 in/out)
    dw3v3<<<dim3(B_ * C_, 3), 256>>>(qb, kb, vb, qd, kd, vd, wd_q, wd_k, wd_v);

    // 4. Gram + softmax
    gram_partial<<<dim3(16, 32), 256>>>(qd, kd, part);
    reduce_softmax<<<32, 256>>>(part, temp, attn);

    // 5. fold attn@v with proj (bf16 planes 3..10), final GEMM fp32 + residual
    build_Mb<<<8, 256>>>(attn, w_proj, whi + 3 * PLANE);
    mma_gemm6<<<gg, 256, GEMM_SMEM>>>(vd, 1, whi + 3 * PLANE, PLANE, 3,
                                      out, out, 0, q_in, nullptr, nullptr);
}

// round 11
// speedup vs baseline: 4.3754x; 1.2186x over previous
#include <cuda_runtime.h>
#include <cuda_bf16.h>
#include <cstddef>
#include <cstdint>

#define B_    8
#define C_    192
#define H_    128
#define W_    128
#define HW_   16384
#define HEADS 4
#define DH    48

// ---------------- scratch ----------------------------------------------------
#define TEN    ((size_t)B_ * C_ * HW_)
#define BFTEN  (TEN / 2)
#define OFF_QB   ((size_t)0)
#define OFF_KB   (BFTEN * 1)
#define OFF_VB   (BFTEN * 2)
#define OFF_QD   (BFTEN * 3)
#define OFF_KD   (BFTEN * 4)
#define OFF_VD   (BFTEN * 5)
#define OFF_PART (BFTEN * 6)
#define PART_SZ  ((size_t)32 * 16 * 2400)
#define OFF_ATTN (OFF_PART + PART_SZ)
#define ATTN_SZ  ((size_t)32 * 48 * 48)
#define PLANE_FL 18432
#define OFF_WHI  (OFF_ATTN + ATTN_SZ)
#define TOTAL_SCRATCH (OFF_WHI + (size_t)11 * PLANE_FL)

__device__ __align__(256) float g_scratch[TOTAL_SCRATCH];

// ---------------- 3 weights -> bf16 planes --------------------------------------
__global__ void __launch_bounds__(256) wconv3(
    const float* __restrict__ w_q, const float* __restrict__ w_k,
    const float* __restrict__ w_v, __nv_bfloat16* __restrict__ dst)
{
    int mat = blockIdx.y;
    const float* src = mat == 0 ? w_q : mat == 1 ? w_k : w_v;
    dst += (size_t)mat * (C_ * C_);
    for (int idx = blockIdx.x * 256 + threadIdx.x; idx < C_ * C_;
         idx += gridDim.x * 256)
        dst[idx] = __float2bfloat16(src[idx]);
}

// ---------------- mma / async helpers -------------------------------------------
__device__ __forceinline__ void mma_bf16(float* c, const uint32_t* a,
                                         const uint32_t* b)
{
    asm volatile(
        "mma.sync.aligned.m16n8k16.row.col.f32.bf16.bf16.f32 "
        "{%0,%1,%2,%3}, {%4,%5,%6,%7}, {%8,%9}, {%0,%1,%2,%3};"
        : "+f"(c[0]), "+f"(c[1]), "+f"(c[2]), "+f"(c[3])
        : "r"(a[0]), "r"(a[1]), "r"(a[2]), "r"(a[3]), "r"(b[0]), "r"(b[1]));
}
__device__ __forceinline__ void ldsm_x4(uint32_t* r, uint32_t addr)
{
    asm volatile("ldmatrix.sync.aligned.m8n8.x4.shared.b16 {%0,%1,%2,%3}, [%4];"
        : "=r"(r[0]), "=r"(r[1]), "=r"(r[2]), "=r"(r[3]) : "r"(addr));
}
__device__ __forceinline__ void ldsm_x2(uint32_t* r, uint32_t addr)
{
    asm volatile("ldmatrix.sync.aligned.m8n8.x2.shared.b16 {%0,%1}, [%2];"
        : "=r"(r[0]), "=r"(r[1]) : "r"(addr));
}
__device__ __forceinline__ void cp_async16(uint32_t dst, const void* src)
{
    asm volatile("cp.async.cg.shared.global [%0], [%1], 16;"
        :: "r"(dst), "l"(src) : "memory");
}
#define CP_COMMIT() asm volatile("cp.async.commit_group;" ::: "memory")
#define CP_WAIT(n)  asm volatile("cp.async.wait_group %0;" :: "n"(n) : "memory")

__device__ __forceinline__ uint32_t pack_bf2(float a, float b) {
    __nv_bfloat162 h = __floats2bfloat162_rn(a, b);
    return *reinterpret_cast<uint32_t*>(&h);
}

// ---------------- tensor-core GEMM v6 (unchanged from R10) ----------------------
__global__ void __launch_bounds__(256) mma_gemm6(
    const void* __restrict__ Xv, int inBf16,
    const __nv_bfloat16* __restrict__ whi,
    int wStride, int mTiles,
    void* __restrict__ Out0, void* __restrict__ Out1, int outBf16,
    const float* __restrict__ R,
    const float* __restrict__ gw, const float* __restrict__ gb)
{
    extern __shared__ uint32_t sm[];
    uint32_t* Bh = sm;
    __shared__ float sP[256], ssP[256];

    int tid  = threadIdx.x;
    int w    = tid >> 5, lane = tid & 31;
    int wm   = w >> 2,  wn = w & 3;
    int g    = lane >> 2, t = lane & 3;
    int np0  = blockIdx.x * 128;
    int b    = blockIdx.y;
    const __nv_bfloat16* wH = whi + (size_t)b * wStride;
    uint32_t smBase = (uint32_t)__cvta_generic_to_shared(sm);

    {
        int p = tid & 127, kh = tid >> 7;
        if (inBf16) {
            const __nv_bfloat16* xc =
                (const __nv_bfloat16*)Xv + (size_t)b * C_ * HW_ + np0 + p;
            #pragma unroll
            for (int i = 0; i < 48; i++) {
                int kp = kh * 48 + i, k = kp * 2;
                union { __nv_bfloat16 h[2]; uint32_t u; } pk;
                pk.h[0] = xc[(size_t)k * HW_];
                pk.h[1] = xc[(size_t)(k + 1) * HW_];
                Bh[p * 100 + kp] = pk.u;
            }
        } else {
            const float* xc = (const float*)Xv + (size_t)b * C_ * HW_ + np0 + p;
            float s = 0.f, ss = 0.f;
            #pragma unroll
            for (int i = 0; i < 48; i++) {
                int k = kh * 96 + i * 2;
                float x0 = xc[(size_t)k * HW_];
                float x1 = xc[(size_t)(k + 1) * HW_];
                s += x0 + x1;
                ss = fmaf(x0, x0, fmaf(x1, x1, ss));
                Bh[p * 100 + kh * 48 + i] = pack_bf2(x0, x1);
            }
            sP[tid] = s; ssP[tid] = ss;
            __syncthreads();
            float st  = sP[p] + sP[p + 128];
            float sst = ssP[p] + ssP[p + 128];
            float mu_ = st * (1.f / C_);
            float rs_ = rsqrtf(sst * (1.f / C_) - mu_ * mu_ + 1e-5f);
            #pragma unroll
            for (int i = 0; i < 48; i++) {
                int kp = kh * 48 + i, k = kp * 2;
                uint32_t u = Bh[p * 100 + kp];
                __nv_bfloat162 hv = *reinterpret_cast<__nv_bfloat162*>(&u);
                float x0 = __bfloat162float(hv.x);
                float x1 = __bfloat162float(hv.y);
                x0 = (x0 - mu_) * rs_ * __ldg(&gw[k])     + __ldg(&gb[k]);
                x1 = (x1 - mu_) * rs_ * __ldg(&gw[k + 1]) + __ldg(&gb[k + 1]);
                Bh[p * 100 + kp] = pack_bf2(x0, x1);
            }
        }
    }

    uint32_t baseB[2];
    #pragma unroll
    for (int in2 = 0; in2 < 2; in2++) {
        int row = wn * 32 + in2 * 16 + ((lane >> 4) << 3) + (lane & 7);
        baseB[in2] = smBase + (uint32_t)((row * 100 + ((lane >> 3) & 1) * 4) * 4);
    }

    auto copyA = [&](int mt, int buf) {
        #pragma unroll
        for (int i = 0; i < 6; i++) {
            int idx = tid + 256 * i;
            int row = idx / 24, j = idx % 24;
            size_t go = (size_t)(mt * 64 + row) * C_ + j * 8;
            uint32_t dst = smBase +
                (uint32_t)((12800 + buf * 6400 + row * 100 + j * 4) * 4);
            cp_async16(dst, &wH[go]);
        }
    };

    copyA(0, 0);
    CP_COMMIT();

    for (int mt = 0; mt < mTiles; mt++) {
        int buf = mt & 1;
        if (mt + 1 < mTiles) {
            copyA(mt + 1, buf ^ 1);
            CP_COMMIT();
            CP_WAIT(1);
        } else {
            CP_WAIT(0);
        }
        __syncthreads();

        uint32_t aB = smBase + (uint32_t)((12800 + buf * 6400) * 4);
        uint32_t baseA[2];
        #pragma unroll
        for (int im = 0; im < 2; im++) {
            int row = wm * 32 + im * 16 + (lane & 15);
            baseA[im] = aB + (uint32_t)(row * 400 + (lane >> 4) * 16);
        }

        float acc[8][4];
        #pragma unroll
        for (int i = 0; i < 8; i++)
            #pragma unroll
            for (int j = 0; j < 4; j++) acc[i][j] = 0.f;

        #pragma unroll
        for (int s = 0; s < 12; s++) {
            uint32_t ah[2][4], bh[2][4];
            #pragma unroll
            for (int im = 0; im < 2; im++)
                ldsm_x4(ah[im], baseA[im] + s * 32);
            #pragma unroll
            for (int in2 = 0; in2 < 2; in2++)
                ldsm_x4(bh[in2], baseB[in2] + s * 32);
            #pragma unroll
            for (int im = 0; im < 2; im++)
                #pragma unroll
                for (int in_ = 0; in_ < 4; in_++)
                    mma_bf16(acc[im * 4 + in_], ah[im],
                             &bh[in_ >> 1][(in_ & 1) * 2]);
        }

        #pragma unroll
        for (int im = 0; im < 2; im++) {
            #pragma unroll
            for (int in_ = 0; in_ < 4; in_++) {
                const float* c = acc[im * 4 + in_];
                int grow = mt * 64 + wm * 32 + im * 16 + g;
                int col  = np0 + wn * 32 + in_ * 8 + t * 2;
                #pragma unroll
                for (int half = 0; half < 2; half++) {
                    int rr = grow + half * 8;
                    float2 v = make_float2(c[half * 2], c[half * 2 + 1]);
                    if (outBf16) {
                        size_t off = (size_t)b * C_ * HW_ +
                            (size_t)((rr < C_) ? rr : rr - C_) * HW_ + col;
                        __nv_bfloat16* o = (rr < C_)
                            ? (__nv_bfloat16*)Out0 + off
                            : (__nv_bfloat16*)Out1 + off;
                        *reinterpret_cast<uint32_t*>(o) = pack_bf2(v.x, v.y);
                    } else {
                        size_t off = (size_t)b * C_ * HW_ +
                            (size_t)((rr < C_) ? rr : rr - C_) * HW_ + col;
                        float* o = (rr < C_) ? (float*)Out0 + off
                                             : (float*)Out1 + off;
                        if (R && rr < C_) {
                            const float2 r2 = *reinterpret_cast<const float2*>(
                                &R[(size_t)b * C_ * HW_ + (size_t)rr * HW_ + col]);
                            v.x += r2.x; v.y += r2.y;
                        }
                        *reinterpret_cast<float2*>(o) = v;
                    }
                }
            }
        }
        __syncthreads();
    }
}

// ---------------- depthwise 3x3 bf16 (unchanged) --------------------------------
__device__ __forceinline__ void dw_load_row_bf(
    const __nv_bfloat16* __restrict__ ib, int y, int lane,
    float& l, float4& f, float& r)
{
    if ((unsigned)y < (unsigned)H_) {
        uint2 u = *reinterpret_cast<const uint2*>(ib + (size_t)y * W_ + lane * 4);
        __nv_bfloat162 lo = *reinterpret_cast<__nv_bfloat162*>(&u.x);
        __nv_bfloat162 hi = *reinterpret_cast<__nv_bfloat162*>(&u.y);
        f = make_float4(__bfloat162float(lo.x), __bfloat162float(lo.y),
                        __bfloat162float(hi.x), __bfloat162float(hi.y));
    } else {
        f = make_float4(0.f, 0.f, 0.f, 0.f);
    }
    float lw = __shfl_up_sync(0xffffffffu, f.w, 1);
    float rx = __shfl_down_sync(0xffffffffu, f.x, 1);
    l = (lane == 0)  ? 0.f : lw;
    r = (lane == 31) ? 0.f : rx;
}

__global__ void __launch_bounds__(256) dw3v3(
    const __nv_bfloat16* __restrict__ inq, const __nv_bfloat16* __restrict__ ink,
    const __nv_bfloat16* __restrict__ inv,
    __nv_bfloat16* __restrict__ outq, __nv_bfloat16* __restrict__ outk,
    __nv_bfloat16* __restrict__ outv,
    const float* __restrict__ wq, const float* __restrict__ wk,
    const float* __restrict__ wv)
{
    int which = blockIdx.y;
    const __nv_bfloat16* in  = which == 0 ? inq  : which == 1 ? ink  : inv;
    __nv_bfloat16*       out = which == 0 ? outq : which == 1 ? outk : outv;
    const float*         wt  = which == 0 ? wq   : which == 1 ? wk   : wv;

    int bc = blockIdx.x;
    int c  = bc % C_;
    const float* wp = wt + c * 9;
    float w00 = __ldg(wp + 0), w01 = __ldg(wp + 1), w02 = __ldg(wp + 2);
    float w10 = __ldg(wp + 3), w11 = __ldg(wp + 4), w12 = __ldg(wp + 5);
    float w20 = __ldg(wp + 6), w21 = __ldg(wp + 7), w22 = __ldg(wp + 8);

    int warp = threadIdx.x >> 5, lane = threadIdx.x & 31;
    int y0 = warp * 16;
    const __nv_bfloat16* ib = in + (size_t)bc * HW_;
    __nv_bfloat16* ob = out + (size_t)bc * HW_;

    float pl, pr, cl, cr, nl, nr;
    float4 pf, cf, nf;
    dw_load_row_bf(ib, y0 - 1, lane, pl, pf, pr);
    dw_load_row_bf(ib, y0,     lane, cl, cf, cr);

    #pragma unroll
    for (int r = 0; r < 16; r++) {
        int y = y0 + r;
        dw_load_row_bf(ib, y + 1, lane, nl, nf, nr);
        float4 o;
        o.x = fmaf(pl,   w00, fmaf(pf.x, w01, fmaf(pf.y, w02,
              fmaf(cl,   w10, fmaf(cf.x, w11, fmaf(cf.y, w12,
              fmaf(nl,   w20, fmaf(nf.x, w21, nf.y * w22))))))));
        o.y = fmaf(pf.x, w00, fmaf(pf.y, w01, fmaf(pf.z, w02,
              fmaf(cf.x, w10, fmaf(cf.y, w11, fmaf(cf.z, w12,
              fmaf(nf.x, w20, fmaf(nf.y, w21, nf.z * w22))))))));
        o.z = fmaf(pf.y, w00, fmaf(pf.z, w01, fmaf(pf.w, w02,
              fmaf(cf.y, w10, fmaf(cf.z, w11, fmaf(cf.w, w12,
              fmaf(nf.y, w20, fmaf(nf.z, w21, nf.w * w22))))))));
        o.w = fmaf(pf.z, w00, fmaf(pf.w, w01, fmaf(pr,   w02,
              fmaf(cf.z, w10, fmaf(cf.w, w11, fmaf(cr,   w12,
              fmaf(nf.z, w20, fmaf(nf.w, w21, nr * w22))))))));
        uint2 st;
        st.x = pack_bf2(o.x, o.y);
        st.y = pack_bf2(o.z, o.w);
        *reinterpret_cast<uint2*>(ob + (size_t)y * W_ + lane * 4) = st;
        pl = cl; pr = cr; pf = cf;
        cl = nl; cr = nr; cf = nf;
    }
}

// ---------------- Gram via mma.sync ----------------------------------------------
// G[i,j] = sum_p q[i,p]*k[j,p] per (b,h); partial over 1024-px chunks.
// smem: 96 rows (48 q + 48 k) x 64 px bf16, stride 36 words, double buffered.
// 6 compute warps: wm = w>>1 (3 m16 tiles), wn = w&1 (n24 each).
// Sum-of-squares accumulated in registers during LDG staging (3 rows/thread).
#define GR_STRIDE 36
#define GR_BUFW   (96 * GR_STRIDE)
__global__ void __launch_bounds__(256) gram_mma(
    const __nv_bfloat16* __restrict__ qd, const __nv_bfloat16* __restrict__ kd,
    float* __restrict__ part)
{
    __shared__ uint32_t gsm[2][GR_BUFW];
    __shared__ float nqs[96];

    int chunk = blockIdx.x;          // 0..15
    int bh    = blockIdx.y;          // 0..31
    int b = bh >> 2, h = bh & 3;
    size_t base = ((size_t)b * C_ + h * DH) * HW_ + (size_t)chunk * 1024;
    const __nv_bfloat16* qb_ = qd + base;
    const __nv_bfloat16* kb_ = kd + base;

    int tid = threadIdx.x;
    int w = tid >> 5, lane = tid & 31;
    int wm = w >> 1, wn = w & 1;     // valid for w<6
    int g = lane >> 2, t4 = lane & 3;
    uint32_t smBase = (uint32_t)__cvta_generic_to_shared(gsm);

    if (tid < 96) nqs[tid] = 0.f;

    // per-thread staging rows (fixed across tiles): (tid+256*it)>>3
    int rowi[3], segi[3];
    #pragma unroll
    for (int it = 0; it < 3; it++) {
        int idx = tid + 256 * it;
        rowi[it] = idx >> 3;
        segi[it] = idx & 7;
    }
    float nacc[3] = {0.f, 0.f, 0.f};

    // ldsm bases (byte offsets within a buffer)
    uint32_t offA = 0, offB4 = 0, offB2 = 0;
    if (w < 6) {
        int rA = wm * 16 + (lane & 15);
        offA = (uint32_t)((rA * GR_STRIDE + (lane >> 4) * 4) * 4);
        int rB4 = 48 + wn * 24 + ((lane >> 4) << 3) + (lane & 7);
        offB4 = (uint32_t)((rB4 * GR_STRIDE + ((lane >> 3) & 1) * 4) * 4);
        int l15 = lane & 15;
        int rB2 = 48 + wn * 24 + 16 + (l15 & 7);
        offB2 = (uint32_t)((rB2 * GR_STRIDE + ((l15 >> 3) & 1) * 4) * 4);
    }

    float acc[3][4];
    #pragma unroll
    for (int i = 0; i < 3; i++)
        #pragma unroll
        for (int j = 0; j < 4; j++) acc[i][j] = 0.f;

    // ---- load tile 0 into regs, sumsq, store to buf0 ----
    uint4 rg[3];
    auto loadTile = [&](int t) {
        #pragma unroll
        for (int it = 0; it < 3; it++) {
            const __nv_bfloat16* src = (rowi[it] < 48)
                ? qb_ + (size_t)rowi[it] * HW_
                : kb_ + (size_t)(rowi[it] - 48) * HW_;
            rg[it] = *reinterpret_cast<const uint4*>(src + t * 64 + segi[it] * 8);
            const uint32_t* u = &rg[it].x;
            #pragma unroll
            for (int j = 0; j < 4; j++) {
                __nv_bfloat162 hv = *reinterpret_cast<const __nv_bfloat162*>(&u[j]);
                float a = __bfloat162float(hv.x), bb = __bfloat162float(hv.y);
                nacc[it] = fmaf(a, a, fmaf(bb, bb, nacc[it]));
            }
        }
    };
    auto storeTile = [&](int buf) {
        #pragma unroll
        for (int it = 0; it < 3; it++) {
            uint32_t* d = &gsm[buf][rowi[it] * GR_STRIDE + segi[it] * 4];
            d[0] = rg[it].x; d[1] = rg[it].y; d[2] = rg[it].z; d[3] = rg[it].w;
        }
    };

    loadTile(0);
    storeTile(0);

    for (int t = 0; t < 16; t++) {
        __syncthreads();                       // buf (t&1) ready
        if (t < 15) loadTile(t + 1);           // LDG next (overlaps mma)
        if (w < 6) {
            uint32_t bufOff = smBase + (uint32_t)((t & 1) * GR_BUFW * 4);
            #pragma unroll
            for (int s = 0; s < 4; s++) {      // 4 k16 steps per 64-px tile
                uint32_t a[4], b4[4], b2[2];
                ldsm_x4(a,  bufOff + offA  + s * 32);
                ldsm_x4(b4, bufOff + offB4 + s * 32);
                ldsm_x2(b2, bufOff + offB2 + s * 32);
                mma_bf16(acc[0], a, &b4[0]);
                mma_bf16(acc[1], a, &b4[2]);
                mma_bf16(acc[2], a, b2);
            }
        }
        if (t < 15) {
            __syncthreads();                   // all mma on buf ((t+1)&1) done
            storeTile((t + 1) & 1);
        }
    }

    // ---- norms reduce ----
    #pragma unroll
    for (int it = 0; it < 3; it++)
        atomicAdd(&nqs[rowi[it]], nacc[it]);
    __syncthreads();

    // ---- write partials ----
    float* pb = part + ((size_t)bh * 16 + chunk) * 2400;
    if (w < 6) {
        int i0 = wm * 16;
        #pragma unroll
        for (int f = 0; f < 3; f++) {
            int n0 = wn * 24 + f * 8;
            pb[(i0 + g) * DH + n0 + t4 * 2]     = acc[f][0];
            pb[(i0 + g) * DH + n0 + t4 * 2 + 1] = acc[f][1];
            pb[(i0 + g + 8) * DH + n0 + t4 * 2]     = acc[f][2];
            pb[(i0 + g + 8) * DH + n0 + t4 * 2 + 1] = acc[f][3];
        }
    }
    if (tid < 96) pb[2304 + tid] = nqs[tid];
}

// ---------------- reduce partials + norms + softmax -----------------------------
__global__ void __launch_bounds__(256) reduce_softmax(
    const float* __restrict__ part, const float* __restrict__ temp,
    float* __restrict__ attn)
{
    int bh = blockIdx.x;
    int h = bh & 3;
    __shared__ float G[DH * DH];
    __shared__ float nq[DH], nk[DH];
    int tid = threadIdx.x;

    for (int e = tid; e < 2400; e += 256) {
        float s = 0.f;
        #pragma unroll
        for (int c = 0; c < 16; c++)
            s += part[((size_t)bh * 16 + c) * 2400 + e];
        if (e < 2304)      G[e] = s;
        else if (e < 2352) nq[e - 2304] = fmaxf(sqrtf(s), 1e-12f);
        else               nk[e - 2352] = fmaxf(sqrtf(s), 1e-12f);
    }
    __syncthreads();

    if (tid < DH) {
        int i = tid;
        float sc = __ldg(&temp[h]) / nq[i];
        float m = -1e30f;
        #pragma unroll 4
        for (int j = 0; j < DH; j++) {
            float s = G[i * DH + j] * sc / nk[j];
            G[i * DH + j] = s;
            m = fmaxf(m, s);
        }
        float sum = 0.f;
        #pragma unroll 4
        for (int j = 0; j < DH; j++) {
            float e = __expf(G[i * DH + j] - m);
            G[i * DH + j] = e;
            sum += e;
        }
        float rs = 1.f / sum;
        #pragma unroll 4
        for (int j = 0; j < DH; j++)
            attn[(size_t)bh * DH * DH + i * DH + j] = G[i * DH + j] * rs;
    }
}

// ---------------- M_b = W_proj @ blockdiag(attn_b), bf16 out --------------------
__global__ void __launch_bounds__(256) build_Mb(
    const float* __restrict__ attn, const float* __restrict__ wp,
    __nv_bfloat16* __restrict__ M)
{
    int b = blockIdx.x;
    __shared__ float sA[HEADS * DH * DH];
    int tid = threadIdx.x;
    for (int e = tid; e < HEADS * DH * DH; e += 256)
        sA[e] = attn[(size_t)b * HEADS * DH * DH + e];
    __syncthreads();

    for (int e = tid; e < C_ * C_; e += 256) {
        int o = e / C_, cp = e % C_;
        int h = cp / DH, d = cp % DH;
        const float* wrow = wp + (size_t)o * C_ + h * DH;
        const float* arow = sA + h * DH * DH + d;
        float s = 0.f;
        #pragma unroll
        for (int i = 0; i < DH; i++)
            s = fmaf(__ldg(&wrow[i]), arow[i * DH], s);
        M[(size_t)b * C_ * C_ + e] = __float2bfloat16(s);
    }
}

// ---------------- launch --------------------------------------------------------
#define GEMM_SMEM 102400

extern "C" void kernel_launch(void* const* d_in, const int* in_sizes, int n_in,
                              void* d_out, int out_size)
{
    const float* xx     = (const float*)d_in[0];
    const float* q_in   = (const float*)d_in[1];
    const float* ln_w   = (const float*)d_in[2];
    const float* ln_b   = (const float*)d_in[3];
    const float* w_q    = (const float*)d_in[4];
    const float* w_k    = (const float*)d_in[5];
    const float* w_v    = (const float*)d_in[6];
    const float* wd_q   = (const float*)d_in[7];
    const float* wd_k   = (const float*)d_in[8];
    const float* wd_v   = (const float*)d_in[9];
    const float* w_proj = (const float*)d_in[10];
    const float* temp   = (const float*)d_in[11];
    float* out = (float*)d_out;

    float* S = nullptr;
    cudaGetSymbolAddress((void**)&S, g_scratch);
    __nv_bfloat16* qb = (__nv_bfloat16*)(S + OFF_QB);
    __nv_bfloat16* kb = (__nv_bfloat16*)(S + OFF_KB);
    __nv_bfloat16* vb = (__nv_bfloat16*)(S + OFF_VB);
    __nv_bfloat16* qd = (__nv_bfloat16*)(S + OFF_QD);
    __nv_bfloat16* kd = (__nv_bfloat16*)(S + OFF_KD);
    __nv_bfloat16* vd = (__nv_bfloat16*)(S + OFF_VD);
    float* part = S + OFF_PART;
    float* attn = S + OFF_ATTN;
    __nv_bfloat16* whi = (__nv_bfloat16*)(S + OFF_WHI);
    const int PLANE = C_ * C_;

    cudaFuncSetAttribute(mma_gemm6,
                         cudaFuncAttributeMaxDynamicSharedMemorySize, GEMM_SMEM);

    // 1. weights -> bf16 planes (slots 0..2)
    wconv3<<<dim3(36, 3), 256>>>(w_q, w_k, w_v, whi);

    // 2. 1x1 convs with fused LN (q: M=192; k+v stacked: M=384), bf16 out
    dim3 gg(HW_ / 128, B_);
    mma_gemm6<<<gg, 256, GEMM_SMEM>>>(q_in, 0, whi + 0 * PLANE, 0, 3,
                                      qb, qb, 1, nullptr, ln_w, ln_b);
    mma_gemm6<<<gg, 256, GEMM_SMEM>>>(xx, 0, whi + 1 * PLANE, 0, 6,
                                      kb, vb, 1, nullptr, ln_w, ln_b);

    // 3. depthwise 3x3 (bf16 in/out)
    dw3v3<<<dim3(B_ * C_, 3), 256>>>(qb, kb, vb, qd, kd, vd, wd_q, wd_k, wd_v);

    // 4. Gram via tensor cores + softmax
    gram_mma<<<dim3(16, 32), 256>>>(qd, kd, part);
    reduce_softmax<<<32, 256>>>(part, temp, attn);

    // 5. fold attn@v with proj (bf16 planes 3..10), final GEMM fp32 + residual
    build_Mb<<<8, 256>>>(attn, w_proj, whi + 3 * PLANE);
    mma_gemm6<<<gg, 256, GEMM_SMEM>>>(vd, 1, whi + 3 * PLANE, PLANE, 3,
                                      out, out, 0, q_in, nullptr, nullptr);
}